// round 9
// baseline (speedup 1.0000x reference)
#include <cuda_runtime.h>
#include <cuda_bf16.h>
#include <math.h>
#include <stdint.h>

// Problem constants
#define B_  8
#define T_  1024
#define D_  512
#define H_  8
#define DK_ 64
#define P_  2047          // 2*T-1
#define NROW_ (B_*T_)     // 8192
#define ND_  (NROW_*D_)   // 4194304

// -------------------- device scratch (no allocs allowed) --------------------
__device__ float g_qn [ND_];
__device__ float g_kn [ND_];
__device__ float g_vn [ND_];
__device__ float g_qu [ND_];   // qh + pos_bias_u (tf32, dk pair-permuted)
__device__ float g_qv [ND_];   // qh + pos_bias_v (tf32, dk pair-permuted)
__device__ float g_kh [ND_];   // tf32, dk pair-permuted
__device__ float g_vh [ND_];   // tf32, natural
__device__ float g_p  [(P_+1)*D_]; // tf32, dk pair-permuted (row 2047 = pad)
__device__ float g_ctx[ND_];   // attn @ V (fp32)

// pair-permutation within 8-groups: logical (k, k+4) -> adjacent positions
__device__ __forceinline__ int pos8(int x) { return ((x & 3) << 1) | ((x >> 2) & 1); }

// ------------------------------ LayerNorm -----------------------------------
__global__ __launch_bounds__(256)
void ln_kernel(const float* __restrict__ x, const float* __restrict__ g,
               const float* __restrict__ bb, float* __restrict__ y)
{
    long row = blockIdx.x;
    const float2* xr = (const float2*)(x + row * D_);
    float2*       yr = (float2*)(y + row * D_);
    int tid = threadIdx.x;
    float2 v = xr[tid];
    float s  = v.x + v.y;
    float sq = v.x * v.x + v.y * v.y;

    __shared__ float rs[8], rq[8];
    #pragma unroll
    for (int o = 16; o > 0; o >>= 1) {
        s  += __shfl_xor_sync(0xffffffffu, s,  o);
        sq += __shfl_xor_sync(0xffffffffu, sq, o);
    }
    int wid = tid >> 5;
    if ((tid & 31) == 0) { rs[wid] = s; rq[wid] = sq; }
    __syncthreads();
    if (tid == 0) {
        float a = 0.f, b2 = 0.f;
        #pragma unroll
        for (int w = 0; w < 8; w++) { a += rs[w]; b2 += rq[w]; }
        rs[0] = a; rq[0] = b2;
    }
    __syncthreads();
    float mean = rs[0] * (1.0f / D_);
    float var  = rq[0] * (1.0f / D_) - mean * mean;
    float rstd = rsqrtf(var + 1e-5f);
    const float2* gv2 = (const float2*)g;
    const float2* bv2 = (const float2*)bb;
    float2 gv = gv2[tid], bv = bv2[tid];
    float2 o;
    o.x = (v.x - mean) * rstd * gv.x + bv.x;
    o.y = (v.y - mean) * rstd * gv.y + bv.y;
    yr[tid] = o;
}

// ------------------------- TF32 helpers --------------------------------------
__device__ __forceinline__ uint32_t f2tf(float f) {
    uint32_t u;
    asm("cvt.rna.tf32.f32 %0, %1;" : "=r"(u) : "f"(f));
    return u;
}

__device__ __forceinline__ void mma_tf32(float c[4], const uint32_t a[4],
                                         const uint32_t b[2]) {
    asm volatile(
        "mma.sync.aligned.m16n8k8.row.col.f32.tf32.tf32.f32 "
        "{%0,%1,%2,%3},{%4,%5,%6,%7},{%8,%9},{%0,%1,%2,%3};\n"
        : "+f"(c[0]), "+f"(c[1]), "+f"(c[2]), "+f"(c[3])
        : "r"(a[0]), "r"(a[1]), "r"(a[2]), "r"(a[3]), "r"(b[0]), "r"(b[1]));
}

__device__ __forceinline__ void cp16(float* dst_smem, const float* src, bool valid) {
    uint32_t d = (uint32_t)__cvta_generic_to_shared(dst_smem);
    int sz = valid ? 16 : 0;
    asm volatile("cp.async.cg.shared.global [%0], [%1], 16, %2;\n"
                 :: "r"(d), "l"(src), "r"(sz));
}
#define CP_COMMIT() asm volatile("cp.async.commit_group;\n" ::: "memory")
#define CP_WAIT0()  asm volatile("cp.async.wait_group 0;\n" ::: "memory")
#define CP_WAIT1()  asm volatile("cp.async.wait_group 1;\n" ::: "memory")

__device__ __forceinline__ uint32_t ldu(const float* p) {
    return __float_as_uint(*p);
}

// ------------------------------ TF32 MMA GEMM --------------------------------
// (projections + FC) 3-stage cp.async pipeline.
// CVT_OUT: store tf32-rounded. PERM_OUT: pair-permute output columns in 8-groups.
template<int BM, int BN, int WM, int WN, bool TRANS_B, bool CVT_OUT, bool PERM_OUT>
__global__ __launch_bounds__(256)
void mma_gemm(const float* __restrict__ A, const float* __restrict__ Bm,
              float* __restrict__ C, float* __restrict__ C2,
              const float* __restrict__ bias1, const float* __restrict__ bias2,
              const float* __restrict__ Res,
              int M, int N, int K, int lda, int ldb, int ldc,
              float alpha)
{
    constexpr int BK = 16;
    constexpr int MT = WM / 16;
    constexpr int NT = WN / 8;
    constexpr int WCOLS = BN / WN;
    static_assert((BM / WM) * (BN / WN) == 8, "8 warps required");

    __shared__ float As[3][BM][BK + 4];
    __shared__ float Bs[3][TRANS_B ? BN : BK][TRANS_B ? (BK + 4) : (BN + 8)];

    int m0 = blockIdx.y * BM, n0 = blockIdx.x * BN;

    int tid  = threadIdx.x;
    int warp = tid >> 5, lane = tid & 31;
    int wm0 = (warp / WCOLS) * WM;
    int wn0 = (warp % WCOLS) * WN;

    auto ldg_async = [&](int k0, int buf) {
        #pragma unroll
        for (int it = 0; it < (BM * BK) / (4 * 256); it++) {
            int s = tid + it * 256;
            int row = s >> 2, kq = s & 3;
            int gm = m0 + row;
            cp16(&As[buf][row][kq * 4], A + (long)gm * lda + k0 + kq * 4, gm < M);
        }
        if (TRANS_B) {
            #pragma unroll
            for (int it = 0; it < (BN * BK) / (4 * 256); it++) {
                int s = tid + it * 256;
                int n = s >> 2, kq = s & 3;
                int gn = n0 + n;
                cp16(&Bs[buf][n][kq * 4], Bm + (long)gn * ldb + k0 + kq * 4, gn < N);
            }
        } else {
            #pragma unroll
            for (int it = 0; it < (BK * BN) / (4 * 256); it++) {
                int s = tid + it * 256;
                int kk = s / (BN / 4), nq = s % (BN / 4);
                cp16(&Bs[buf][kk][nq * 4],
                     Bm + (long)(k0 + kk) * ldb + n0 + nq * 4, true);
            }
        }
        CP_COMMIT();
    };

    float acc[MT][NT][4];
    #pragma unroll
    for (int i = 0; i < MT; i++)
        #pragma unroll
        for (int j = 0; j < NT; j++)
            #pragma unroll
            for (int e = 0; e < 4; e++) acc[i][j][e] = 0.f;

    const int nIter = K / BK;
    ldg_async(0, 0);
    if (nIter > 1) ldg_async(BK, 1);
    if (nIter > 1) { CP_WAIT1(); } else { CP_WAIT0(); }
    __syncthreads();

    for (int itk = 0; itk < nIter; itk++) {
        int buf = itk % 3;
        if (itk + 2 < nIter) ldg_async((itk + 2) * BK, (itk + 2) % 3);

        #pragma unroll
        for (int ks = 0; ks < 2; ks++) {
            const int kb = ks * 8;
            const int kc = kb + (lane & 3);
            uint32_t af[MT][4];
            uint32_t bf[NT][2];
            #pragma unroll
            for (int mt = 0; mt < MT; mt++) {
                int mrow = wm0 + mt * 16 + (lane >> 2);
                af[mt][0] = f2tf(As[buf][mrow    ][kc    ]);
                af[mt][1] = f2tf(As[buf][mrow + 8][kc    ]);
                af[mt][2] = f2tf(As[buf][mrow    ][kc + 4]);
                af[mt][3] = f2tf(As[buf][mrow + 8][kc + 4]);
            }
            #pragma unroll
            for (int nt = 0; nt < NT; nt++) {
                int ncol = wn0 + nt * 8 + (lane >> 2);
                if (TRANS_B) {
                    bf[nt][0] = f2tf(Bs[buf][ncol][kc    ]);
                    bf[nt][1] = f2tf(Bs[buf][ncol][kc + 4]);
                } else {
                    bf[nt][0] = f2tf(Bs[buf][kc    ][ncol]);
                    bf[nt][1] = f2tf(Bs[buf][kc + 4][ncol]);
                }
            }
            #pragma unroll
            for (int mt = 0; mt < MT; mt++)
                #pragma unroll
                for (int nt = 0; nt < NT; nt++)
                    mma_tf32(acc[mt][nt], af[mt], bf[nt]);
        }

        if (itk + 1 < nIter) {
            if (itk + 2 < nIter) { CP_WAIT1(); } else { CP_WAIT0(); }
        }
        __syncthreads();
    }

    auto emit = [&](int gm, int gn, float v) {
        if (gm < M && gn < N) {
            float val = v * alpha;
            if (Res) val += Res[(long)gm * ldc + gn];
            int gns = PERM_OUT ? ((gn & ~7) | pos8(gn & 7)) : gn;
            if (C2) {
                float v1 = val + bias1[gn];
                float v2 = val + bias2[gn];
                if (CVT_OUT) { v1 = __uint_as_float(f2tf(v1)); v2 = __uint_as_float(f2tf(v2)); }
                C [(long)gm * ldc + gns] = v1;
                C2[(long)gm * ldc + gns] = v2;
            } else {
                float v1 = val + (bias1 ? bias1[gn] : 0.f);
                if (CVT_OUT) v1 = __uint_as_float(f2tf(v1));
                C[(long)gm * ldc + gns] = v1;
            }
        }
    };
    #pragma unroll
    for (int mt = 0; mt < MT; mt++) {
        #pragma unroll
        for (int nt = 0; nt < NT; nt++) {
            int gm = m0 + wm0 + mt * 16 + (lane >> 2);
            int gn = n0 + wn0 + nt * 8 + 2 * (lane & 3);
            emit(gm,     gn,     acc[mt][nt][0]);
            emit(gm,     gn + 1, acc[mt][nt][1]);
            emit(gm + 8, gn,     acc[mt][nt][2]);
            emit(gm + 8, gn + 1, acc[mt][nt][3]);
        }
    }
}

// ===================== FUSED ATTENTION ======================================
// One CTA: (b,h), 32 query rows, 512 threads. S strip [32 x 1024] in smem.
// qu/qv/kh/p are dk pair-permuted (fragment pairs adjacent -> LDS.64).
// S is stored j pair-permuted; softmax un-permutes by register wiring.
#define S_STRIDE 1028
#define K_STRIDE 68
#define V_STRIDE 72
#define SMEM_FLOATS (32*S_STRIDE + 2*128*V_STRIDE + 2*32*K_STRIDE)

__global__ __launch_bounds__(512)
void fused_attn(const float* __restrict__ qu, const float* __restrict__ qv,
                const float* __restrict__ kh, const float* __restrict__ vh,
                const float* __restrict__ pbuf, const int* __restrict__ mask,
                float* __restrict__ attn, float* __restrict__ ctx)
{
    extern __shared__ float sm[];
    float* S   = sm;                          // [32][1028], j pair-permuted
    float* KV0 = sm + 32 * S_STRIDE;          // [128][72] (K/P use stride 68)
    float* KV1 = KV0 + 128 * V_STRIDE;
    float* Qu  = KV1 + 128 * V_STRIDE;        // [32][68]
    float* Qv  = Qu + 32 * K_STRIDE;

    const int i0 = blockIdx.x * 32;
    const int z  = blockIdx.y;                // b*H + h
    const int b  = z >> 3, h = z & 7;
    const int tid = threadIdx.x;
    const int w = tid >> 5, lane = tid & 31;
    const float scale = 0.125f;
    const float NEG = __int_as_float(0xff7fffff);   // -FLT_MAX sentinel

    // ---- load Qu, Qv tiles (32 x 64) ----
    {
        int r = tid >> 4, kq = tid & 15;
        long base = ((long)(b * T_ + i0 + r) * D_ + h * DK_ + kq * 4);
        cp16(&Qu[r * K_STRIDE + kq * 4], qu + base, true);
        cp16(&Qv[r * K_STRIDE + kq * 4], qv + base, true);
    }
    CP_COMMIT();

    auto load_k = [&](int jt, float* buf) {
        #pragma unroll
        for (int it = 0; it < 4; it++) {
            int s = tid + it * 512;
            int n = s >> 4, kq = s & 15;
            cp16(&buf[n * K_STRIDE + kq * 4],
                 kh + ((long)(b * T_ + jt * 128 + n) * D_ + h * DK_ + kq * 4), true);
        }
        CP_COMMIT();
    };
    auto load_v = [&](int jt, float* buf) {
        #pragma unroll
        for (int it = 0; it < 4; it++) {
            int s = tid + it * 512;
            int n = s >> 4, kq = s & 15;
            cp16(&buf[n * V_STRIDE + kq * 4],
                 vh + ((long)(b * T_ + jt * 128 + n) * D_ + h * DK_ + kq * 4), true);
        }
        CP_COMMIT();
    };
    auto load_p = [&](int pt0, float* buf) {
        #pragma unroll
        for (int it = 0; it < 4; it++) {
            int s = tid + it * 512;
            int n = s >> 4, kq = s & 15;
            int p = pt0 + n;
            cp16(&buf[n * K_STRIDE + kq * 4],
                 pbuf + ((long)p * D_ + h * DK_ + kq * 4), p <= P_ - 1);
        }
        CP_COMMIT();
    };

    // warp mapping for score phases: mh = row-half(16), ne = col-strip of 16
    const int mh = w & 1, ne = w >> 1;
    const int r0 = mh * 16 + (lane >> 2);
    const int l  = lane & 3;
    // store positions within 8-group for logical offsets 2l and 2l+1
    const int posA = (((2*l) & 3) << 1) | ((2*l) >> 2);
    const int posB = (((2*l+1) & 3) << 1) | ((2*l+1) >> 2);

    // ---------------- Phase 1: ac = scale * Qu @ K^T ----------------
    load_k(0, KV0);
    CP_WAIT0();
    __syncthreads();

    {
        uint32_t au[8][4];                   // hoisted Qu fragments (paired LDS.64)
        #pragma unroll
        for (int kk = 0; kk < 8; kk++) {
            int kp = kk * 8 + 2 * l;
            float2 p0 = *(const float2*)&Qu[r0 * K_STRIDE + kp];
            float2 p1 = *(const float2*)&Qu[(r0 + 8) * K_STRIDE + kp];
            au[kk][0] = __float_as_uint(p0.x);
            au[kk][1] = __float_as_uint(p1.x);
            au[kk][2] = __float_as_uint(p0.y);
            au[kk][3] = __float_as_uint(p1.y);
        }

        for (int jt = 0; jt < 8; jt++) {
            float* cur = (jt & 1) ? KV1 : KV0;
            float* nxt = (jt & 1) ? KV0 : KV1;
            if (jt + 1 < 8) load_k(jt + 1, nxt);

            float acc[2][4] = {{0.f,0.f,0.f,0.f},{0.f,0.f,0.f,0.f}};
            #pragma unroll
            for (int kk = 0; kk < 8; kk++) {
                int kp = kk * 8 + 2 * l;
                #pragma unroll
                for (int nt = 0; nt < 2; nt++) {
                    int ncol = ne * 16 + nt * 8 + (lane >> 2);
                    float2 bp = *(const float2*)&cur[ncol * K_STRIDE + kp];
                    uint32_t bf[2] = { __float_as_uint(bp.x), __float_as_uint(bp.y) };
                    mma_tf32(acc[nt], au[kk], bf);
                }
            }
            #pragma unroll
            for (int nt = 0; nt < 2; nt++) {
                int base = jt * 128 + ne * 16 + nt * 8;
                S[r0 * S_STRIDE + base + posA]       = acc[nt][0] * scale;
                S[r0 * S_STRIDE + base + posB]       = acc[nt][1] * scale;
                S[(r0 + 8) * S_STRIDE + base + posA] = acc[nt][2] * scale;
                S[(r0 + 8) * S_STRIDE + base + posB] = acc[nt][3] * scale;
            }
            if (jt + 1 < 8) CP_WAIT0();
            __syncthreads();
        }
    }

    // ------------- Phase 2: bd scatter-add over p-window -------------
    const int pbase = (T_ - 1) - (i0 + 31);
    load_p(pbase, KV0);
    {
        uint32_t av[8][4];
        #pragma unroll
        for (int kk = 0; kk < 8; kk++) {
            int kp = kk * 8 + 2 * l;
            float2 p0 = *(const float2*)&Qv[r0 * K_STRIDE + kp];
            float2 p1 = *(const float2*)&Qv[(r0 + 8) * K_STRIDE + kp];
            av[kk][0] = __float_as_uint(p0.x);
            av[kk][1] = __float_as_uint(p1.x);
            av[kk][2] = __float_as_uint(p0.y);
            av[kk][3] = __float_as_uint(p1.y);
        }
        CP_WAIT0();
        __syncthreads();

        for (int pt = 0; pt < 9; pt++) {
            float* cur = (pt & 1) ? KV1 : KV0;
            float* nxt = (pt & 1) ? KV0 : KV1;
            if (pt + 1 < 9) load_p(pbase + (pt + 1) * 128, nxt);

            float acc[2][4] = {{0.f,0.f,0.f,0.f},{0.f,0.f,0.f,0.f}};
            #pragma unroll
            for (int kk = 0; kk < 8; kk++) {
                int kp = kk * 8 + 2 * l;
                #pragma unroll
                for (int nt = 0; nt < 2; nt++) {
                    int ncol = ne * 16 + nt * 8 + (lane >> 2);
                    float2 bp = *(const float2*)&cur[ncol * K_STRIDE + kp];
                    uint32_t bf[2] = { __float_as_uint(bp.x), __float_as_uint(bp.y) };
                    mma_tf32(acc[nt], av[kk], bf);
                }
            }
            const int pt0 = pbase + pt * 128;
            #pragma unroll
            for (int nt = 0; nt < 2; nt++) {
                int c0 = ne * 16 + nt * 8 + 2 * l;
                #pragma unroll
                for (int e = 0; e < 4; e++) {
                    int r = r0 + (e >> 1) * 8;
                    int p = pt0 + c0 + (e & 1);
                    int j = p - (T_ - 1) + i0 + r;
                    if ((unsigned)j < (unsigned)T_) {
                        int jc = (j & ~7) | pos8(j & 7);
                        S[r * S_STRIDE + jc] += acc[nt][e] * scale;
                    }
                }
            }
            if (pt + 1 < 9) CP_WAIT0();
            __syncthreads();
        }
    }

    // -------- prefetch V tile 0 (overlaps softmax) --------
    load_v(0, KV0);

    // ------ Phase 3: softmax over permuted S; register un-permutation ------
    #pragma unroll
    for (int t = 0; t < 2; t++) {
        int r = w + 16 * t;
        int i = i0 + r;
        const int4* mrow = (const int4*)(mask + ((long)b * T_ + i) * T_);
        float4*     srow = (float4*)(S + r * S_STRIDE);
        float4*     arow = (float4*)(attn + ((long)z * T_ + i) * T_);

        // lane owns whole 8-groups: g = e*32 + lane (4 groups/lane)
        float4 s0[4], s1[4];
        float lmax = NEG;
        #pragma unroll
        for (int e = 0; e < 4; e++) {
            int g = e * 32 + lane;
            float4 v0 = srow[2 * g];        // positions 0..3 = logical {0,4,1,5}
            float4 v1 = srow[2 * g + 1];    // positions 4..7 = logical {2,6,3,7}
            int4   m0 = mrow[2 * g];        // logical {0,1,2,3}
            int4   m1 = mrow[2 * g + 1];    // logical {4,5,6,7}
            v0.x = (m0.x == 0) ? NEG : v0.x;   // j0
            v0.y = (m1.x == 0) ? NEG : v0.y;   // j4
            v0.z = (m0.y == 0) ? NEG : v0.z;   // j1
            v0.w = (m1.y == 0) ? NEG : v0.w;   // j5
            v1.x = (m0.z == 0) ? NEG : v1.x;   // j2
            v1.y = (m1.z == 0) ? NEG : v1.y;   // j6
            v1.z = (m0.w == 0) ? NEG : v1.z;   // j3
            v1.w = (m1.w == 0) ? NEG : v1.w;   // j7
            s0[e] = v0; s1[e] = v1;
            lmax = fmaxf(lmax, fmaxf(fmaxf(v0.x, v0.y), fmaxf(v0.z, v0.w)));
            lmax = fmaxf(lmax, fmaxf(fmaxf(v1.x, v1.y), fmaxf(v1.z, v1.w)));
        }
        #pragma unroll
        for (int o = 16; o > 0; o >>= 1)
            lmax = fmaxf(lmax, __shfl_xor_sync(0xffffffffu, lmax, o));

        if (lmax == NEG) {
            float4 zero = make_float4(0.f, 0.f, 0.f, 0.f);
            #pragma unroll
            for (int e = 0; e < 4; e++) {
                int g = e * 32 + lane;
                srow[2 * g] = zero; srow[2 * g + 1] = zero;
                arow[2 * g] = zero; arow[2 * g + 1] = zero;
            }
            continue;
        }
        float sum = 0.f;
        #pragma unroll
        for (int e = 0; e < 4; e++) {
            float4 v0 = s0[e], v1 = s1[e];
            v0.x = __expf(v0.x - lmax); v0.y = __expf(v0.y - lmax);
            v0.z = __expf(v0.z - lmax); v0.w = __expf(v0.w - lmax);
            v1.x = __expf(v1.x - lmax); v1.y = __expf(v1.y - lmax);
            v1.z = __expf(v1.z - lmax); v1.w = __expf(v1.w - lmax);
            s0[e] = v0; s1[e] = v1;
            sum += (v0.x + v0.y) + (v0.z + v0.w) + (v1.x + v1.y) + (v1.z + v1.w);
        }
        #pragma unroll
        for (int o = 16; o > 0; o >>= 1)
            sum += __shfl_xor_sync(0xffffffffu, sum, o);
        float inv = 1.0f / sum;
        #pragma unroll
        for (int e = 0; e < 4; e++) {
            int g = e * 32 + lane;
            float4 v0 = s0[e], v1 = s1[e];
            v0.x *= inv; v0.y *= inv; v0.z *= inv; v0.w *= inv;
            v1.x *= inv; v1.y *= inv; v1.z *= inv; v1.w *= inv;
            // attn natural order: {j0,j1,j2,j3} = {v0.x, v0.z, v1.x, v1.z}
            arow[2 * g]     = make_float4(v0.x, v0.z, v1.x, v1.z);
            arow[2 * g + 1] = make_float4(v0.y, v0.w, v1.y, v1.w);
            // smem keeps permuted layout, tf32-rounded for phase 4
            float4 w0, w1;
            w0.x = __uint_as_float(f2tf(v0.x)); w0.y = __uint_as_float(f2tf(v0.y));
            w0.z = __uint_as_float(f2tf(v0.z)); w0.w = __uint_as_float(f2tf(v0.w));
            w1.x = __uint_as_float(f2tf(v1.x)); w1.y = __uint_as_float(f2tf(v1.y));
            w1.z = __uint_as_float(f2tf(v1.z)); w1.w = __uint_as_float(f2tf(v1.w));
            srow[2 * g] = w0; srow[2 * g + 1] = w1;
        }
    }
    CP_WAIT0();
    __syncthreads();

    // ---------------- Phase 4: O = S @ V -> ctx ----------------
    const int mt = w >> 3, nt4 = w & 7;    // 2 x 8 warp grid over [32 x 64]
    float oacc[4] = {0.f, 0.f, 0.f, 0.f};
    const int r4 = mt * 16 + (lane >> 2);
    const int vn = nt4 * 8 + (lane >> 2);

    for (int jt = 0; jt < 8; jt++) {
        float* cur = (jt & 1) ? KV1 : KV0;
        float* nxt = (jt & 1) ? KV0 : KV1;
        if (jt + 1 < 8) load_v(jt + 1, nxt);

        #pragma unroll
        for (int kk = 0; kk < 16; kk++) {
            int kp = jt * 128 + kk * 8 + 2 * l;          // paired S positions
            float2 a0 = *(const float2*)&S[r4 * S_STRIDE + kp];
            float2 a1 = *(const float2*)&S[(r4 + 8) * S_STRIDE + kp];
            uint32_t af[4] = { __float_as_uint(a0.x), __float_as_uint(a1.x),
                               __float_as_uint(a0.y), __float_as_uint(a1.y) };
            int kc = kk * 8 + l;                          // logical t (natural V)
            uint32_t bf[2] = { ldu(&cur[kc * V_STRIDE + vn]),
                               ldu(&cur[(kc + 4) * V_STRIDE + vn]) };
            mma_tf32(oacc, af, bf);
        }
        if (jt + 1 < 8) CP_WAIT0();
        __syncthreads();
    }

    const int n0 = nt4 * 8 + 2 * l;
    long o0 = (long)(b * T_ + i0 + r4) * D_ + h * DK_ + n0;
    long o1 = (long)(b * T_ + i0 + r4 + 8) * D_ + h * DK_ + n0;
    *(float2*)&ctx[o0] = make_float2(oacc[0], oacc[1]);
    *(float2*)&ctx[o1] = make_float2(oacc[2], oacc[3]);
}

// ------------------------------ launch ---------------------------------------
extern "C" void kernel_launch(void* const* d_in, const int* in_sizes, int n_in,
                              void* d_out, int out_size)
{
    const float* q    = (const float*)d_in[0];
    const float* k    = (const float*)d_in[1];
    const float* v    = (const float*)d_in[2];
    const float* pos  = (const float*)d_in[3];
    const int*   mask = (const int*)  d_in[4];
    const float* lnqg = (const float*)d_in[5],  *lnqb = (const float*)d_in[6];
    const float* lnkg = (const float*)d_in[7],  *lnkb = (const float*)d_in[8];
    const float* lnvg = (const float*)d_in[9],  *lnvb = (const float*)d_in[10];
    const float* wq   = (const float*)d_in[11], *wk   = (const float*)d_in[12];
    const float* wv   = (const float*)d_in[13], *wpos = (const float*)d_in[14];
    const float* wfc  = (const float*)d_in[15];
    const float* pbu  = (const float*)d_in[16], *pbv  = (const float*)d_in[17];

    float* out  = (float*)d_out;                 // [B,T,D]
    float* attn = out + (size_t)ND_;             // [B,H,T,T]

    float *qn,*kn,*vn,*qu,*qvb,*kh,*vh,*pb,*ctx;
    cudaGetSymbolAddress((void**)&qn,  g_qn);
    cudaGetSymbolAddress((void**)&kn,  g_kn);
    cudaGetSymbolAddress((void**)&vn,  g_vn);
    cudaGetSymbolAddress((void**)&qu,  g_qu);
    cudaGetSymbolAddress((void**)&qvb, g_qv);
    cudaGetSymbolAddress((void**)&kh,  g_kh);
    cudaGetSymbolAddress((void**)&vh,  g_vh);
    cudaGetSymbolAddress((void**)&pb,  g_p);
    cudaGetSymbolAddress((void**)&ctx, g_ctx);

    static const size_t fused_smem = SMEM_FLOATS * sizeof(float);
    cudaFuncSetAttribute(fused_attn,
                         cudaFuncAttributeMaxDynamicSharedMemorySize,
                         (int)fused_smem);

    // LayerNorms
    ln_kernel<<<NROW_, 256>>>(q, lnqg, lnqb, qn);
    ln_kernel<<<NROW_, 256>>>(k, lnkg, lnkb, kn);
    ln_kernel<<<NROW_, 256>>>(v, lnvg, lnvb, vn);

    // Q projection -> qu/qv (tf32, dk pair-permuted)
    mma_gemm<128,128,64,32,true,true,true><<<dim3(4,64,1),256>>>(
        qn, wq, qu, qvb, pbu, pbv, nullptr,
        NROW_, D_, D_, D_, D_, D_, 1.f);
    // K projection (tf32, dk pair-permuted)
    mma_gemm<128,128,64,32,true,true,true><<<dim3(4,64,1),256>>>(
        kn, wk, kh, nullptr, nullptr, nullptr, nullptr,
        NROW_, D_, D_, D_, D_, D_, 1.f);
    // V projection (tf32, natural)
    mma_gemm<128,128,64,32,true,true,false><<<dim3(4,64,1),256>>>(
        vn, wv, vh, nullptr, nullptr, nullptr, nullptr,
        NROW_, D_, D_, D_, D_, D_, 1.f);
    // pos projection  (M = 2047, tf32, dk pair-permuted)
    mma_gemm<128,128,64,32,true,true,true><<<dim3(4,16,1),256>>>(
        pos, wpos, pb, nullptr, nullptr, nullptr, nullptr,
        P_, D_, D_, D_, D_, D_, 1.f);

    // fused attention: ac + bd(rel-shift) + softmax + attn-write + PV
    fused_attn<<<dim3(32, 64), 512, fused_smem>>>(
        qu, qvb, kh, vh, pb, mask, attn, ctx);

    // out = ctx @ Wfc^T + residual(q)  (fp32 output)
    mma_gemm<128,128,64,32,true,false,false><<<dim3(4,64,1),256>>>(
        ctx, wfc, out, nullptr, nullptr, nullptr, q,
        NROW_, D_, D_, D_, D_, D_, 1.f);
}

// round 10
// speedup vs baseline: 1.3131x; 1.3131x over previous
#include <cuda_runtime.h>
#include <cuda_bf16.h>
#include <math.h>
#include <stdint.h>

// Problem constants
#define B_  8
#define T_  1024
#define D_  512
#define H_  8
#define DK_ 64
#define P_  2047          // 2*T-1
#define NROW_ (B_*T_)     // 8192
#define ND_  (NROW_*D_)   // 4194304

// -------------------- device scratch (no allocs allowed) --------------------
__device__ float g_qn [ND_];
__device__ float g_kn [ND_];
__device__ float g_vn [ND_];
__device__ float g_qu [ND_];   // qh + pos_bias_u (tf32, dk pair-permuted)
__device__ float g_qv [ND_];   // qh + pos_bias_v (tf32, dk pair-permuted)
__device__ float g_kh [ND_];   // tf32, dk pair-permuted
__device__ float g_vh [ND_];   // tf32, natural
__device__ float g_p  [(P_+1)*D_]; // tf32, dk pair-permuted (row 2047 = pad)
__device__ float g_ctx[ND_];   // attn @ V (fp32)

// pair-permutation within 8-groups: logical (k, k+4) -> adjacent positions
__device__ __forceinline__ int pos8(int x) { return ((x & 3) << 1) | ((x >> 2) & 1); }

// ------------------------------ LayerNorm -----------------------------------
__global__ __launch_bounds__(256)
void ln_kernel(const float* __restrict__ x, const float* __restrict__ g,
               const float* __restrict__ bb, float* __restrict__ y)
{
    long row = blockIdx.x;
    const float2* xr = (const float2*)(x + row * D_);
    float2*       yr = (float2*)(y + row * D_);
    int tid = threadIdx.x;
    float2 v = xr[tid];
    float s  = v.x + v.y;
    float sq = v.x * v.x + v.y * v.y;

    __shared__ float rs[8], rq[8];
    #pragma unroll
    for (int o = 16; o > 0; o >>= 1) {
        s  += __shfl_xor_sync(0xffffffffu, s,  o);
        sq += __shfl_xor_sync(0xffffffffu, sq, o);
    }
    int wid = tid >> 5;
    if ((tid & 31) == 0) { rs[wid] = s; rq[wid] = sq; }
    __syncthreads();
    if (tid == 0) {
        float a = 0.f, b2 = 0.f;
        #pragma unroll
        for (int w = 0; w < 8; w++) { a += rs[w]; b2 += rq[w]; }
        rs[0] = a; rq[0] = b2;
    }
    __syncthreads();
    float mean = rs[0] * (1.0f / D_);
    float var  = rq[0] * (1.0f / D_) - mean * mean;
    float rstd = rsqrtf(var + 1e-5f);
    const float2* gv2 = (const float2*)g;
    const float2* bv2 = (const float2*)bb;
    float2 gv = gv2[tid], bv = bv2[tid];
    float2 o;
    o.x = (v.x - mean) * rstd * gv.x + bv.x;
    o.y = (v.y - mean) * rstd * gv.y + bv.y;
    yr[tid] = o;
}

// ------------------------- TF32 helpers --------------------------------------
__device__ __forceinline__ uint32_t f2tf(float f) {
    uint32_t u;
    asm("cvt.rna.tf32.f32 %0, %1;" : "=r"(u) : "f"(f));
    return u;
}

__device__ __forceinline__ void mma_tf32(float c[4], const uint32_t a[4],
                                         const uint32_t b[2]) {
    asm volatile(
        "mma.sync.aligned.m16n8k8.row.col.f32.tf32.tf32.f32 "
        "{%0,%1,%2,%3},{%4,%5,%6,%7},{%8,%9},{%0,%1,%2,%3};\n"
        : "+f"(c[0]), "+f"(c[1]), "+f"(c[2]), "+f"(c[3])
        : "r"(a[0]), "r"(a[1]), "r"(a[2]), "r"(a[3]), "r"(b[0]), "r"(b[1]));
}

__device__ __forceinline__ void cp16(float* dst_smem, const float* src, bool valid) {
    uint32_t d = (uint32_t)__cvta_generic_to_shared(dst_smem);
    int sz = valid ? 16 : 0;
    asm volatile("cp.async.cg.shared.global [%0], [%1], 16, %2;\n"
                 :: "r"(d), "l"(src), "r"(sz));
}
#define CP_COMMIT() asm volatile("cp.async.commit_group;\n" ::: "memory")
#define CP_WAIT0()  asm volatile("cp.async.wait_group 0;\n" ::: "memory")
#define CP_WAIT1()  asm volatile("cp.async.wait_group 1;\n" ::: "memory")

__device__ __forceinline__ uint32_t ldu(const float* p) {
    return __float_as_uint(*p);
}

// ------------------------------ TF32 MMA GEMM --------------------------------
// (projections + FC) 3-stage cp.async pipeline.
// CVT_OUT: store tf32-rounded. PERM_OUT: pair-permute output columns in 8-groups.
template<int BM, int BN, int WM, int WN, bool TRANS_B, bool CVT_OUT, bool PERM_OUT>
__global__ __launch_bounds__(256)
void mma_gemm(const float* __restrict__ A, const float* __restrict__ Bm,
              float* __restrict__ C, float* __restrict__ C2,
              const float* __restrict__ bias1, const float* __restrict__ bias2,
              const float* __restrict__ Res,
              int M, int N, int K, int lda, int ldb, int ldc,
              float alpha)
{
    constexpr int BK = 16;
    constexpr int MT = WM / 16;
    constexpr int NT = WN / 8;
    constexpr int WCOLS = BN / WN;
    static_assert((BM / WM) * (BN / WN) == 8, "8 warps required");

    __shared__ float As[3][BM][BK + 4];
    __shared__ float Bs[3][TRANS_B ? BN : BK][TRANS_B ? (BK + 4) : (BN + 8)];

    int m0 = blockIdx.y * BM, n0 = blockIdx.x * BN;

    int tid  = threadIdx.x;
    int warp = tid >> 5, lane = tid & 31;
    int wm0 = (warp / WCOLS) * WM;
    int wn0 = (warp % WCOLS) * WN;

    auto ldg_async = [&](int k0, int buf) {
        #pragma unroll
        for (int it = 0; it < (BM * BK) / (4 * 256); it++) {
            int s = tid + it * 256;
            int row = s >> 2, kq = s & 3;
            int gm = m0 + row;
            cp16(&As[buf][row][kq * 4], A + (long)gm * lda + k0 + kq * 4, gm < M);
        }
        if (TRANS_B) {
            #pragma unroll
            for (int it = 0; it < (BN * BK) / (4 * 256); it++) {
                int s = tid + it * 256;
                int n = s >> 2, kq = s & 3;
                int gn = n0 + n;
                cp16(&Bs[buf][n][kq * 4], Bm + (long)gn * ldb + k0 + kq * 4, gn < N);
            }
        } else {
            #pragma unroll
            for (int it = 0; it < (BK * BN) / (4 * 256); it++) {
                int s = tid + it * 256;
                int kk = s / (BN / 4), nq = s % (BN / 4);
                cp16(&Bs[buf][kk][nq * 4],
                     Bm + (long)(k0 + kk) * ldb + n0 + nq * 4, true);
            }
        }
        CP_COMMIT();
    };

    float acc[MT][NT][4];
    #pragma unroll
    for (int i = 0; i < MT; i++)
        #pragma unroll
        for (int j = 0; j < NT; j++)
            #pragma unroll
            for (int e = 0; e < 4; e++) acc[i][j][e] = 0.f;

    const int nIter = K / BK;
    ldg_async(0, 0);
    if (nIter > 1) ldg_async(BK, 1);
    if (nIter > 1) { CP_WAIT1(); } else { CP_WAIT0(); }
    __syncthreads();

    for (int itk = 0; itk < nIter; itk++) {
        int buf = itk % 3;
        if (itk + 2 < nIter) ldg_async((itk + 2) * BK, (itk + 2) % 3);

        #pragma unroll
        for (int ks = 0; ks < 2; ks++) {
            const int kb = ks * 8;
            const int kc = kb + (lane & 3);
            uint32_t af[MT][4];
            uint32_t bf[NT][2];
            #pragma unroll
            for (int mt = 0; mt < MT; mt++) {
                int mrow = wm0 + mt * 16 + (lane >> 2);
                af[mt][0] = f2tf(As[buf][mrow    ][kc    ]);
                af[mt][1] = f2tf(As[buf][mrow + 8][kc    ]);
                af[mt][2] = f2tf(As[buf][mrow    ][kc + 4]);
                af[mt][3] = f2tf(As[buf][mrow + 8][kc + 4]);
            }
            #pragma unroll
            for (int nt = 0; nt < NT; nt++) {
                int ncol = wn0 + nt * 8 + (lane >> 2);
                if (TRANS_B) {
                    bf[nt][0] = f2tf(Bs[buf][ncol][kc    ]);
                    bf[nt][1] = f2tf(Bs[buf][ncol][kc + 4]);
                } else {
                    bf[nt][0] = f2tf(Bs[buf][kc    ][ncol]);
                    bf[nt][1] = f2tf(Bs[buf][kc + 4][ncol]);
                }
            }
            #pragma unroll
            for (int mt = 0; mt < MT; mt++)
                #pragma unroll
                for (int nt = 0; nt < NT; nt++)
                    mma_tf32(acc[mt][nt], af[mt], bf[nt]);
        }

        if (itk + 1 < nIter) {
            if (itk + 2 < nIter) { CP_WAIT1(); } else { CP_WAIT0(); }
        }
        __syncthreads();
    }

    auto emit = [&](int gm, int gn, float v) {
        if (gm < M && gn < N) {
            float val = v * alpha;
            if (Res) val += Res[(long)gm * ldc + gn];
            int gns = PERM_OUT ? ((gn & ~7) | pos8(gn & 7)) : gn;
            if (C2) {
                float v1 = val + bias1[gn];
                float v2 = val + bias2[gn];
                if (CVT_OUT) { v1 = __uint_as_float(f2tf(v1)); v2 = __uint_as_float(f2tf(v2)); }
                C [(long)gm * ldc + gns] = v1;
                C2[(long)gm * ldc + gns] = v2;
            } else {
                float v1 = val + (bias1 ? bias1[gn] : 0.f);
                if (CVT_OUT) v1 = __uint_as_float(f2tf(v1));
                C[(long)gm * ldc + gns] = v1;
            }
        }
    };
    #pragma unroll
    for (int mt = 0; mt < MT; mt++) {
        #pragma unroll
        for (int nt = 0; nt < NT; nt++) {
            int gm = m0 + wm0 + mt * 16 + (lane >> 2);
            int gn = n0 + wn0 + nt * 8 + 2 * (lane & 3);
            emit(gm,     gn,     acc[mt][nt][0]);
            emit(gm,     gn + 1, acc[mt][nt][1]);
            emit(gm + 8, gn,     acc[mt][nt][2]);
            emit(gm + 8, gn + 1, acc[mt][nt][3]);
        }
    }
}

// ===================== FUSED ATTENTION ======================================
// One CTA: (b,h), 32 query rows, 512 threads. S strip [32 x 1024] in smem
// (natural layout). qu/qv/kh/p are dk pair-permuted; tile stride 72
// (== 8 mod 32) makes the paired float2 fragment loads bank-conflict-free.
#define S_STRIDE 1028
#define K_STRIDE 72
#define V_STRIDE 72
#define SMEM_FLOATS (32*S_STRIDE + 2*128*V_STRIDE + 2*32*K_STRIDE)

__global__ __launch_bounds__(512)
void fused_attn(const float* __restrict__ qu, const float* __restrict__ qv,
                const float* __restrict__ kh, const float* __restrict__ vh,
                const float* __restrict__ pbuf, const int* __restrict__ mask,
                float* __restrict__ attn, float* __restrict__ ctx)
{
    extern __shared__ float sm[];
    float* S   = sm;                          // [32][1028], natural
    float* KV0 = sm + 32 * S_STRIDE;          // [128][72]
    float* KV1 = KV0 + 128 * V_STRIDE;
    float* Qu  = KV1 + 128 * V_STRIDE;        // [32][72]
    float* Qv  = Qu + 32 * K_STRIDE;

    const int i0 = blockIdx.x * 32;
    const int z  = blockIdx.y;                // b*H + h
    const int b  = z >> 3, h = z & 7;
    const int tid = threadIdx.x;
    const int w = tid >> 5, lane = tid & 31;
    const float scale = 0.125f;
    const float NEG = __int_as_float(0xff7fffff);   // -FLT_MAX sentinel

    // ---- load Qu, Qv tiles (32 x 64) ----
    {
        int r = tid >> 4, kq = tid & 15;
        long base = ((long)(b * T_ + i0 + r) * D_ + h * DK_ + kq * 4);
        cp16(&Qu[r * K_STRIDE + kq * 4], qu + base, true);
        cp16(&Qv[r * K_STRIDE + kq * 4], qv + base, true);
    }
    CP_COMMIT();

    auto load_k = [&](int jt, float* buf) {
        #pragma unroll
        for (int it = 0; it < 4; it++) {
            int s = tid + it * 512;
            int n = s >> 4, kq = s & 15;
            cp16(&buf[n * K_STRIDE + kq * 4],
                 kh + ((long)(b * T_ + jt * 128 + n) * D_ + h * DK_ + kq * 4), true);
        }
        CP_COMMIT();
    };
    auto load_v = [&](int jt, float* buf) {
        #pragma unroll
        for (int it = 0; it < 4; it++) {
            int s = tid + it * 512;
            int n = s >> 4, kq = s & 15;
            cp16(&buf[n * V_STRIDE + kq * 4],
                 vh + ((long)(b * T_ + jt * 128 + n) * D_ + h * DK_ + kq * 4), true);
        }
        CP_COMMIT();
    };
    auto load_p = [&](int pt0, float* buf) {
        #pragma unroll
        for (int it = 0; it < 4; it++) {
            int s = tid + it * 512;
            int n = s >> 4, kq = s & 15;
            int p = pt0 + n;
            cp16(&buf[n * K_STRIDE + kq * 4],
                 pbuf + ((long)p * D_ + h * DK_ + kq * 4), p <= P_ - 1);
        }
        CP_COMMIT();
    };

    // warp mapping for score phases: mh = row-half(16), ne = col-strip of 16
    const int mh = w & 1, ne = w >> 1;
    const int r0 = mh * 16 + (lane >> 2);
    const int l  = lane & 3;

    // ---------------- Phase 1: ac = scale * Qu @ K^T ----------------
    load_k(0, KV0);
    CP_WAIT0();
    __syncthreads();

    {
        uint32_t au[8][4];                   // hoisted Qu fragments (paired LDS.64)
        #pragma unroll
        for (int kk = 0; kk < 8; kk++) {
            int kp = kk * 8 + 2 * l;
            float2 p0 = *(const float2*)&Qu[r0 * K_STRIDE + kp];
            float2 p1 = *(const float2*)&Qu[(r0 + 8) * K_STRIDE + kp];
            au[kk][0] = __float_as_uint(p0.x);
            au[kk][1] = __float_as_uint(p1.x);
            au[kk][2] = __float_as_uint(p0.y);
            au[kk][3] = __float_as_uint(p1.y);
        }

        for (int jt = 0; jt < 8; jt++) {
            float* cur = (jt & 1) ? KV1 : KV0;
            float* nxt = (jt & 1) ? KV0 : KV1;
            if (jt + 1 < 8) load_k(jt + 1, nxt);

            float acc[2][4] = {{0.f,0.f,0.f,0.f},{0.f,0.f,0.f,0.f}};
            #pragma unroll
            for (int kk = 0; kk < 8; kk++) {
                int kp = kk * 8 + 2 * l;
                #pragma unroll
                for (int nt = 0; nt < 2; nt++) {
                    int ncol = ne * 16 + nt * 8 + (lane >> 2);
                    float2 bp = *(const float2*)&cur[ncol * K_STRIDE + kp];
                    uint32_t bf[2] = { __float_as_uint(bp.x), __float_as_uint(bp.y) };
                    mma_tf32(acc[nt], au[kk], bf);
                }
            }
            #pragma unroll
            for (int nt = 0; nt < 2; nt++) {
                int c0 = jt * 128 + ne * 16 + nt * 8 + 2 * l;
                *(float2*)&S[r0 * S_STRIDE + c0] =
                    make_float2(acc[nt][0] * scale, acc[nt][1] * scale);
                *(float2*)&S[(r0 + 8) * S_STRIDE + c0] =
                    make_float2(acc[nt][2] * scale, acc[nt][3] * scale);
            }
            if (jt + 1 < 8) CP_WAIT0();
            __syncthreads();
        }
    }

    // ------------- Phase 2: bd scatter-add over p-window -------------
    const int pbase = (T_ - 1) - (i0 + 31);
    load_p(pbase, KV0);
    {
        uint32_t av[8][4];
        #pragma unroll
        for (int kk = 0; kk < 8; kk++) {
            int kp = kk * 8 + 2 * l;
            float2 p0 = *(const float2*)&Qv[r0 * K_STRIDE + kp];
            float2 p1 = *(const float2*)&Qv[(r0 + 8) * K_STRIDE + kp];
            av[kk][0] = __float_as_uint(p0.x);
            av[kk][1] = __float_as_uint(p1.x);
            av[kk][2] = __float_as_uint(p0.y);
            av[kk][3] = __float_as_uint(p1.y);
        }
        CP_WAIT0();
        __syncthreads();

        for (int pt = 0; pt < 9; pt++) {
            float* cur = (pt & 1) ? KV1 : KV0;
            float* nxt = (pt & 1) ? KV0 : KV1;
            if (pt + 1 < 9) load_p(pbase + (pt + 1) * 128, nxt);

            float acc[2][4] = {{0.f,0.f,0.f,0.f},{0.f,0.f,0.f,0.f}};
            #pragma unroll
            for (int kk = 0; kk < 8; kk++) {
                int kp = kk * 8 + 2 * l;
                #pragma unroll
                for (int nt = 0; nt < 2; nt++) {
                    int ncol = ne * 16 + nt * 8 + (lane >> 2);
                    float2 bp = *(const float2*)&cur[ncol * K_STRIDE + kp];
                    uint32_t bf[2] = { __float_as_uint(bp.x), __float_as_uint(bp.y) };
                    mma_tf32(acc[nt], av[kk], bf);
                }
            }
            const int pt0 = pbase + pt * 128;
            #pragma unroll
            for (int nt = 0; nt < 2; nt++) {
                int c0 = ne * 16 + nt * 8 + 2 * l;
                #pragma unroll
                for (int e = 0; e < 4; e++) {
                    int r = r0 + (e >> 1) * 8;
                    int p = pt0 + c0 + (e & 1);
                    int j = p - (T_ - 1) + i0 + r;
                    if ((unsigned)j < (unsigned)T_)
                        S[r * S_STRIDE + j] += acc[nt][e] * scale;
                }
            }
            if (pt + 1 < 9) CP_WAIT0();
            __syncthreads();
        }
    }

    // -------- prefetch V tile 0 (overlaps softmax) --------
    load_v(0, KV0);

    // ------ Phase 3: softmax; attn gets fp32, S gets tf32-rounded ------
    #pragma unroll
    for (int t = 0; t < 2; t++) {
        int r = w + 16 * t;
        int i = i0 + r;
        const int4*   mrow = (const int4*)(mask + ((long)b * T_ + i) * T_);
        float4*       srow = (float4*)(S + r * S_STRIDE);
        float4*       arow = (float4*)(attn + ((long)z * T_ + i) * T_);

        float4 vals[8];
        float lmax = NEG;
        #pragma unroll
        for (int e = 0; e < 8; e++) {
            int idx = e * 32 + lane;
            float4 v = srow[idx];
            int4   m = mrow[idx];
            v.x = (m.x == 0) ? NEG : v.x;
            v.y = (m.y == 0) ? NEG : v.y;
            v.z = (m.z == 0) ? NEG : v.z;
            v.w = (m.w == 0) ? NEG : v.w;
            vals[e] = v;
            lmax = fmaxf(lmax, fmaxf(fmaxf(v.x, v.y), fmaxf(v.z, v.w)));
        }
        #pragma unroll
        for (int o = 16; o > 0; o >>= 1)
            lmax = fmaxf(lmax, __shfl_xor_sync(0xffffffffu, lmax, o));

        if (lmax == NEG) {
            float4 zero = make_float4(0.f, 0.f, 0.f, 0.f);
            #pragma unroll
            for (int e = 0; e < 8; e++) {
                int idx = e * 32 + lane;
                srow[idx] = zero;
                arow[idx] = zero;
            }
            continue;
        }
        float sum = 0.f;
        #pragma unroll
        for (int e = 0; e < 8; e++) {
            float4 v = vals[e];
            v.x = __expf(v.x - lmax); v.y = __expf(v.y - lmax);
            v.z = __expf(v.z - lmax); v.w = __expf(v.w - lmax);
            vals[e] = v;
            sum += (v.x + v.y) + (v.z + v.w);
        }
        #pragma unroll
        for (int o = 16; o > 0; o >>= 1)
            sum += __shfl_xor_sync(0xffffffffu, sum, o);
        float inv = 1.0f / sum;
        #pragma unroll
        for (int e = 0; e < 8; e++) {
            int idx = e * 32 + lane;
            float4 v = vals[e];
            v.x *= inv; v.y *= inv; v.z *= inv; v.w *= inv;
            arow[idx] = v;                       // exact fp32 out
            float4 vt;                           // tf32-rounded smem copy
            vt.x = __uint_as_float(f2tf(v.x));
            vt.y = __uint_as_float(f2tf(v.y));
            vt.z = __uint_as_float(f2tf(v.z));
            vt.w = __uint_as_float(f2tf(v.w));
            srow[idx] = vt;
        }
    }
    CP_WAIT0();
    __syncthreads();

    // ---------------- Phase 4: O = S @ V -> ctx ----------------
    const int mt = w >> 3, nt4 = w & 7;    // 2 x 8 warp grid over [32 x 64]
    float oacc[4] = {0.f, 0.f, 0.f, 0.f};
    const int r4 = mt * 16 + (lane >> 2);
    const int vn = nt4 * 8 + (lane >> 2);

    for (int jt = 0; jt < 8; jt++) {
        float* cur = (jt & 1) ? KV1 : KV0;
        float* nxt = (jt & 1) ? KV0 : KV1;
        if (jt + 1 < 8) load_v(jt + 1, nxt);

        #pragma unroll
        for (int kk = 0; kk < 16; kk++) {
            int kc = kk * 8 + l;
            uint32_t af[4] = { ldu(&S[r4 * S_STRIDE + jt * 128 + kc]),
                               ldu(&S[(r4 + 8) * S_STRIDE + jt * 128 + kc]),
                               ldu(&S[r4 * S_STRIDE + jt * 128 + kc + 4]),
                               ldu(&S[(r4 + 8) * S_STRIDE + jt * 128 + kc + 4]) };
            uint32_t bf[2] = { ldu(&cur[kc * V_STRIDE + vn]),
                               ldu(&cur[(kc + 4) * V_STRIDE + vn]) };
            mma_tf32(oacc, af, bf);
        }
        if (jt + 1 < 8) CP_WAIT0();
        __syncthreads();
    }

    const int n0 = nt4 * 8 + 2 * l;
    long o0 = (long)(b * T_ + i0 + r4) * D_ + h * DK_ + n0;
    long o1 = (long)(b * T_ + i0 + r4 + 8) * D_ + h * DK_ + n0;
    *(float2*)&ctx[o0] = make_float2(oacc[0], oacc[1]);
    *(float2*)&ctx[o1] = make_float2(oacc[2], oacc[3]);
}

// ------------------------------ launch ---------------------------------------
extern "C" void kernel_launch(void* const* d_in, const int* in_sizes, int n_in,
                              void* d_out, int out_size)
{
    const float* q    = (const float*)d_in[0];
    const float* k    = (const float*)d_in[1];
    const float* v    = (const float*)d_in[2];
    const float* pos  = (const float*)d_in[3];
    const int*   mask = (const int*)  d_in[4];
    const float* lnqg = (const float*)d_in[5],  *lnqb = (const float*)d_in[6];
    const float* lnkg = (const float*)d_in[7],  *lnkb = (const float*)d_in[8];
    const float* lnvg = (const float*)d_in[9],  *lnvb = (const float*)d_in[10];
    const float* wq   = (const float*)d_in[11], *wk   = (const float*)d_in[12];
    const float* wv   = (const float*)d_in[13], *wpos = (const float*)d_in[14];
    const float* wfc  = (const float*)d_in[15];
    const float* pbu  = (const float*)d_in[16], *pbv  = (const float*)d_in[17];

    float* out  = (float*)d_out;                 // [B,T,D]
    float* attn = out + (size_t)ND_;             // [B,H,T,T]

    float *qn,*kn,*vn,*qu,*qvb,*kh,*vh,*pb,*ctx;
    cudaGetSymbolAddress((void**)&qn,  g_qn);
    cudaGetSymbolAddress((void**)&kn,  g_kn);
    cudaGetSymbolAddress((void**)&vn,  g_vn);
    cudaGetSymbolAddress((void**)&qu,  g_qu);
    cudaGetSymbolAddress((void**)&qvb, g_qv);
    cudaGetSymbolAddress((void**)&kh,  g_kh);
    cudaGetSymbolAddress((void**)&vh,  g_vh);
    cudaGetSymbolAddress((void**)&pb,  g_p);
    cudaGetSymbolAddress((void**)&ctx, g_ctx);

    static const size_t fused_smem = SMEM_FLOATS * sizeof(float);
    cudaFuncSetAttribute(fused_attn,
                         cudaFuncAttributeMaxDynamicSharedMemorySize,
                         (int)fused_smem);

    // LayerNorms
    ln_kernel<<<NROW_, 256>>>(q, lnqg, lnqb, qn);
    ln_kernel<<<NROW_, 256>>>(k, lnkg, lnkb, kn);
    ln_kernel<<<NROW_, 256>>>(v, lnvg, lnvb, vn);

    // Q projection -> qu/qv (tf32, dk pair-permuted)
    mma_gemm<128,128,64,32,true,true,true><<<dim3(4,64,1),256>>>(
        qn, wq, qu, qvb, pbu, pbv, nullptr,
        NROW_, D_, D_, D_, D_, D_, 1.f);
    // K projection (tf32, dk pair-permuted)
    mma_gemm<128,128,64,32,true,true,true><<<dim3(4,64,1),256>>>(
        kn, wk, kh, nullptr, nullptr, nullptr, nullptr,
        NROW_, D_, D_, D_, D_, D_, 1.f);
    // V projection (tf32, natural)
    mma_gemm<128,128,64,32,true,true,false><<<dim3(4,64,1),256>>>(
        vn, wv, vh, nullptr, nullptr, nullptr, nullptr,
        NROW_, D_, D_, D_, D_, D_, 1.f);
    // pos projection  (M = 2047, tf32, dk pair-permuted)
    mma_gemm<128,128,64,32,true,true,true><<<dim3(4,16,1),256>>>(
        pos, wpos, pb, nullptr, nullptr, nullptr, nullptr,
        P_, D_, D_, D_, D_, D_, 1.f);

    // fused attention: ac + bd(rel-shift) + softmax + attn-write + PV
    fused_attn<<<dim3(32, 64), 512, fused_smem>>>(
        qu, qvb, kh, vh, pb, mask, attn, ctx);

    // out = ctx @ Wfc^T + residual(q)  (fp32 output)
    mma_gemm<128,128,64,32,true,false,false><<<dim3(4,64,1),256>>>(
        ctx, wfc, out, nullptr, nullptr, nullptr, q,
        NROW_, D_, D_, D_, D_, D_, 1.f);
}

// round 11
// speedup vs baseline: 1.3210x; 1.0060x over previous
#include <cuda_runtime.h>
#include <cuda_bf16.h>
#include <math.h>
#include <stdint.h>

// Problem constants
#define B_  8
#define T_  1024
#define D_  512
#define H_  8
#define DK_ 64
#define P_  2047          // 2*T-1
#define NROW_ (B_*T_)     // 8192
#define ND_  (NROW_*D_)   // 4194304

// -------------------- device scratch (no allocs allowed) --------------------
__device__ float g_qn [ND_];
__device__ float g_kn [ND_];
__device__ float g_vn [ND_];
__device__ float g_qu [ND_];   // qh + pos_bias_u (tf32, dk pair-permuted)
__device__ float g_qv [ND_];   // qh + pos_bias_v (tf32, dk pair-permuted)
__device__ float g_kh [ND_];   // tf32, dk pair-permuted
__device__ float g_vh [ND_];   // tf32, natural
__device__ float g_p  [(P_+1)*D_]; // tf32, dk pair-permuted (row 2047 = pad)
__device__ float g_ctx[ND_];   // attn @ V (tf32-rounded at producer)
__device__ float g_w  [5][D_*D_];  // tf32-rounded weights: wq,wk,wv,wpos,wfc
__device__ float g_pr [P_*D_];     // tf32-rounded pos input

__device__ __forceinline__ int pos8(int x) { return ((x & 3) << 1) | ((x >> 2) & 1); }

// ------------------------- TF32 helpers --------------------------------------
__device__ __forceinline__ uint32_t f2tf(float f) {
    uint32_t u;
    asm("cvt.rna.tf32.f32 %0, %1;" : "=r"(u) : "f"(f));
    return u;
}
__device__ __forceinline__ float tfr(float f) { return __uint_as_float(f2tf(f)); }

__device__ __forceinline__ void mma_tf32(float c[4], const uint32_t a[4],
                                         const uint32_t b[2]) {
    asm volatile(
        "mma.sync.aligned.m16n8k8.row.col.f32.tf32.tf32.f32 "
        "{%0,%1,%2,%3},{%4,%5,%6,%7},{%8,%9},{%0,%1,%2,%3};\n"
        : "+f"(c[0]), "+f"(c[1]), "+f"(c[2]), "+f"(c[3])
        : "r"(a[0]), "r"(a[1]), "r"(a[2]), "r"(a[3]), "r"(b[0]), "r"(b[1]));
}

__device__ __forceinline__ void cp16(float* dst_smem, const float* src, bool valid) {
    uint32_t d = (uint32_t)__cvta_generic_to_shared(dst_smem);
    int sz = valid ? 16 : 0;
    asm volatile("cp.async.cg.shared.global [%0], [%1], 16, %2;\n"
                 :: "r"(d), "l"(src), "r"(sz));
}
#define CP_COMMIT() asm volatile("cp.async.commit_group;\n" ::: "memory")
#define CP_WAIT0()  asm volatile("cp.async.wait_group 0;\n" ::: "memory")
#define CP_WAIT1()  asm volatile("cp.async.wait_group 1;\n" ::: "memory")

__device__ __forceinline__ uint32_t ldu(const float* p) {
    return __float_as_uint(*p);
}

// ----------------------- tf32 pre-round pass ---------------------------------
__global__ __launch_bounds__(256)
void round_kernel(const float* __restrict__ src, float* __restrict__ dst, int n4)
{
    int i = blockIdx.x * 256 + threadIdx.x;
    if (i < n4) {
        float4 v = ((const float4*)src)[i];
        v.x = tfr(v.x); v.y = tfr(v.y); v.z = tfr(v.z); v.w = tfr(v.w);
        ((float4*)dst)[i] = v;
    }
}

// ------------------------------ LayerNorm (tf32-rounded out) ------------------
__global__ __launch_bounds__(256)
void ln_kernel(const float* __restrict__ x, const float* __restrict__ g,
               const float* __restrict__ bb, float* __restrict__ y)
{
    long row = blockIdx.x;
    const float2* xr = (const float2*)(x + row * D_);
    float2*       yr = (float2*)(y + row * D_);
    int tid = threadIdx.x;
    float2 v = xr[tid];
    float s  = v.x + v.y;
    float sq = v.x * v.x + v.y * v.y;

    __shared__ float rs[8], rq[8];
    #pragma unroll
    for (int o = 16; o > 0; o >>= 1) {
        s  += __shfl_xor_sync(0xffffffffu, s,  o);
        sq += __shfl_xor_sync(0xffffffffu, sq, o);
    }
    int wid = tid >> 5;
    if ((tid & 31) == 0) { rs[wid] = s; rq[wid] = sq; }
    __syncthreads();
    if (tid == 0) {
        float a = 0.f, b2 = 0.f;
        #pragma unroll
        for (int w = 0; w < 8; w++) { a += rs[w]; b2 += rq[w]; }
        rs[0] = a; rq[0] = b2;
    }
    __syncthreads();
    float mean = rs[0] * (1.0f / D_);
    float var  = rq[0] * (1.0f / D_) - mean * mean;
    float rstd = rsqrtf(var + 1e-5f);
    const float2* gv2 = (const float2*)g;
    const float2* bv2 = (const float2*)bb;
    float2 gv = gv2[tid], bv = bv2[tid];
    float2 o;
    o.x = tfr((v.x - mean) * rstd * gv.x + bv.x);
    o.y = tfr((v.y - mean) * rstd * gv.y + bv.y);
    yr[tid] = o;
}

// ------------------------------ TF32 MMA GEMM core ----------------------------
// All operands pre-rounded to tf32 -> pure LDS, no cvt in mainloop.
template<int BM, int BN, int WM, int WN, bool TRANS_B, bool CVT_OUT>
__device__ __forceinline__
void gemm_core(const float* __restrict__ A, const float* __restrict__ Bm,
               float* __restrict__ C, float* __restrict__ C2,
               const float* __restrict__ bias1, const float* __restrict__ bias2,
               const float* __restrict__ Res,
               int M, int N, int K, int lda, int ldb, int ldc,
               float alpha, bool perm, int m0, int n0)
{
    constexpr int BK = 16;
    constexpr int MT = WM / 16;
    constexpr int NT = WN / 8;
    constexpr int WCOLS = BN / WN;
    static_assert((BM / WM) * (BN / WN) == 8, "8 warps required");

    __shared__ float As[3][BM][BK + 4];
    __shared__ float Bs[3][TRANS_B ? BN : BK][TRANS_B ? (BK + 4) : (BN + 8)];

    int tid  = threadIdx.x;
    int warp = tid >> 5, lane = tid & 31;
    int wm0 = (warp / WCOLS) * WM;
    int wn0 = (warp % WCOLS) * WN;

    auto ldg_async = [&](int k0, int buf) {
        #pragma unroll
        for (int it = 0; it < (BM * BK) / (4 * 256); it++) {
            int s = tid + it * 256;
            int row = s >> 2, kq = s & 3;
            int gm = m0 + row;
            cp16(&As[buf][row][kq * 4], A + (long)gm * lda + k0 + kq * 4, gm < M);
        }
        if (TRANS_B) {
            #pragma unroll
            for (int it = 0; it < (BN * BK) / (4 * 256); it++) {
                int s = tid + it * 256;
                int n = s >> 2, kq = s & 3;
                int gn = n0 + n;
                cp16(&Bs[buf][n][kq * 4], Bm + (long)gn * ldb + k0 + kq * 4, gn < N);
            }
        } else {
            #pragma unroll
            for (int it = 0; it < (BK * BN) / (4 * 256); it++) {
                int s = tid + it * 256;
                int kk = s / (BN / 4), nq = s % (BN / 4);
                cp16(&Bs[buf][kk][nq * 4],
                     Bm + (long)(k0 + kk) * ldb + n0 + nq * 4, true);
            }
        }
        CP_COMMIT();
    };

    float acc[MT][NT][4];
    #pragma unroll
    for (int i = 0; i < MT; i++)
        #pragma unroll
        for (int j = 0; j < NT; j++)
            #pragma unroll
            for (int e = 0; e < 4; e++) acc[i][j][e] = 0.f;

    const int nIter = K / BK;
    ldg_async(0, 0);
    if (nIter > 1) ldg_async(BK, 1);
    if (nIter > 1) { CP_WAIT1(); } else { CP_WAIT0(); }
    __syncthreads();

    for (int itk = 0; itk < nIter; itk++) {
        int buf = itk % 3;
        if (itk + 2 < nIter) ldg_async((itk + 2) * BK, (itk + 2) % 3);

        #pragma unroll
        for (int ks = 0; ks < 2; ks++) {
            const int kc = ks * 8 + (lane & 3);
            uint32_t af[MT][4];
            uint32_t bf[NT][2];
            #pragma unroll
            for (int mt = 0; mt < MT; mt++) {
                int mrow = wm0 + mt * 16 + (lane >> 2);
                af[mt][0] = ldu(&As[buf][mrow    ][kc    ]);
                af[mt][1] = ldu(&As[buf][mrow + 8][kc    ]);
                af[mt][2] = ldu(&As[buf][mrow    ][kc + 4]);
                af[mt][3] = ldu(&As[buf][mrow + 8][kc + 4]);
            }
            #pragma unroll
            for (int nt = 0; nt < NT; nt++) {
                int ncol = wn0 + nt * 8 + (lane >> 2);
                if (TRANS_B) {
                    bf[nt][0] = ldu(&Bs[buf][ncol][kc    ]);
                    bf[nt][1] = ldu(&Bs[buf][ncol][kc + 4]);
                } else {
                    bf[nt][0] = ldu(&Bs[buf][kc    ][ncol]);
                    bf[nt][1] = ldu(&Bs[buf][kc + 4][ncol]);
                }
            }
            #pragma unroll
            for (int mt = 0; mt < MT; mt++)
                #pragma unroll
                for (int nt = 0; nt < NT; nt++)
                    mma_tf32(acc[mt][nt], af[mt], bf[nt]);
        }

        if (itk + 1 < nIter) {
            if (itk + 2 < nIter) { CP_WAIT1(); } else { CP_WAIT0(); }
        }
        __syncthreads();
    }

    auto emit = [&](int gm, int gn, float v) {
        if (gm < M && gn < N) {
            float val = v * alpha;
            if (Res) val += Res[(long)gm * ldc + gn];
            int gns = perm ? ((gn & ~7) | pos8(gn & 7)) : gn;
            if (C2) {
                float v1 = val + bias1[gn];
                float v2 = val + bias2[gn];
                if (CVT_OUT) { v1 = tfr(v1); v2 = tfr(v2); }
                C [(long)gm * ldc + gns] = v1;
                C2[(long)gm * ldc + gns] = v2;
            } else {
                float v1 = val + (bias1 ? bias1[gn] : 0.f);
                if (CVT_OUT) v1 = tfr(v1);
                C[(long)gm * ldc + gns] = v1;
            }
        }
    };
    #pragma unroll
    for (int mt = 0; mt < MT; mt++) {
        #pragma unroll
        for (int nt = 0; nt < NT; nt++) {
            int gm = m0 + wm0 + mt * 16 + (lane >> 2);
            int gn = n0 + wn0 + nt * 8 + 2 * (lane & 3);
            emit(gm,     gn,     acc[mt][nt][0]);
            emit(gm,     gn + 1, acc[mt][nt][1]);
            emit(gm + 8, gn,     acc[mt][nt][2]);
            emit(gm + 8, gn + 1, acc[mt][nt][3]);
        }
    }
}

// generic wrapper (pos projection, FC)
template<int BM, int BN, int WM, int WN, bool TRANS_B, bool CVT_OUT>
__global__ __launch_bounds__(256)
void mma_gemm(const float* __restrict__ A, const float* __restrict__ Bm,
              float* __restrict__ C,
              const float* __restrict__ Res,
              int M, int N, int K, float alpha, int perm)
{
    gemm_core<BM,BN,WM,WN,TRANS_B,CVT_OUT>(
        A, Bm, C, nullptr, nullptr, nullptr, Res,
        M, N, K, K, K, N, alpha, perm != 0,
        blockIdx.y * BM, blockIdx.x * BN);
}

// merged Q/K/V projection: grid.z in {0,1,2}
__global__ __launch_bounds__(256)
void qkv_gemm(const float* __restrict__ qn, const float* __restrict__ kn,
              const float* __restrict__ vn,
              const float* __restrict__ wq, const float* __restrict__ wk,
              const float* __restrict__ wv,
              float* __restrict__ qu, float* __restrict__ kh,
              float* __restrict__ vh, float* __restrict__ qvb,
              const float* __restrict__ pbu, const float* __restrict__ pbv)
{
    int zz = blockIdx.z;
    const float* A  = (zz == 0) ? qn : (zz == 1) ? kn : vn;
    const float* Bm = (zz == 0) ? wq : (zz == 1) ? wk : wv;
    float* C  = (zz == 0) ? qu : (zz == 1) ? kh : vh;
    float* C2 = (zz == 0) ? qvb : nullptr;
    const float* b1 = (zz == 0) ? pbu : nullptr;
    const float* b2 = (zz == 0) ? pbv : nullptr;
    bool perm = (zz < 2);
    gemm_core<128,128,64,32,true,true>(
        A, Bm, C, C2, b1, b2, nullptr,
        NROW_, D_, D_, D_, D_, D_, 1.f, perm,
        blockIdx.y * 128, blockIdx.x * 128);
}

// ===================== FUSED ATTENTION ======================================
#define S_STRIDE 1028
#define K_STRIDE 72
#define V_STRIDE 72
#define SMEM_FLOATS (32*S_STRIDE + 2*128*V_STRIDE + 2*32*K_STRIDE)

__global__ __launch_bounds__(512)
void fused_attn(const float* __restrict__ qu, const float* __restrict__ qv,
                const float* __restrict__ kh, const float* __restrict__ vh,
                const float* __restrict__ pbuf, const int* __restrict__ mask,
                float* __restrict__ attn, float* __restrict__ ctx)
{
    extern __shared__ float sm[];
    float* S   = sm;                          // [32][1028], natural
    float* KV0 = sm + 32 * S_STRIDE;          // [128][72]
    float* KV1 = KV0 + 128 * V_STRIDE;
    float* Qu  = KV1 + 128 * V_STRIDE;        // [32][72]
    float* Qv  = Qu + 32 * K_STRIDE;

    const int i0 = blockIdx.x * 32;
    const int z  = blockIdx.y;                // b*H + h
    const int b  = z >> 3, h = z & 7;
    const int tid = threadIdx.x;
    const int w = tid >> 5, lane = tid & 31;
    const float scale = 0.125f;
    const float NEG = __int_as_float(0xff7fffff);

    {
        int r = tid >> 4, kq = tid & 15;
        long base = ((long)(b * T_ + i0 + r) * D_ + h * DK_ + kq * 4);
        cp16(&Qu[r * K_STRIDE + kq * 4], qu + base, true);
        cp16(&Qv[r * K_STRIDE + kq * 4], qv + base, true);
    }
    CP_COMMIT();

    auto load_k = [&](int jt, float* buf) {
        #pragma unroll
        for (int it = 0; it < 4; it++) {
            int s = tid + it * 512;
            int n = s >> 4, kq = s & 15;
            cp16(&buf[n * K_STRIDE + kq * 4],
                 kh + ((long)(b * T_ + jt * 128 + n) * D_ + h * DK_ + kq * 4), true);
        }
        CP_COMMIT();
    };
    auto load_v = [&](int jt, float* buf) {
        #pragma unroll
        for (int it = 0; it < 4; it++) {
            int s = tid + it * 512;
            int n = s >> 4, kq = s & 15;
            cp16(&buf[n * V_STRIDE + kq * 4],
                 vh + ((long)(b * T_ + jt * 128 + n) * D_ + h * DK_ + kq * 4), true);
        }
        CP_COMMIT();
    };
    auto load_p = [&](int pt0, float* buf) {
        #pragma unroll
        for (int it = 0; it < 4; it++) {
            int s = tid + it * 512;
            int n = s >> 4, kq = s & 15;
            int p = pt0 + n;
            cp16(&buf[n * K_STRIDE + kq * 4],
                 pbuf + ((long)p * D_ + h * DK_ + kq * 4), p <= P_ - 1);
        }
        CP_COMMIT();
    };

    const int mh = w & 1, ne = w >> 1;
    const int r0 = mh * 16 + (lane >> 2);
    const int l  = lane & 3;

    // ---------------- Phase 1: ac = scale * Qu @ K^T ----------------
    load_k(0, KV0);
    CP_WAIT0();
    __syncthreads();

    {
        uint32_t au[8][4];
        #pragma unroll
        for (int kk = 0; kk < 8; kk++) {
            int kp = kk * 8 + 2 * l;
            float2 p0 = *(const float2*)&Qu[r0 * K_STRIDE + kp];
            float2 p1 = *(const float2*)&Qu[(r0 + 8) * K_STRIDE + kp];
            au[kk][0] = __float_as_uint(p0.x);
            au[kk][1] = __float_as_uint(p1.x);
            au[kk][2] = __float_as_uint(p0.y);
            au[kk][3] = __float_as_uint(p1.y);
        }

        for (int jt = 0; jt < 8; jt++) {
            float* cur = (jt & 1) ? KV1 : KV0;
            float* nxt = (jt & 1) ? KV0 : KV1;
            if (jt + 1 < 8) load_k(jt + 1, nxt);

            float acc[2][4] = {{0.f,0.f,0.f,0.f},{0.f,0.f,0.f,0.f}};
            #pragma unroll
            for (int kk = 0; kk < 8; kk++) {
                int kp = kk * 8 + 2 * l;
                #pragma unroll
                for (int nt = 0; nt < 2; nt++) {
                    int ncol = ne * 16 + nt * 8 + (lane >> 2);
                    float2 bp = *(const float2*)&cur[ncol * K_STRIDE + kp];
                    uint32_t bf[2] = { __float_as_uint(bp.x), __float_as_uint(bp.y) };
                    mma_tf32(acc[nt], au[kk], bf);
                }
            }
            #pragma unroll
            for (int nt = 0; nt < 2; nt++) {
                int c0 = jt * 128 + ne * 16 + nt * 8 + 2 * l;
                *(float2*)&S[r0 * S_STRIDE + c0] =
                    make_float2(acc[nt][0] * scale, acc[nt][1] * scale);
                *(float2*)&S[(r0 + 8) * S_STRIDE + c0] =
                    make_float2(acc[nt][2] * scale, acc[nt][3] * scale);
            }
            if (jt + 1 < 8) CP_WAIT0();
            __syncthreads();
        }
    }

    // ------------- Phase 2: bd scatter-add over p-window -------------
    const int pbase = (T_ - 1) - (i0 + 31);
    load_p(pbase, KV0);
    {
        uint32_t av[8][4];
        #pragma unroll
        for (int kk = 0; kk < 8; kk++) {
            int kp = kk * 8 + 2 * l;
            float2 p0 = *(const float2*)&Qv[r0 * K_STRIDE + kp];
            float2 p1 = *(const float2*)&Qv[(r0 + 8) * K_STRIDE + kp];
            av[kk][0] = __float_as_uint(p0.x);
            av[kk][1] = __float_as_uint(p1.x);
            av[kk][2] = __float_as_uint(p0.y);
            av[kk][3] = __float_as_uint(p1.y);
        }
        CP_WAIT0();
        __syncthreads();

        for (int pt = 0; pt < 9; pt++) {
            float* cur = (pt & 1) ? KV1 : KV0;
            float* nxt = (pt & 1) ? KV0 : KV1;
            if (pt + 1 < 9) load_p(pbase + (pt + 1) * 128, nxt);

            float acc[2][4] = {{0.f,0.f,0.f,0.f},{0.f,0.f,0.f,0.f}};
            #pragma unroll
            for (int kk = 0; kk < 8; kk++) {
                int kp = kk * 8 + 2 * l;
                #pragma unroll
                for (int nt = 0; nt < 2; nt++) {
                    int ncol = ne * 16 + nt * 8 + (lane >> 2);
                    float2 bp = *(const float2*)&cur[ncol * K_STRIDE + kp];
                    uint32_t bf[2] = { __float_as_uint(bp.x), __float_as_uint(bp.y) };
                    mma_tf32(acc[nt], av[kk], bf);
                }
            }
            const int pt0 = pbase + pt * 128;
            #pragma unroll
            for (int nt = 0; nt < 2; nt++) {
                int c0 = ne * 16 + nt * 8 + 2 * l;
                #pragma unroll
                for (int e = 0; e < 4; e++) {
                    int r = r0 + (e >> 1) * 8;
                    int p = pt0 + c0 + (e & 1);
                    int j = p - (T_ - 1) + i0 + r;
                    if ((unsigned)j < (unsigned)T_)
                        S[r * S_STRIDE + j] += acc[nt][e] * scale;
                }
            }
            if (pt + 1 < 9) CP_WAIT0();
            __syncthreads();
        }
    }

    // -------- prefetch V tile 0 (overlaps softmax) --------
    load_v(0, KV0);

    // ------ Phase 3: softmax; attn gets fp32, S gets tf32-rounded ------
    #pragma unroll
    for (int t = 0; t < 2; t++) {
        int r = w + 16 * t;
        int i = i0 + r;
        const int4*   mrow = (const int4*)(mask + ((long)b * T_ + i) * T_);
        float4*       srow = (float4*)(S + r * S_STRIDE);
        float4*       arow = (float4*)(attn + ((long)z * T_ + i) * T_);

        float4 vals[8];
        float lmax = NEG;
        #pragma unroll
        for (int e = 0; e < 8; e++) {
            int idx = e * 32 + lane;
            float4 v = srow[idx];
            int4   m = mrow[idx];
            v.x = (m.x == 0) ? NEG : v.x;
            v.y = (m.y == 0) ? NEG : v.y;
            v.z = (m.z == 0) ? NEG : v.z;
            v.w = (m.w == 0) ? NEG : v.w;
            vals[e] = v;
            lmax = fmaxf(lmax, fmaxf(fmaxf(v.x, v.y), fmaxf(v.z, v.w)));
        }
        #pragma unroll
        for (int o = 16; o > 0; o >>= 1)
            lmax = fmaxf(lmax, __shfl_xor_sync(0xffffffffu, lmax, o));

        if (lmax == NEG) {
            float4 zero = make_float4(0.f, 0.f, 0.f, 0.f);
            #pragma unroll
            for (int e = 0; e < 8; e++) {
                int idx = e * 32 + lane;
                srow[idx] = zero;
                arow[idx] = zero;
            }
            continue;
        }
        float sum = 0.f;
        #pragma unroll
        for (int e = 0; e < 8; e++) {
            float4 v = vals[e];
            v.x = __expf(v.x - lmax); v.y = __expf(v.y - lmax);
            v.z = __expf(v.z - lmax); v.w = __expf(v.w - lmax);
            vals[e] = v;
            sum += (v.x + v.y) + (v.z + v.w);
        }
        #pragma unroll
        for (int o = 16; o > 0; o >>= 1)
            sum += __shfl_xor_sync(0xffffffffu, sum, o);
        float inv = 1.0f / sum;
        #pragma unroll
        for (int e = 0; e < 8; e++) {
            int idx = e * 32 + lane;
            float4 v = vals[e];
            v.x *= inv; v.y *= inv; v.z *= inv; v.w *= inv;
            arow[idx] = v;
            float4 vt;
            vt.x = tfr(v.x); vt.y = tfr(v.y);
            vt.z = tfr(v.z); vt.w = tfr(v.w);
            srow[idx] = vt;
        }
    }
    CP_WAIT0();
    __syncthreads();

    // ---------------- Phase 4: O = S @ V -> ctx (tf32-rounded) ---------------
    const int mt = w >> 3, nt4 = w & 7;
    float oacc[4] = {0.f, 0.f, 0.f, 0.f};
    const int r4 = mt * 16 + (lane >> 2);
    const int vn = nt4 * 8 + (lane >> 2);

    for (int jt = 0; jt < 8; jt++) {
        float* cur = (jt & 1) ? KV1 : KV0;
        float* nxt = (jt & 1) ? KV0 : KV1;
        if (jt + 1 < 8) load_v(jt + 1, nxt);

        #pragma unroll
        for (int kk = 0; kk < 16; kk++) {
            int kc = kk * 8 + l;
            uint32_t af[4] = { ldu(&S[r4 * S_STRIDE + jt * 128 + kc]),
                               ldu(&S[(r4 + 8) * S_STRIDE + jt * 128 + kc]),
                               ldu(&S[r4 * S_STRIDE + jt * 128 + kc + 4]),
                               ldu(&S[(r4 + 8) * S_STRIDE + jt * 128 + kc + 4]) };
            uint32_t bf[2] = { ldu(&cur[kc * V_STRIDE + vn]),
                               ldu(&cur[(kc + 4) * V_STRIDE + vn]) };
            mma_tf32(oacc, af, bf);
        }
        if (jt + 1 < 8) CP_WAIT0();
        __syncthreads();
    }

    const int n0 = nt4 * 8 + 2 * l;
    long o0 = (long)(b * T_ + i0 + r4) * D_ + h * DK_ + n0;
    long o1 = (long)(b * T_ + i0 + r4 + 8) * D_ + h * DK_ + n0;
    *(float2*)&ctx[o0] = make_float2(tfr(oacc[0]), tfr(oacc[1]));
    *(float2*)&ctx[o1] = make_float2(tfr(oacc[2]), tfr(oacc[3]));
}

// ------------------------------ launch ---------------------------------------
extern "C" void kernel_launch(void* const* d_in, const int* in_sizes, int n_in,
                              void* d_out, int out_size)
{
    const float* q    = (const float*)d_in[0];
    const float* k    = (const float*)d_in[1];
    const float* v    = (const float*)d_in[2];
    const float* pos  = (const float*)d_in[3];
    const int*   mask = (const int*)  d_in[4];
    const float* lnqg = (const float*)d_in[5],  *lnqb = (const float*)d_in[6];
    const float* lnkg = (const float*)d_in[7],  *lnkb = (const float*)d_in[8];
    const float* lnvg = (const float*)d_in[9],  *lnvb = (const float*)d_in[10];
    const float* wq   = (const float*)d_in[11], *wk   = (const float*)d_in[12];
    const float* wv   = (const float*)d_in[13], *wpos = (const float*)d_in[14];
    const float* wfc  = (const float*)d_in[15];
    const float* pbu  = (const float*)d_in[16], *pbv  = (const float*)d_in[17];

    float* out  = (float*)d_out;                 // [B,T,D]
    float* attn = out + (size_t)ND_;             // [B,H,T,T]

    float *qn,*kn,*vn,*qu,*qvb,*kh,*vh,*pb,*ctx,*wbuf,*prb;
    cudaGetSymbolAddress((void**)&qn,  g_qn);
    cudaGetSymbolAddress((void**)&kn,  g_kn);
    cudaGetSymbolAddress((void**)&vn,  g_vn);
    cudaGetSymbolAddress((void**)&qu,  g_qu);
    cudaGetSymbolAddress((void**)&qvb, g_qv);
    cudaGetSymbolAddress((void**)&kh,  g_kh);
    cudaGetSymbolAddress((void**)&vh,  g_vh);
    cudaGetSymbolAddress((void**)&pb,  g_p);
    cudaGetSymbolAddress((void**)&ctx, g_ctx);
    cudaGetSymbolAddress((void**)&wbuf, g_w);
    cudaGetSymbolAddress((void**)&prb, g_pr);

    static const size_t fused_smem = SMEM_FLOATS * sizeof(float);
    cudaFuncSetAttribute(fused_attn,
                         cudaFuncAttributeMaxDynamicSharedMemorySize,
                         (int)fused_smem);

    const int WN4 = (D_ * D_) / 4;              // 65536 float4 per weight

    // pre-round weights + pos to tf32 (bit-identical to in-loop cvt)
    round_kernel<<<WN4 / 256, 256>>>(wq,   wbuf + 0 * D_ * D_, WN4);
    round_kernel<<<WN4 / 256, 256>>>(wk,   wbuf + 1 * D_ * D_, WN4);
    round_kernel<<<WN4 / 256, 256>>>(wv,   wbuf + 2 * D_ * D_, WN4);
    round_kernel<<<WN4 / 256, 256>>>(wpos, wbuf + 3 * D_ * D_, WN4);
    round_kernel<<<WN4 / 256, 256>>>(wfc,  wbuf + 4 * D_ * D_, WN4);
    {
        int pn4 = (P_ * D_) / 4;                // 2047*512/4 = 262016
        round_kernel<<<(pn4 + 255) / 256, 256>>>(pos, prb, pn4);
    }

    // LayerNorms (tf32-rounded outputs)
    ln_kernel<<<NROW_, 256>>>(q, lnqg, lnqb, qn);
    ln_kernel<<<NROW_, 256>>>(k, lnkg, lnkb, kn);
    ln_kernel<<<NROW_, 256>>>(v, lnvg, lnvb, vn);

    // merged Q/K/V projections
    qkv_gemm<<<dim3(4,64,3),256>>>(qn, kn, vn,
        wbuf + 0 * D_ * D_, wbuf + 1 * D_ * D_, wbuf + 2 * D_ * D_,
        qu, kh, vh, qvb, pbu, pbv);

    // pos projection  (M = 2047, tf32, dk pair-permuted)
    mma_gemm<128,128,64,32,true,true><<<dim3(4,16,1),256>>>(
        prb, wbuf + 3 * D_ * D_, pb, nullptr,
        P_, D_, D_, 1.f, 1);

    // fused attention
    fused_attn<<<dim3(32, 64), 512, fused_smem>>>(
        qu, qvb, kh, vh, pb, mask, attn, ctx);

    // out = ctx @ Wfc^T + residual(q)  (fp32 output)
    mma_gemm<128,128,64,32,true,false><<<dim3(4,64,1),256>>>(
        ctx, wbuf + 4 * D_ * D_, out, q,
        NROW_, D_, D_, 1.f, 0);
}

// round 12
// speedup vs baseline: 1.3990x; 1.0590x over previous
#include <cuda_runtime.h>
#include <cuda_bf16.h>
#include <math.h>
#include <stdint.h>

// Problem constants
#define B_  8
#define T_  1024
#define D_  512
#define H_  8
#define DK_ 64
#define P_  2047          // 2*T-1
#define NROW_ (B_*T_)     // 8192
#define ND_  (NROW_*D_)   // 4194304

// -------------------- device scratch (no allocs allowed) --------------------
__device__ float g_qn [ND_];
__device__ float g_kn [ND_];
__device__ float g_vn [ND_];
__device__ float g_qu [ND_];   // qh + pos_bias_u (tf32, dk pair-permuted)
__device__ float g_qv [ND_];   // qh + pos_bias_v (tf32, dk pair-permuted)
__device__ float g_kh [ND_];   // tf32, dk pair-permuted
__device__ float g_vh [ND_];   // tf32, natural
__device__ float g_p  [(P_+1)*D_]; // tf32, dk pair-permuted (row 2047 = pad)
__device__ float g_ctx[ND_];   // attn @ V (tf32-rounded at producer)
__device__ float g_w  [5][D_*D_];  // tf32-rounded weights: wq,wk,wv,wpos,wfc
__device__ float g_pr [P_*D_];     // tf32-rounded pos input

__device__ __forceinline__ int pos8(int x) { return ((x & 3) << 1) | ((x >> 2) & 1); }

// ------------------------- TF32 helpers --------------------------------------
__device__ __forceinline__ uint32_t f2tf(float f) {
    uint32_t u;
    asm("cvt.rna.tf32.f32 %0, %1;" : "=r"(u) : "f"(f));
    return u;
}
__device__ __forceinline__ float tfr(float f) { return __uint_as_float(f2tf(f)); }

__device__ __forceinline__ void mma_tf32(float c[4], const uint32_t a[4],
                                         const uint32_t b[2]) {
    asm volatile(
        "mma.sync.aligned.m16n8k8.row.col.f32.tf32.tf32.f32 "
        "{%0,%1,%2,%3},{%4,%5,%6,%7},{%8,%9},{%0,%1,%2,%3};\n"
        : "+f"(c[0]), "+f"(c[1]), "+f"(c[2]), "+f"(c[3])
        : "r"(a[0]), "r"(a[1]), "r"(a[2]), "r"(a[3]), "r"(b[0]), "r"(b[1]));
}

__device__ __forceinline__ void cp16(float* dst_smem, const float* src, bool valid) {
    uint32_t d = (uint32_t)__cvta_generic_to_shared(dst_smem);
    int sz = valid ? 16 : 0;
    asm volatile("cp.async.cg.shared.global [%0], [%1], 16, %2;\n"
                 :: "r"(d), "l"(src), "r"(sz));
}
#define CP_COMMIT() asm volatile("cp.async.commit_group;\n" ::: "memory")
#define CP_WAIT0()  asm volatile("cp.async.wait_group 0;\n" ::: "memory")
#define CP_WAIT1()  asm volatile("cp.async.wait_group 1;\n" ::: "memory")

__device__ __forceinline__ uint32_t ldu(const float* p) {
    return __float_as_uint(*p);
}

// ----------------------- tf32 pre-round pass (single launch) ------------------
// grid.y selects tensor: 0..4 = weights (n4=65536), 5 = pos (n4=262016)
__global__ __launch_bounds__(256)
void round_all(const float* __restrict__ wq, const float* __restrict__ wk,
               const float* __restrict__ wv, const float* __restrict__ wpos,
               const float* __restrict__ wfc, const float* __restrict__ pos,
               float* __restrict__ wbuf, float* __restrict__ prb)
{
    int slice = blockIdx.y;
    const float* src;
    float* dst;
    int n4;
    if (slice < 5) {
        src = (slice == 0) ? wq : (slice == 1) ? wk : (slice == 2) ? wv
            : (slice == 3) ? wpos : wfc;
        dst = wbuf + (long)slice * D_ * D_;
        n4 = (D_ * D_) / 4;
    } else {
        src = pos;
        dst = prb;
        n4 = (P_ * D_) / 4;
    }
    int i = blockIdx.x * 256 + threadIdx.x;
    if (i < n4) {
        float4 v = ((const float4*)src)[i];
        v.x = tfr(v.x); v.y = tfr(v.y); v.z = tfr(v.z); v.w = tfr(v.w);
        ((float4*)dst)[i] = v;
    }
}

// ------------------------- merged LayerNorm (3 slices) ------------------------
__global__ __launch_bounds__(256)
void ln3_kernel(const float* __restrict__ q, const float* __restrict__ k,
                const float* __restrict__ v,
                const float* __restrict__ gq, const float* __restrict__ bq,
                const float* __restrict__ gk, const float* __restrict__ bk,
                const float* __restrict__ gv, const float* __restrict__ bv,
                float* __restrict__ yq, float* __restrict__ yk,
                float* __restrict__ yv)
{
    int slice = blockIdx.y;
    const float* x  = (slice == 0) ? q  : (slice == 1) ? k  : v;
    const float* g  = (slice == 0) ? gq : (slice == 1) ? gk : gv;
    const float* bb = (slice == 0) ? bq : (slice == 1) ? bk : bv;
    float*       y  = (slice == 0) ? yq : (slice == 1) ? yk : yv;

    long row = blockIdx.x;
    const float2* xr = (const float2*)(x + row * D_);
    float2*       yr = (float2*)(y + row * D_);
    int tid = threadIdx.x;
    float2 vv = xr[tid];
    float s  = vv.x + vv.y;
    float sq = vv.x * vv.x + vv.y * vv.y;

    __shared__ float rs[8], rq[8];
    #pragma unroll
    for (int o = 16; o > 0; o >>= 1) {
        s  += __shfl_xor_sync(0xffffffffu, s,  o);
        sq += __shfl_xor_sync(0xffffffffu, sq, o);
    }
    int wid = tid >> 5;
    if ((tid & 31) == 0) { rs[wid] = s; rq[wid] = sq; }
    __syncthreads();
    if (tid == 0) {
        float a = 0.f, b2 = 0.f;
        #pragma unroll
        for (int w = 0; w < 8; w++) { a += rs[w]; b2 += rq[w]; }
        rs[0] = a; rq[0] = b2;
    }
    __syncthreads();
    float mean = rs[0] * (1.0f / D_);
    float var  = rq[0] * (1.0f / D_) - mean * mean;
    float rstd = rsqrtf(var + 1e-5f);
    const float2* gv2 = (const float2*)g;
    const float2* bv2 = (const float2*)bb;
    float2 gg = gv2[tid], bbv = bv2[tid];
    float2 o;
    o.x = tfr((vv.x - mean) * rstd * gg.x + bbv.x);
    o.y = tfr((vv.y - mean) * rstd * gg.y + bbv.y);
    yr[tid] = o;
}

// ------------------------------ TF32 MMA GEMM core ----------------------------
template<int BM, int BN, int WM, int WN, bool TRANS_B, bool CVT_OUT>
__device__ __forceinline__
void gemm_core(const float* __restrict__ A, const float* __restrict__ Bm,
               float* __restrict__ C, float* __restrict__ C2,
               const float* __restrict__ bias1, const float* __restrict__ bias2,
               const float* __restrict__ Res,
               int M, int N, int K, int lda, int ldb, int ldc,
               float alpha, bool perm, int m0, int n0)
{
    constexpr int BK = 16;
    constexpr int MT = WM / 16;
    constexpr int NT = WN / 8;
    constexpr int WCOLS = BN / WN;
    static_assert((BM / WM) * (BN / WN) == 8, "8 warps required");

    __shared__ float As[3][BM][BK + 4];
    __shared__ float Bs[3][TRANS_B ? BN : BK][TRANS_B ? (BK + 4) : (BN + 8)];

    int tid  = threadIdx.x;
    int warp = tid >> 5, lane = tid & 31;
    int wm0 = (warp / WCOLS) * WM;
    int wn0 = (warp % WCOLS) * WN;

    auto ldg_async = [&](int k0, int buf) {
        #pragma unroll
        for (int it = 0; it < (BM * BK) / (4 * 256); it++) {
            int s = tid + it * 256;
            int row = s >> 2, kq = s & 3;
            int gm = m0 + row;
            cp16(&As[buf][row][kq * 4], A + (long)gm * lda + k0 + kq * 4, gm < M);
        }
        if (TRANS_B) {
            #pragma unroll
            for (int it = 0; it < (BN * BK) / (4 * 256); it++) {
                int s = tid + it * 256;
                int n = s >> 2, kq = s & 3;
                int gn = n0 + n;
                cp16(&Bs[buf][n][kq * 4], Bm + (long)gn * ldb + k0 + kq * 4, gn < N);
            }
        } else {
            #pragma unroll
            for (int it = 0; it < (BK * BN) / (4 * 256); it++) {
                int s = tid + it * 256;
                int kk = s / (BN / 4), nq = s % (BN / 4);
                cp16(&Bs[buf][kk][nq * 4],
                     Bm + (long)(k0 + kk) * ldb + n0 + nq * 4, true);
            }
        }
        CP_COMMIT();
    };

    float acc[MT][NT][4];
    #pragma unroll
    for (int i = 0; i < MT; i++)
        #pragma unroll
        for (int j = 0; j < NT; j++)
            #pragma unroll
            for (int e = 0; e < 4; e++) acc[i][j][e] = 0.f;

    const int nIter = K / BK;
    ldg_async(0, 0);
    if (nIter > 1) ldg_async(BK, 1);
    if (nIter > 1) { CP_WAIT1(); } else { CP_WAIT0(); }
    __syncthreads();

    for (int itk = 0; itk < nIter; itk++) {
        int buf = itk % 3;
        if (itk + 2 < nIter) ldg_async((itk + 2) * BK, (itk + 2) % 3);

        #pragma unroll
        for (int ks = 0; ks < 2; ks++) {
            const int kc = ks * 8 + (lane & 3);
            uint32_t af[MT][4];
            uint32_t bf[NT][2];
            #pragma unroll
            for (int mt = 0; mt < MT; mt++) {
                int mrow = wm0 + mt * 16 + (lane >> 2);
                af[mt][0] = ldu(&As[buf][mrow    ][kc    ]);
                af[mt][1] = ldu(&As[buf][mrow + 8][kc    ]);
                af[mt][2] = ldu(&As[buf][mrow    ][kc + 4]);
                af[mt][3] = ldu(&As[buf][mrow + 8][kc + 4]);
            }
            #pragma unroll
            for (int nt = 0; nt < NT; nt++) {
                int ncol = wn0 + nt * 8 + (lane >> 2);
                if (TRANS_B) {
                    bf[nt][0] = ldu(&Bs[buf][ncol][kc    ]);
                    bf[nt][1] = ldu(&Bs[buf][ncol][kc + 4]);
                } else {
                    bf[nt][0] = ldu(&Bs[buf][kc    ][ncol]);
                    bf[nt][1] = ldu(&Bs[buf][kc + 4][ncol]);
                }
            }
            #pragma unroll
            for (int mt = 0; mt < MT; mt++)
                #pragma unroll
                for (int nt = 0; nt < NT; nt++)
                    mma_tf32(acc[mt][nt], af[mt], bf[nt]);
        }

        if (itk + 1 < nIter) {
            if (itk + 2 < nIter) { CP_WAIT1(); } else { CP_WAIT0(); }
        }
        __syncthreads();
    }

    auto emit = [&](int gm, int gn, float v) {
        if (gm < M && gn < N) {
            float val = v * alpha;
            if (Res) val += Res[(long)gm * ldc + gn];
            int gns = perm ? ((gn & ~7) | pos8(gn & 7)) : gn;
            if (C2) {
                float v1 = val + bias1[gn];
                float v2 = val + bias2[gn];
                if (CVT_OUT) { v1 = tfr(v1); v2 = tfr(v2); }
                C [(long)gm * ldc + gns] = v1;
                C2[(long)gm * ldc + gns] = v2;
            } else {
                float v1 = val + (bias1 ? bias1[gn] : 0.f);
                if (CVT_OUT) v1 = tfr(v1);
                C[(long)gm * ldc + gns] = v1;
            }
        }
    };
    #pragma unroll
    for (int mt = 0; mt < MT; mt++) {
        #pragma unroll
        for (int nt = 0; nt < NT; nt++) {
            int gm = m0 + wm0 + mt * 16 + (lane >> 2);
            int gn = n0 + wn0 + nt * 8 + 2 * (lane & 3);
            emit(gm,     gn,     acc[mt][nt][0]);
            emit(gm,     gn + 1, acc[mt][nt][1]);
            emit(gm + 8, gn,     acc[mt][nt][2]);
            emit(gm + 8, gn + 1, acc[mt][nt][3]);
        }
    }
}

// generic wrapper (FC)
template<int BM, int BN, int WM, int WN, bool TRANS_B, bool CVT_OUT>
__global__ __launch_bounds__(256)
void mma_gemm(const float* __restrict__ A, const float* __restrict__ Bm,
              float* __restrict__ C,
              const float* __restrict__ Res,
              int M, int N, int K, float alpha, int perm)
{
    gemm_core<BM,BN,WM,WN,TRANS_B,CVT_OUT>(
        A, Bm, C, nullptr, nullptr, nullptr, Res,
        M, N, K, K, K, N, alpha, perm != 0,
        blockIdx.y * BM, blockIdx.x * BN);
}

// merged Q/K/V/pos projection: grid.z in {0,1,2,3}
__global__ __launch_bounds__(256)
void qkvp_gemm(const float* __restrict__ qn, const float* __restrict__ kn,
               const float* __restrict__ vn, const float* __restrict__ prb,
               const float* __restrict__ wbuf,
               float* __restrict__ qu, float* __restrict__ kh,
               float* __restrict__ vh, float* __restrict__ qvb,
               float* __restrict__ pb,
               const float* __restrict__ pbu, const float* __restrict__ pbv)
{
    int zz = blockIdx.z;
    if (zz == 3) {                           // pos projection: only 16 y-tiles
        if (blockIdx.y >= 16) return;
        gemm_core<128,128,64,32,true,true>(
            prb, wbuf + 3L * D_ * D_, pb, nullptr, nullptr, nullptr, nullptr,
            P_, D_, D_, D_, D_, D_, 1.f, true,
            blockIdx.y * 128, blockIdx.x * 128);
        return;
    }
    const float* A  = (zz == 0) ? qn : (zz == 1) ? kn : vn;
    const float* Bm = wbuf + (long)zz * D_ * D_;
    float* C  = (zz == 0) ? qu : (zz == 1) ? kh : vh;
    float* C2 = (zz == 0) ? qvb : nullptr;
    const float* b1 = (zz == 0) ? pbu : nullptr;
    const float* b2 = (zz == 0) ? pbv : nullptr;
    bool perm = (zz < 2);
    gemm_core<128,128,64,32,true,true>(
        A, Bm, C, C2, b1, b2, nullptr,
        NROW_, D_, D_, D_, D_, D_, 1.f, perm,
        blockIdx.y * 128, blockIdx.x * 128);
}

// ===================== FUSED ATTENTION ======================================
#define S_STRIDE 1028
#define K_STRIDE 72
#define V_STRIDE 72
#define SMEM_FLOATS (32*S_STRIDE + 2*128*V_STRIDE + 2*32*K_STRIDE)

__global__ __launch_bounds__(512)
void fused_attn(const float* __restrict__ qu, const float* __restrict__ qv,
                const float* __restrict__ kh, const float* __restrict__ vh,
                const float* __restrict__ pbuf, const int* __restrict__ mask,
                float* __restrict__ attn, float* __restrict__ ctx)
{
    extern __shared__ float sm[];
    float* S   = sm;                          // [32][1028], natural
    float* KV0 = sm + 32 * S_STRIDE;          // [128][72]
    float* KV1 = KV0 + 128 * V_STRIDE;
    float* Qu  = KV1 + 128 * V_STRIDE;        // [32][72]
    float* Qv  = Qu + 32 * K_STRIDE;

    const int i0 = blockIdx.x * 32;
    const int z  = blockIdx.y;                // b*H + h
    const int b  = z >> 3, h = z & 7;
    const int tid = threadIdx.x;
    const int w = tid >> 5, lane = tid & 31;
    const float scale = 0.125f;
    const float NEG = __int_as_float(0xff7fffff);

    {
        int r = tid >> 4, kq = tid & 15;
        long base = ((long)(b * T_ + i0 + r) * D_ + h * DK_ + kq * 4);
        cp16(&Qu[r * K_STRIDE + kq * 4], qu + base, true);
        cp16(&Qv[r * K_STRIDE + kq * 4], qv + base, true);
    }
    CP_COMMIT();

    auto load_k = [&](int jt, float* buf) {
        #pragma unroll
        for (int it = 0; it < 4; it++) {
            int s = tid + it * 512;
            int n = s >> 4, kq = s & 15;
            cp16(&buf[n * K_STRIDE + kq * 4],
                 kh + ((long)(b * T_ + jt * 128 + n) * D_ + h * DK_ + kq * 4), true);
        }
        CP_COMMIT();
    };
    auto load_v = [&](int jt, float* buf) {
        #pragma unroll
        for (int it = 0; it < 4; it++) {
            int s = tid + it * 512;
            int n = s >> 4, kq = s & 15;
            cp16(&buf[n * V_STRIDE + kq * 4],
                 vh + ((long)(b * T_ + jt * 128 + n) * D_ + h * DK_ + kq * 4), true);
        }
        CP_COMMIT();
    };
    auto load_p = [&](int pt0, float* buf) {
        #pragma unroll
        for (int it = 0; it < 4; it++) {
            int s = tid + it * 512;
            int n = s >> 4, kq = s & 15;
            int p = pt0 + n;
            cp16(&buf[n * K_STRIDE + kq * 4],
                 pbuf + ((long)p * D_ + h * DK_ + kq * 4), p <= P_ - 1);
        }
        CP_COMMIT();
    };

    const int mh = w & 1, ne = w >> 1;
    const int r0 = mh * 16 + (lane >> 2);
    const int l  = lane & 3;

    // ---------------- Phase 1: ac = scale * Qu @ K^T ----------------
    load_k(0, KV0);
    CP_WAIT0();
    __syncthreads();

    {
        uint32_t au[8][4];
        #pragma unroll
        for (int kk = 0; kk < 8; kk++) {
            int kp = kk * 8 + 2 * l;
            float2 p0 = *(const float2*)&Qu[r0 * K_STRIDE + kp];
            float2 p1 = *(const float2*)&Qu[(r0 + 8) * K_STRIDE + kp];
            au[kk][0] = __float_as_uint(p0.x);
            au[kk][1] = __float_as_uint(p1.x);
            au[kk][2] = __float_as_uint(p0.y);
            au[kk][3] = __float_as_uint(p1.y);
        }

        for (int jt = 0; jt < 8; jt++) {
            float* cur = (jt & 1) ? KV1 : KV0;
            float* nxt = (jt & 1) ? KV0 : KV1;
            if (jt + 1 < 8) load_k(jt + 1, nxt);

            float acc[2][4] = {{0.f,0.f,0.f,0.f},{0.f,0.f,0.f,0.f}};
            #pragma unroll
            for (int kk = 0; kk < 8; kk++) {
                int kp = kk * 8 + 2 * l;
                #pragma unroll
                for (int nt = 0; nt < 2; nt++) {
                    int ncol = ne * 16 + nt * 8 + (lane >> 2);
                    float2 bp = *(const float2*)&cur[ncol * K_STRIDE + kp];
                    uint32_t bf[2] = { __float_as_uint(bp.x), __float_as_uint(bp.y) };
                    mma_tf32(acc[nt], au[kk], bf);
                }
            }
            #pragma unroll
            for (int nt = 0; nt < 2; nt++) {
                int c0 = jt * 128 + ne * 16 + nt * 8 + 2 * l;
                *(float2*)&S[r0 * S_STRIDE + c0] =
                    make_float2(acc[nt][0] * scale, acc[nt][1] * scale);
                *(float2*)&S[(r0 + 8) * S_STRIDE + c0] =
                    make_float2(acc[nt][2] * scale, acc[nt][3] * scale);
            }
            if (jt + 1 < 8) CP_WAIT0();
            __syncthreads();
        }
    }

    // ------------- Phase 2: bd scatter-add over p-window -------------
    const int pbase = (T_ - 1) - (i0 + 31);
    load_p(pbase, KV0);
    {
        uint32_t av[8][4];
        #pragma unroll
        for (int kk = 0; kk < 8; kk++) {
            int kp = kk * 8 + 2 * l;
            float2 p0 = *(const float2*)&Qv[r0 * K_STRIDE + kp];
            float2 p1 = *(const float2*)&Qv[(r0 + 8) * K_STRIDE + kp];
            av[kk][0] = __float_as_uint(p0.x);
            av[kk][1] = __float_as_uint(p1.x);
            av[kk][2] = __float_as_uint(p0.y);
            av[kk][3] = __float_as_uint(p1.y);
        }
        CP_WAIT0();
        __syncthreads();

        for (int pt = 0; pt < 9; pt++) {
            float* cur = (pt & 1) ? KV1 : KV0;
            float* nxt = (pt & 1) ? KV0 : KV1;
            if (pt + 1 < 9) load_p(pbase + (pt + 1) * 128, nxt);

            float acc[2][4] = {{0.f,0.f,0.f,0.f},{0.f,0.f,0.f,0.f}};
            #pragma unroll
            for (int kk = 0; kk < 8; kk++) {
                int kp = kk * 8 + 2 * l;
                #pragma unroll
                for (int nt = 0; nt < 2; nt++) {
                    int ncol = ne * 16 + nt * 8 + (lane >> 2);
                    float2 bp = *(const float2*)&cur[ncol * K_STRIDE + kp];
                    uint32_t bf[2] = { __float_as_uint(bp.x), __float_as_uint(bp.y) };
                    mma_tf32(acc[nt], av[kk], bf);
                }
            }
            const int pt0 = pbase + pt * 128;
            #pragma unroll
            for (int nt = 0; nt < 2; nt++) {
                int c0 = ne * 16 + nt * 8 + 2 * l;
                #pragma unroll
                for (int e = 0; e < 4; e++) {
                    int r = r0 + (e >> 1) * 8;
                    int p = pt0 + c0 + (e & 1);
                    int j = p - (T_ - 1) + i0 + r;
                    if ((unsigned)j < (unsigned)T_)
                        S[r * S_STRIDE + j] += acc[nt][e] * scale;
                }
            }
            if (pt + 1 < 9) CP_WAIT0();
            __syncthreads();
        }
    }

    // -------- prefetch V tile 0 (overlaps softmax) --------
    load_v(0, KV0);

    // ------ Phase 3: softmax; attn gets fp32, S gets tf32-rounded ------
    #pragma unroll
    for (int t = 0; t < 2; t++) {
        int r = w + 16 * t;
        int i = i0 + r;
        const int4*   mrow = (const int4*)(mask + ((long)b * T_ + i) * T_);
        float4*       srow = (float4*)(S + r * S_STRIDE);
        float4*       arow = (float4*)(attn + ((long)z * T_ + i) * T_);

        float4 vals[8];
        float lmax = NEG;
        #pragma unroll
        for (int e = 0; e < 8; e++) {
            int idx = e * 32 + lane;
            float4 v = srow[idx];
            int4   m = mrow[idx];
            v.x = (m.x == 0) ? NEG : v.x;
            v.y = (m.y == 0) ? NEG : v.y;
            v.z = (m.z == 0) ? NEG : v.z;
            v.w = (m.w == 0) ? NEG : v.w;
            vals[e] = v;
            lmax = fmaxf(lmax, fmaxf(fmaxf(v.x, v.y), fmaxf(v.z, v.w)));
        }
        #pragma unroll
        for (int o = 16; o > 0; o >>= 1)
            lmax = fmaxf(lmax, __shfl_xor_sync(0xffffffffu, lmax, o));

        if (lmax == NEG) {
            float4 zero = make_float4(0.f, 0.f, 0.f, 0.f);
            #pragma unroll
            for (int e = 0; e < 8; e++) {
                int idx = e * 32 + lane;
                srow[idx] = zero;
                arow[idx] = zero;
            }
            continue;
        }
        float sum = 0.f;
        #pragma unroll
        for (int e = 0; e < 8; e++) {
            float4 v = vals[e];
            v.x = __expf(v.x - lmax); v.y = __expf(v.y - lmax);
            v.z = __expf(v.z - lmax); v.w = __expf(v.w - lmax);
            vals[e] = v;
            sum += (v.x + v.y) + (v.z + v.w);
        }
        #pragma unroll
        for (int o = 16; o > 0; o >>= 1)
            sum += __shfl_xor_sync(0xffffffffu, sum, o);
        float inv = 1.0f / sum;
        #pragma unroll
        for (int e = 0; e < 8; e++) {
            int idx = e * 32 + lane;
            float4 v = vals[e];
            v.x *= inv; v.y *= inv; v.z *= inv; v.w *= inv;
            arow[idx] = v;
            float4 vt;
            vt.x = tfr(v.x); vt.y = tfr(v.y);
            vt.z = tfr(v.z); vt.w = tfr(v.w);
            srow[idx] = vt;
        }
    }
    CP_WAIT0();
    __syncthreads();

    // ---------------- Phase 4: O = S @ V -> ctx (tf32-rounded) ---------------
    const int mt = w >> 3, nt4 = w & 7;
    float oacc[4] = {0.f, 0.f, 0.f, 0.f};
    const int r4 = mt * 16 + (lane >> 2);
    const int vn = nt4 * 8 + (lane >> 2);

    for (int jt = 0; jt < 8; jt++) {
        float* cur = (jt & 1) ? KV1 : KV0;
        float* nxt = (jt & 1) ? KV0 : KV1;
        if (jt + 1 < 8) load_v(jt + 1, nxt);

        #pragma unroll
        for (int kk = 0; kk < 16; kk++) {
            int kc = kk * 8 + l;
            uint32_t af[4] = { ldu(&S[r4 * S_STRIDE + jt * 128 + kc]),
                               ldu(&S[(r4 + 8) * S_STRIDE + jt * 128 + kc]),
                               ldu(&S[r4 * S_STRIDE + jt * 128 + kc + 4]),
                               ldu(&S[(r4 + 8) * S_STRIDE + jt * 128 + kc + 4]) };
            uint32_t bf[2] = { ldu(&cur[kc * V_STRIDE + vn]),
                               ldu(&cur[(kc + 4) * V_STRIDE + vn]) };
            mma_tf32(oacc, af, bf);
        }
        if (jt + 1 < 8) CP_WAIT0();
        __syncthreads();
    }

    const int n0 = nt4 * 8 + 2 * l;
    long o0 = (long)(b * T_ + i0 + r4) * D_ + h * DK_ + n0;
    long o1 = (long)(b * T_ + i0 + r4 + 8) * D_ + h * DK_ + n0;
    *(float2*)&ctx[o0] = make_float2(tfr(oacc[0]), tfr(oacc[1]));
    *(float2*)&ctx[o1] = make_float2(tfr(oacc[2]), tfr(oacc[3]));
}

// ------------------------------ launch ---------------------------------------
extern "C" void kernel_launch(void* const* d_in, const int* in_sizes, int n_in,
                              void* d_out, int out_size)
{
    const float* q    = (const float*)d_in[0];
    const float* k    = (const float*)d_in[1];
    const float* v    = (const float*)d_in[2];
    const float* pos  = (const float*)d_in[3];
    const int*   mask = (const int*)  d_in[4];
    const float* lnqg = (const float*)d_in[5],  *lnqb = (const float*)d_in[6];
    const float* lnkg = (const float*)d_in[7],  *lnkb = (const float*)d_in[8];
    const float* lnvg = (const float*)d_in[9],  *lnvb = (const float*)d_in[10];
    const float* wq   = (const float*)d_in[11], *wk   = (const float*)d_in[12];
    const float* wv   = (const float*)d_in[13], *wpos = (const float*)d_in[14];
    const float* wfc  = (const float*)d_in[15];
    const float* pbu  = (const float*)d_in[16], *pbv  = (const float*)d_in[17];

    float* out  = (float*)d_out;                 // [B,T,D]
    float* attn = out + (size_t)ND_;             // [B,H,T,T]

    float *qn,*kn,*vn,*qu,*qvb,*kh,*vh,*pb,*ctx,*wbuf,*prb;
    cudaGetSymbolAddress((void**)&qn,  g_qn);
    cudaGetSymbolAddress((void**)&kn,  g_kn);
    cudaGetSymbolAddress((void**)&vn,  g_vn);
    cudaGetSymbolAddress((void**)&qu,  g_qu);
    cudaGetSymbolAddress((void**)&qvb, g_qv);
    cudaGetSymbolAddress((void**)&kh,  g_kh);
    cudaGetSymbolAddress((void**)&vh,  g_vh);
    cudaGetSymbolAddress((void**)&pb,  g_p);
    cudaGetSymbolAddress((void**)&ctx, g_ctx);
    cudaGetSymbolAddress((void**)&wbuf, g_w);
    cudaGetSymbolAddress((void**)&prb, g_pr);

    static const size_t fused_smem = SMEM_FLOATS * sizeof(float);
    cudaFuncSetAttribute(fused_attn,
                         cudaFuncAttributeMaxDynamicSharedMemorySize,
                         (int)fused_smem);

    // single-launch tf32 pre-round of 5 weights + pos input
    {
        int pn4 = (P_ * D_) / 4;                 // 262016 -> 1024 x-blocks
        round_all<<<dim3((pn4 + 255) / 256, 6), 256>>>(
            wq, wk, wv, wpos, wfc, pos, wbuf, prb);
    }

    // merged LayerNorms (tf32-rounded outputs)
    ln3_kernel<<<dim3(NROW_, 3), 256>>>(q, k, v,
        lnqg, lnqb, lnkg, lnkb, lnvg, lnvb, qn, kn, vn);

    // merged Q/K/V/pos projections (grid.z = 4)
    qkvp_gemm<<<dim3(4,64,4),256>>>(qn, kn, vn, prb, wbuf,
        qu, kh, vh, qvb, pb, pbu, pbv);

    // fused attention
    fused_attn<<<dim3(32, 64), 512, fused_smem>>>(
        qu, qvb, kh, vh, pb, mask, attn, ctx);

    // out = ctx @ Wfc^T + residual(q)  (fp32 output)
    mma_gemm<128,128,64,32,true,false><<<dim3(4,64,1),256>>>(
        ctx, wbuf + 4L * D_ * D_, out, q,
        NROW_, D_, D_, 1.f, 0);
}

// round 13
// speedup vs baseline: 1.4090x; 1.0072x over previous
#include <cuda_runtime.h>
#include <cuda_bf16.h>
#include <math.h>
#include <stdint.h>

// Problem constants
#define B_  8
#define T_  1024
#define D_  512
#define H_  8
#define DK_ 64
#define P_  2047          // 2*T-1
#define NROW_ (B_*T_)     // 8192
#define ND_  (NROW_*D_)   // 4194304

// -------------------- device scratch (no allocs allowed) --------------------
__device__ float g_qn [ND_];
__device__ float g_kn [ND_];
__device__ float g_vn [ND_];
__device__ float g_qu [ND_];   // qh + pos_bias_u (tf32, dk pair-permuted)
__device__ float g_qv [ND_];   // qh + pos_bias_v (tf32, dk pair-permuted)
__device__ float g_kh [ND_];   // tf32, dk pair-permuted
__device__ float g_vh [ND_];   // tf32, natural
__device__ float g_p  [(P_+1)*D_]; // tf32, dk pair-permuted (row 2047 = pad)
__device__ float g_ctx[ND_];   // attn @ V (tf32-rounded at producer)
__device__ float g_w  [5][D_*D_];  // tf32-rounded weights: wq,wk,wv,wpos,wfc
__device__ float g_pr [P_*D_];     // tf32-rounded pos input

__device__ __forceinline__ int pos8(int x) { return ((x & 3) << 1) | ((x >> 2) & 1); }

// ------------------------- TF32 helpers --------------------------------------
__device__ __forceinline__ uint32_t f2tf(float f) {
    uint32_t u;
    asm("cvt.rna.tf32.f32 %0, %1;" : "=r"(u) : "f"(f));
    return u;
}
__device__ __forceinline__ float tfr(float f) { return __uint_as_float(f2tf(f)); }

__device__ __forceinline__ void mma_tf32(float c[4], const uint32_t a[4],
                                         const uint32_t b[2]) {
    asm volatile(
        "mma.sync.aligned.m16n8k8.row.col.f32.tf32.tf32.f32 "
        "{%0,%1,%2,%3},{%4,%5,%6,%7},{%8,%9},{%0,%1,%2,%3};\n"
        : "+f"(c[0]), "+f"(c[1]), "+f"(c[2]), "+f"(c[3])
        : "r"(a[0]), "r"(a[1]), "r"(a[2]), "r"(a[3]), "r"(b[0]), "r"(b[1]));
}

__device__ __forceinline__ void cp16(float* dst_smem, const float* src, bool valid) {
    uint32_t d = (uint32_t)__cvta_generic_to_shared(dst_smem);
    int sz = valid ? 16 : 0;
    asm volatile("cp.async.cg.shared.global [%0], [%1], 16, %2;\n"
                 :: "r"(d), "l"(src), "r"(sz));
}
#define CP_COMMIT() asm volatile("cp.async.commit_group;\n" ::: "memory")
#define CP_WAIT0()  asm volatile("cp.async.wait_group 0;\n" ::: "memory")
#define CP_WAIT1()  asm volatile("cp.async.wait_group 1;\n" ::: "memory")

__device__ __forceinline__ uint32_t ldu(const float* p) {
    return __float_as_uint(*p);
}

// ----------------------- tf32 pre-round pass (single launch) ------------------
__global__ __launch_bounds__(256)
void round_all(const float* __restrict__ wq, const float* __restrict__ wk,
               const float* __restrict__ wv, const float* __restrict__ wpos,
               const float* __restrict__ wfc, const float* __restrict__ pos,
               float* __restrict__ wbuf, float* __restrict__ prb)
{
    int slice = blockIdx.y;
    const float* src;
    float* dst;
    int n4;
    if (slice < 5) {
        src = (slice == 0) ? wq : (slice == 1) ? wk : (slice == 2) ? wv
            : (slice == 3) ? wpos : wfc;
        dst = wbuf + (long)slice * D_ * D_;
        n4 = (D_ * D_) / 4;
    } else {
        src = pos;
        dst = prb;
        n4 = (P_ * D_) / 4;
    }
    int i = blockIdx.x * 256 + threadIdx.x;
    if (i < n4) {
        float4 v = ((const float4*)src)[i];
        v.x = tfr(v.x); v.y = tfr(v.y); v.z = tfr(v.z); v.w = tfr(v.w);
        ((float4*)dst)[i] = v;
    }
}

// ------------------------- merged LayerNorm (3 slices) ------------------------
__global__ __launch_bounds__(256)
void ln3_kernel(const float* __restrict__ q, const float* __restrict__ k,
                const float* __restrict__ v,
                const float* __restrict__ gq, const float* __restrict__ bq,
                const float* __restrict__ gk, const float* __restrict__ bk,
                const float* __restrict__ gv, const float* __restrict__ bv,
                float* __restrict__ yq, float* __restrict__ yk,
                float* __restrict__ yv)
{
    int slice = blockIdx.y;
    const float* x  = (slice == 0) ? q  : (slice == 1) ? k  : v;
    const float* g  = (slice == 0) ? gq : (slice == 1) ? gk : gv;
    const float* bb = (slice == 0) ? bq : (slice == 1) ? bk : bv;
    float*       y  = (slice == 0) ? yq : (slice == 1) ? yk : yv;

    long row = blockIdx.x;
    const float2* xr = (const float2*)(x + row * D_);
    float2*       yr = (float2*)(y + row * D_);
    int tid = threadIdx.x;
    float2 vv = xr[tid];
    float s  = vv.x + vv.y;
    float sq = vv.x * vv.x + vv.y * vv.y;

    __shared__ float rs[8], rq[8];
    #pragma unroll
    for (int o = 16; o > 0; o >>= 1) {
        s  += __shfl_xor_sync(0xffffffffu, s,  o);
        sq += __shfl_xor_sync(0xffffffffu, sq, o);
    }
    int wid = tid >> 5;
    if ((tid & 31) == 0) { rs[wid] = s; rq[wid] = sq; }
    __syncthreads();
    if (tid == 0) {
        float a = 0.f, b2 = 0.f;
        #pragma unroll
        for (int w = 0; w < 8; w++) { a += rs[w]; b2 += rq[w]; }
        rs[0] = a; rq[0] = b2;
    }
    __syncthreads();
    float mean = rs[0] * (1.0f / D_);
    float var  = rq[0] * (1.0f / D_) - mean * mean;
    float rstd = rsqrtf(var + 1e-5f);
    const float2* gv2 = (const float2*)g;
    const float2* bv2 = (const float2*)bb;
    float2 gg = gv2[tid], bbv = bv2[tid];
    float2 o;
    o.x = tfr((vv.x - mean) * rstd * gg.x + bbv.x);
    o.y = tfr((vv.y - mean) * rstd * gg.y + bbv.y);
    yr[tid] = o;
}

// ------------------------------ TF32 MMA GEMM core ----------------------------
template<int BM, int BN, int WM, int WN, bool TRANS_B, bool CVT_OUT>
__device__ __forceinline__
void gemm_core(const float* __restrict__ A, const float* __restrict__ Bm,
               float* __restrict__ C, float* __restrict__ C2,
               const float* __restrict__ bias1, const float* __restrict__ bias2,
               const float* __restrict__ Res,
               int M, int N, int K, int lda, int ldb, int ldc,
               float alpha, bool perm, int m0, int n0)
{
    constexpr int BK = 16;
    constexpr int MT = WM / 16;
    constexpr int NT = WN / 8;
    constexpr int WCOLS = BN / WN;
    static_assert((BM / WM) * (BN / WN) == 8, "8 warps required");

    __shared__ float As[3][BM][BK + 4];
    __shared__ float Bs[3][TRANS_B ? BN : BK][TRANS_B ? (BK + 4) : (BN + 8)];

    int tid  = threadIdx.x;
    int warp = tid >> 5, lane = tid & 31;
    int wm0 = (warp / WCOLS) * WM;
    int wn0 = (warp % WCOLS) * WN;

    auto ldg_async = [&](int k0, int buf) {
        #pragma unroll
        for (int it = 0; it < (BM * BK) / (4 * 256); it++) {
            int s = tid + it * 256;
            int row = s >> 2, kq = s & 3;
            int gm = m0 + row;
            cp16(&As[buf][row][kq * 4], A + (long)gm * lda + k0 + kq * 4, gm < M);
        }
        if (TRANS_B) {
            #pragma unroll
            for (int it = 0; it < (BN * BK) / (4 * 256); it++) {
                int s = tid + it * 256;
                int n = s >> 2, kq = s & 3;
                int gn = n0 + n;
                cp16(&Bs[buf][n][kq * 4], Bm + (long)gn * ldb + k0 + kq * 4, gn < N);
            }
        } else {
            #pragma unroll
            for (int it = 0; it < (BK * BN) / (4 * 256); it++) {
                int s = tid + it * 256;
                int kk = s / (BN / 4), nq = s % (BN / 4);
                cp16(&Bs[buf][kk][nq * 4],
                     Bm + (long)(k0 + kk) * ldb + n0 + nq * 4, true);
            }
        }
        CP_COMMIT();
    };

    float acc[MT][NT][4];
    #pragma unroll
    for (int i = 0; i < MT; i++)
        #pragma unroll
        for (int j = 0; j < NT; j++)
            #pragma unroll
            for (int e = 0; e < 4; e++) acc[i][j][e] = 0.f;

    const int nIter = K / BK;
    ldg_async(0, 0);
    if (nIter > 1) ldg_async(BK, 1);
    if (nIter > 1) { CP_WAIT1(); } else { CP_WAIT0(); }
    __syncthreads();

    for (int itk = 0; itk < nIter; itk++) {
        int buf = itk % 3;
        if (itk + 2 < nIter) ldg_async((itk + 2) * BK, (itk + 2) % 3);

        #pragma unroll
        for (int ks = 0; ks < 2; ks++) {
            const int kc = ks * 8 + (lane & 3);
            uint32_t af[MT][4];
            uint32_t bf[NT][2];
            #pragma unroll
            for (int mt = 0; mt < MT; mt++) {
                int mrow = wm0 + mt * 16 + (lane >> 2);
                af[mt][0] = ldu(&As[buf][mrow    ][kc    ]);
                af[mt][1] = ldu(&As[buf][mrow + 8][kc    ]);
                af[mt][2] = ldu(&As[buf][mrow    ][kc + 4]);
                af[mt][3] = ldu(&As[buf][mrow + 8][kc + 4]);
            }
            #pragma unroll
            for (int nt = 0; nt < NT; nt++) {
                int ncol = wn0 + nt * 8 + (lane >> 2);
                if (TRANS_B) {
                    bf[nt][0] = ldu(&Bs[buf][ncol][kc    ]);
                    bf[nt][1] = ldu(&Bs[buf][ncol][kc + 4]);
                } else {
                    bf[nt][0] = ldu(&Bs[buf][kc    ][ncol]);
                    bf[nt][1] = ldu(&Bs[buf][kc + 4][ncol]);
                }
            }
            #pragma unroll
            for (int mt = 0; mt < MT; mt++)
                #pragma unroll
                for (int nt = 0; nt < NT; nt++)
                    mma_tf32(acc[mt][nt], af[mt], bf[nt]);
        }

        if (itk + 1 < nIter) {
            if (itk + 2 < nIter) { CP_WAIT1(); } else { CP_WAIT0(); }
        }
        __syncthreads();
    }

    auto emit = [&](int gm, int gn, float v) {
        if (gm < M && gn < N) {
            float val = v * alpha;
            if (Res) val += Res[(long)gm * ldc + gn];
            int gns = perm ? ((gn & ~7) | pos8(gn & 7)) : gn;
            if (C2) {
                float v1 = val + bias1[gn];
                float v2 = val + bias2[gn];
                if (CVT_OUT) { v1 = tfr(v1); v2 = tfr(v2); }
                C [(long)gm * ldc + gns] = v1;
                C2[(long)gm * ldc + gns] = v2;
            } else {
                float v1 = val + (bias1 ? bias1[gn] : 0.f);
                if (CVT_OUT) v1 = tfr(v1);
                C[(long)gm * ldc + gns] = v1;
            }
        }
    };
    #pragma unroll
    for (int mt = 0; mt < MT; mt++) {
        #pragma unroll
        for (int nt = 0; nt < NT; nt++) {
            int gm = m0 + wm0 + mt * 16 + (lane >> 2);
            int gn = n0 + wn0 + nt * 8 + 2 * (lane & 3);
            emit(gm,     gn,     acc[mt][nt][0]);
            emit(gm,     gn + 1, acc[mt][nt][1]);
            emit(gm + 8, gn,     acc[mt][nt][2]);
            emit(gm + 8, gn + 1, acc[mt][nt][3]);
        }
    }
}

// generic wrapper (FC)
template<int BM, int BN, int WM, int WN, bool TRANS_B, bool CVT_OUT>
__global__ __launch_bounds__(256)
void mma_gemm(const float* __restrict__ A, const float* __restrict__ Bm,
              float* __restrict__ C,
              const float* __restrict__ Res,
              int M, int N, int K, float alpha, int perm)
{
    gemm_core<BM,BN,WM,WN,TRANS_B,CVT_OUT>(
        A, Bm, C, nullptr, nullptr, nullptr, Res,
        M, N, K, K, K, N, alpha, perm != 0,
        blockIdx.y * BM, blockIdx.x * BN);
}

// merged Q/K/V/pos projection: grid.z in {0,1,2,3}
__global__ __launch_bounds__(256)
void qkvp_gemm(const float* __restrict__ qn, const float* __restrict__ kn,
               const float* __restrict__ vn, const float* __restrict__ prb,
               const float* __restrict__ wbuf,
               float* __restrict__ qu, float* __restrict__ kh,
               float* __restrict__ vh, float* __restrict__ qvb,
               float* __restrict__ pb,
               const float* __restrict__ pbu, const float* __restrict__ pbv)
{
    int zz = blockIdx.z;
    if (zz == 3) {
        if (blockIdx.y >= 16) return;
        gemm_core<128,128,64,32,true,true>(
            prb, wbuf + 3L * D_ * D_, pb, nullptr, nullptr, nullptr, nullptr,
            P_, D_, D_, D_, D_, D_, 1.f, true,
            blockIdx.y * 128, blockIdx.x * 128);
        return;
    }
    const float* A  = (zz == 0) ? qn : (zz == 1) ? kn : vn;
    const float* Bm = wbuf + (long)zz * D_ * D_;
    float* C  = (zz == 0) ? qu : (zz == 1) ? kh : vh;
    float* C2 = (zz == 0) ? qvb : nullptr;
    const float* b1 = (zz == 0) ? pbu : nullptr;
    const float* b2 = (zz == 0) ? pbv : nullptr;
    bool perm = (zz < 2);
    gemm_core<128,128,64,32,true,true>(
        A, Bm, C, C2, b1, b2, nullptr,
        NROW_, D_, D_, D_, D_, D_, 1.f, perm,
        blockIdx.y * 128, blockIdx.x * 128);
}

// ===================== FUSED ATTENTION ======================================
#define S_STRIDE 1028
#define K_STRIDE 72
#define V_STRIDE 72
#define P_STRIDE 72                 // partial-sum row stride (phase 4 reduce)
#define PSLICE   (32 * P_STRIDE)    // 2304 floats per k-slice partial
#define SMEM_FLOATS (32*S_STRIDE + 2*128*V_STRIDE + 2*32*K_STRIDE)

__global__ __launch_bounds__(512)
void fused_attn(const float* __restrict__ qu, const float* __restrict__ qv,
                const float* __restrict__ kh, const float* __restrict__ vh,
                const float* __restrict__ pbuf, const int* __restrict__ mask,
                float* __restrict__ attn, float* __restrict__ ctx)
{
    extern __shared__ float sm[];
    float* S   = sm;                          // [32][1028], natural
    float* KV0 = sm + 32 * S_STRIDE;          // [128][72]
    float* KV1 = KV0 + 128 * V_STRIDE;
    float* Qu  = KV1 + 128 * V_STRIDE;        // [32][72]
    float* Qv  = Qu + 32 * K_STRIDE;
    float* part = KV0;                        // phase-4 partials alias KV0/KV1

    const int i0 = blockIdx.x * 32;
    const int z  = blockIdx.y;                // b*H + h
    const int b  = z >> 3, h = z & 7;
    const int tid = threadIdx.x;
    const int w = tid >> 5, lane = tid & 31;
    const float scale = 0.125f;
    const float NEG = __int_as_float(0xff7fffff);

    {
        int r = tid >> 4, kq = tid & 15;
        long base = ((long)(b * T_ + i0 + r) * D_ + h * DK_ + kq * 4);
        cp16(&Qu[r * K_STRIDE + kq * 4], qu + base, true);
        cp16(&Qv[r * K_STRIDE + kq * 4], qv + base, true);
    }
    CP_COMMIT();

    auto load_k = [&](int jt, float* buf) {
        #pragma unroll
        for (int it = 0; it < 4; it++) {
            int s = tid + it * 512;
            int n = s >> 4, kq = s & 15;
            cp16(&buf[n * K_STRIDE + kq * 4],
                 kh + ((long)(b * T_ + jt * 128 + n) * D_ + h * DK_ + kq * 4), true);
        }
        CP_COMMIT();
    };
    auto load_v = [&](int jt, float* buf) {
        #pragma unroll
        for (int it = 0; it < 4; it++) {
            int s = tid + it * 512;
            int n = s >> 4, kq = s & 15;
            cp16(&buf[n * V_STRIDE + kq * 4],
                 vh + ((long)(b * T_ + jt * 128 + n) * D_ + h * DK_ + kq * 4), true);
        }
        CP_COMMIT();
    };
    auto load_p = [&](int pt0, float* buf) {
        #pragma unroll
        for (int it = 0; it < 4; it++) {
            int s = tid + it * 512;
            int n = s >> 4, kq = s & 15;
            int p = pt0 + n;
            cp16(&buf[n * K_STRIDE + kq * 4],
                 pbuf + ((long)p * D_ + h * DK_ + kq * 4), p <= P_ - 1);
        }
        CP_COMMIT();
    };

    const int mh = w & 1, ne = w >> 1;
    const int r0 = mh * 16 + (lane >> 2);
    const int l  = lane & 3;

    // ---------------- Phase 1: ac = scale * Qu @ K^T ----------------
    load_k(0, KV0);
    CP_WAIT0();
    __syncthreads();

    {
        uint32_t au[8][4];
        #pragma unroll
        for (int kk = 0; kk < 8; kk++) {
            int kp = kk * 8 + 2 * l;
            float2 p0 = *(const float2*)&Qu[r0 * K_STRIDE + kp];
            float2 p1 = *(const float2*)&Qu[(r0 + 8) * K_STRIDE + kp];
            au[kk][0] = __float_as_uint(p0.x);
            au[kk][1] = __float_as_uint(p1.x);
            au[kk][2] = __float_as_uint(p0.y);
            au[kk][3] = __float_as_uint(p1.y);
        }

        for (int jt = 0; jt < 8; jt++) {
            float* cur = (jt & 1) ? KV1 : KV0;
            float* nxt = (jt & 1) ? KV0 : KV1;
            if (jt + 1 < 8) load_k(jt + 1, nxt);

            float acc[2][4] = {{0.f,0.f,0.f,0.f},{0.f,0.f,0.f,0.f}};
            #pragma unroll
            for (int kk = 0; kk < 8; kk++) {
                int kp = kk * 8 + 2 * l;
                #pragma unroll
                for (int nt = 0; nt < 2; nt++) {
                    int ncol = ne * 16 + nt * 8 + (lane >> 2);
                    float2 bp = *(const float2*)&cur[ncol * K_STRIDE + kp];
                    uint32_t bf[2] = { __float_as_uint(bp.x), __float_as_uint(bp.y) };
                    mma_tf32(acc[nt], au[kk], bf);
                }
            }
            #pragma unroll
            for (int nt = 0; nt < 2; nt++) {
                int c0 = jt * 128 + ne * 16 + nt * 8 + 2 * l;
                *(float2*)&S[r0 * S_STRIDE + c0] =
                    make_float2(acc[nt][0] * scale, acc[nt][1] * scale);
                *(float2*)&S[(r0 + 8) * S_STRIDE + c0] =
                    make_float2(acc[nt][2] * scale, acc[nt][3] * scale);
            }
            if (jt + 1 < 8) CP_WAIT0();
            __syncthreads();
        }
    }

    // ------------- Phase 2: bd scatter-add over p-window -------------
    const int pbase = (T_ - 1) - (i0 + 31);
    load_p(pbase, KV0);
    {
        uint32_t av[8][4];
        #pragma unroll
        for (int kk = 0; kk < 8; kk++) {
            int kp = kk * 8 + 2 * l;
            float2 p0 = *(const float2*)&Qv[r0 * K_STRIDE + kp];
            float2 p1 = *(const float2*)&Qv[(r0 + 8) * K_STRIDE + kp];
            av[kk][0] = __float_as_uint(p0.x);
            av[kk][1] = __float_as_uint(p1.x);
            av[kk][2] = __float_as_uint(p0.y);
            av[kk][3] = __float_as_uint(p1.y);
        }
        CP_WAIT0();
        __syncthreads();

        for (int pt = 0; pt < 9; pt++) {
            float* cur = (pt & 1) ? KV1 : KV0;
            float* nxt = (pt & 1) ? KV0 : KV1;
            if (pt + 1 < 9) load_p(pbase + (pt + 1) * 128, nxt);

            float acc[2][4] = {{0.f,0.f,0.f,0.f},{0.f,0.f,0.f,0.f}};
            #pragma unroll
            for (int kk = 0; kk < 8; kk++) {
                int kp = kk * 8 + 2 * l;
                #pragma unroll
                for (int nt = 0; nt < 2; nt++) {
                    int ncol = ne * 16 + nt * 8 + (lane >> 2);
                    float2 bp = *(const float2*)&cur[ncol * K_STRIDE + kp];
                    uint32_t bf[2] = { __float_as_uint(bp.x), __float_as_uint(bp.y) };
                    mma_tf32(acc[nt], av[kk], bf);
                }
            }
            const int pt0 = pbase + pt * 128;
            #pragma unroll
            for (int nt = 0; nt < 2; nt++) {
                int c0 = ne * 16 + nt * 8 + 2 * l;
                #pragma unroll
                for (int e = 0; e < 4; e++) {
                    int r = r0 + (e >> 1) * 8;
                    int p = pt0 + c0 + (e & 1);
                    int j = p - (T_ - 1) + i0 + r;
                    if ((unsigned)j < (unsigned)T_)
                        S[r * S_STRIDE + j] += acc[nt][e] * scale;
                }
            }
            if (pt + 1 < 9) CP_WAIT0();
            __syncthreads();
        }
    }

    // -------- prefetch V tile 0 (overlaps softmax) --------
    load_v(0, KV0);

    // ------ Phase 3: softmax; attn gets fp32, S gets tf32-rounded ------
    #pragma unroll
    for (int t = 0; t < 2; t++) {
        int r = w + 16 * t;
        int i = i0 + r;
        const int4*   mrow = (const int4*)(mask + ((long)b * T_ + i) * T_);
        float4*       srow = (float4*)(S + r * S_STRIDE);
        float4*       arow = (float4*)(attn + ((long)z * T_ + i) * T_);

        float4 vals[8];
        float lmax = NEG;
        #pragma unroll
        for (int e = 0; e < 8; e++) {
            int idx = e * 32 + lane;
            float4 v = srow[idx];
            int4   m = mrow[idx];
            v.x = (m.x == 0) ? NEG : v.x;
            v.y = (m.y == 0) ? NEG : v.y;
            v.z = (m.z == 0) ? NEG : v.z;
            v.w = (m.w == 0) ? NEG : v.w;
            vals[e] = v;
            lmax = fmaxf(lmax, fmaxf(fmaxf(v.x, v.y), fmaxf(v.z, v.w)));
        }
        #pragma unroll
        for (int o = 16; o > 0; o >>= 1)
            lmax = fmaxf(lmax, __shfl_xor_sync(0xffffffffu, lmax, o));

        if (lmax == NEG) {
            float4 zero = make_float4(0.f, 0.f, 0.f, 0.f);
            #pragma unroll
            for (int e = 0; e < 8; e++) {
                int idx = e * 32 + lane;
                srow[idx] = zero;
                arow[idx] = zero;
            }
            continue;
        }
        float sum = 0.f;
        #pragma unroll
        for (int e = 0; e < 8; e++) {
            float4 v = vals[e];
            v.x = __expf(v.x - lmax); v.y = __expf(v.y - lmax);
            v.z = __expf(v.z - lmax); v.w = __expf(v.w - lmax);
            vals[e] = v;
            sum += (v.x + v.y) + (v.z + v.w);
        }
        #pragma unroll
        for (int o = 16; o > 0; o >>= 1)
            sum += __shfl_xor_sync(0xffffffffu, sum, o);
        float inv = 1.0f / sum;
        #pragma unroll
        for (int e = 0; e < 8; e++) {
            int idx = e * 32 + lane;
            float4 v = vals[e];
            v.x *= inv; v.y *= inv; v.z *= inv; v.w *= inv;
            arow[idx] = v;
            float4 vt;
            vt.x = tfr(v.x); vt.y = tfr(v.y);
            vt.z = tfr(v.z); vt.w = tfr(v.w);
            srow[idx] = vt;
        }
    }
    CP_WAIT0();
    __syncthreads();

    // ------- Phase 4 (split-K): warp (mt, ks); ks covers kk {2ks, 2ks+1} -----
    {
        const int mt4 = w & 1, ks = w >> 1;
        const int r4 = mt4 * 16 + (lane >> 2);
        float oacc[8][4];
        #pragma unroll
        for (int nt = 0; nt < 8; nt++)
            #pragma unroll
            for (int e = 0; e < 4; e++) oacc[nt][e] = 0.f;

        for (int jt = 0; jt < 8; jt++) {
            float* cur = (jt & 1) ? KV1 : KV0;
            float* nxt = (jt & 1) ? KV0 : KV1;
            if (jt + 1 < 8) load_v(jt + 1, nxt);

            #pragma unroll
            for (int kx = 0; kx < 2; kx++) {
                int kc = (ks * 2 + kx) * 8 + l;         // 0..127 within tile
                uint32_t af[4] = {
                    ldu(&S[r4 * S_STRIDE + jt * 128 + kc]),
                    ldu(&S[(r4 + 8) * S_STRIDE + jt * 128 + kc]),
                    ldu(&S[r4 * S_STRIDE + jt * 128 + kc + 4]),
                    ldu(&S[(r4 + 8) * S_STRIDE + jt * 128 + kc + 4]) };
                #pragma unroll
                for (int nt = 0; nt < 8; nt++) {
                    int vn = nt * 8 + (lane >> 2);
                    uint32_t bf[2] = { ldu(&cur[kc * V_STRIDE + vn]),
                                       ldu(&cur[(kc + 4) * V_STRIDE + vn]) };
                    mma_tf32(oacc[nt], af, bf);
                }
            }
            if (jt + 1 < 8) CP_WAIT0();
            __syncthreads();        // also separates last V read from partial writes
        }

        // store per-slice partials (stride 72 -> conflict-free float2)
        #pragma unroll
        for (int nt = 0; nt < 8; nt++) {
            int c = nt * 8 + 2 * l;
            *(float2*)&part[ks * PSLICE + r4 * P_STRIDE + c] =
                make_float2(oacc[nt][0], oacc[nt][1]);
            *(float2*)&part[ks * PSLICE + (r4 + 8) * P_STRIDE + c] =
                make_float2(oacc[nt][2], oacc[nt][3]);
        }
    }
    __syncthreads();

    // reduce 8 partials -> ctx (tf32-rounded)
    {
        int rr = tid >> 4;              // 0..31
        int c0 = (tid & 15) * 4;        // 0..60
        float4 acc = make_float4(0.f, 0.f, 0.f, 0.f);
        #pragma unroll
        for (int s = 0; s < 8; s++) {
            float4 pv = *(const float4*)&part[s * PSLICE + rr * P_STRIDE + c0];
            acc.x += pv.x; acc.y += pv.y; acc.z += pv.z; acc.w += pv.w;
        }
        long o = (long)(b * T_ + i0 + rr) * D_ + h * DK_ + c0;
        *(float4*)&ctx[o] = make_float4(tfr(acc.x), tfr(acc.y),
                                        tfr(acc.z), tfr(acc.w));
    }
}

// ------------------------------ launch ---------------------------------------
extern "C" void kernel_launch(void* const* d_in, const int* in_sizes, int n_in,
                              void* d_out, int out_size)
{
    const float* q    = (const float*)d_in[0];
    const float* k    = (const float*)d_in[1];
    const float* v    = (const float*)d_in[2];
    const float* pos  = (const float*)d_in[3];
    const int*   mask = (const int*)  d_in[4];
    const float* lnqg = (const float*)d_in[5],  *lnqb = (const float*)d_in[6];
    const float* lnkg = (const float*)d_in[7],  *lnkb = (const float*)d_in[8];
    const float* lnvg = (const float*)d_in[9],  *lnvb = (const float*)d_in[10];
    const float* wq   = (const float*)d_in[11], *wk   = (const float*)d_in[12];
    const float* wv   = (const float*)d_in[13], *wpos = (const float*)d_in[14];
    const float* wfc  = (const float*)d_in[15];
    const float* pbu  = (const float*)d_in[16], *pbv  = (const float*)d_in[17];

    float* out  = (float*)d_out;                 // [B,T,D]
    float* attn = out + (size_t)ND_;             // [B,H,T,T]

    float *qn,*kn,*vn,*qu,*qvb,*kh,*vh,*pb,*ctx,*wbuf,*prb;
    cudaGetSymbolAddress((void**)&qn,  g_qn);
    cudaGetSymbolAddress((void**)&kn,  g_kn);
    cudaGetSymbolAddress((void**)&vn,  g_vn);
    cudaGetSymbolAddress((void**)&qu,  g_qu);
    cudaGetSymbolAddress((void**)&qvb, g_qv);
    cudaGetSymbolAddress((void**)&kh,  g_kh);
    cudaGetSymbolAddress((void**)&vh,  g_vh);
    cudaGetSymbolAddress((void**)&pb,  g_p);
    cudaGetSymbolAddress((void**)&ctx, g_ctx);
    cudaGetSymbolAddress((void**)&wbuf, g_w);
    cudaGetSymbolAddress((void**)&prb, g_pr);

    static const size_t fused_smem = SMEM_FLOATS * sizeof(float);
    cudaFuncSetAttribute(fused_attn,
                         cudaFuncAttributeMaxDynamicSharedMemorySize,
                         (int)fused_smem);

    // single-launch tf32 pre-round of 5 weights + pos input
    {
        int pn4 = (P_ * D_) / 4;
        round_all<<<dim3((pn4 + 255) / 256, 6), 256>>>(
            wq, wk, wv, wpos, wfc, pos, wbuf, prb);
    }

    // merged LayerNorms (tf32-rounded outputs)
    ln3_kernel<<<dim3(NROW_, 3), 256>>>(q, k, v,
        lnqg, lnqb, lnkg, lnkb, lnvg, lnvb, qn, kn, vn);

    // merged Q/K/V/pos projections (grid.z = 4)
    qkvp_gemm<<<dim3(4,64,4),256>>>(qn, kn, vn, prb, wbuf,
        qu, kh, vh, qvb, pb, pbu, pbv);

    // fused attention
    fused_attn<<<dim3(32, 64), 512, fused_smem>>>(
        qu, qvb, kh, vh, pb, mask, attn, ctx);

    // out = ctx @ Wfc^T + residual(q)  (fp32 output)
    mma_gemm<128,128,64,32,true,false><<<dim3(4,64,1),256>>>(
        ctx, wbuf + 4L * D_ * D_, out, q,
        NROW_, D_, D_, 1.f, 0);
}

// round 15
// speedup vs baseline: 1.4872x; 1.0555x over previous
#include <cuda_runtime.h>
#include <cuda_bf16.h>
#include <math.h>
#include <stdint.h>

// Problem constants
#define B_  8
#define T_  1024
#define D_  512
#define H_  8
#define DK_ 64
#define P_  2047          // 2*T-1
#define NROW_ (B_*T_)     // 8192
#define ND_  (NROW_*D_)   // 4194304

// -------------------- device scratch (no allocs allowed) --------------------
__device__ float g_qn [ND_];
__device__ float g_kn [ND_];
__device__ float g_vn [ND_];
__device__ float g_qu [ND_];   // qh + pos_bias_u (tf32, dk pair-permuted)
__device__ float g_qv [ND_];   // qh + pos_bias_v (tf32, dk pair-permuted)
__device__ float g_kh [ND_];   // tf32, dk pair-permuted
__device__ float g_vh [ND_];   // tf32, natural
__device__ float g_p  [(P_+1)*D_]; // tf32, dk pair-permuted (row 2047 = pad)
__device__ float g_ctx[ND_];   // attn @ V (tf32-rounded at producer)
__device__ float g_w  [5][D_*D_];  // tf32-rounded weights: wq,wk,wv,wpos,wfc
__device__ float g_pr [P_*D_];     // tf32-rounded pos input

__device__ __forceinline__ int pos8(int x) { return ((x & 3) << 1) | ((x >> 2) & 1); }

// ------------------------- TF32 helpers --------------------------------------
__device__ __forceinline__ uint32_t f2tf(float f) {
    uint32_t u;
    asm("cvt.rna.tf32.f32 %0, %1;" : "=r"(u) : "f"(f));
    return u;
}
__device__ __forceinline__ float tfr(float f) { return __uint_as_float(f2tf(f)); }

__device__ __forceinline__ void mma_tf32(float c[4], const uint32_t a[4],
                                         const uint32_t b[2]) {
    asm volatile(
        "mma.sync.aligned.m16n8k8.row.col.f32.tf32.tf32.f32 "
        "{%0,%1,%2,%3},{%4,%5,%6,%7},{%8,%9},{%0,%1,%2,%3};\n"
        : "+f"(c[0]), "+f"(c[1]), "+f"(c[2]), "+f"(c[3])
        : "r"(a[0]), "r"(a[1]), "r"(a[2]), "r"(a[3]), "r"(b[0]), "r"(b[1]));
}

__device__ __forceinline__ void cp16(float* dst_smem, const float* src, bool valid) {
    uint32_t d = (uint32_t)__cvta_generic_to_shared(dst_smem);
    int sz = valid ? 16 : 0;
    asm volatile("cp.async.cg.shared.global [%0], [%1], 16, %2;\n"
                 :: "r"(d), "l"(src), "r"(sz));
}
#define CP_COMMIT() asm volatile("cp.async.commit_group;\n" ::: "memory")
#define CP_WAIT0()  asm volatile("cp.async.wait_group 0;\n" ::: "memory")
#define CP_WAIT1()  asm volatile("cp.async.wait_group 1;\n" ::: "memory")

__device__ __forceinline__ uint32_t ldu(const float* p) {
    return __float_as_uint(*p);
}

// ----------------------- tf32 pre-round pass (single launch) ------------------
__global__ __launch_bounds__(256)
void round_all(const float* __restrict__ wq, const float* __restrict__ wk,
               const float* __restrict__ wv, const float* __restrict__ wpos,
               const float* __restrict__ wfc, const float* __restrict__ pos,
               float* __restrict__ wbuf, float* __restrict__ prb)
{
    int slice = blockIdx.y;
    const float* src;
    float* dst;
    int n4;
    if (slice < 5) {
        src = (slice == 0) ? wq : (slice == 1) ? wk : (slice == 2) ? wv
            : (slice == 3) ? wpos : wfc;
        dst = wbuf + (long)slice * D_ * D_;
        n4 = (D_ * D_) / 4;
    } else {
        src = pos;
        dst = prb;
        n4 = (P_ * D_) / 4;
    }
    int i = blockIdx.x * 256 + threadIdx.x;
    if (i < n4) {
        float4 v = ((const float4*)src)[i];
        v.x = tfr(v.x); v.y = tfr(v.y); v.z = tfr(v.z); v.w = tfr(v.w);
        ((float4*)dst)[i] = v;
    }
}

// ------------------------- merged LayerNorm (3 slices) ------------------------
__global__ __launch_bounds__(256)
void ln3_kernel(const float* __restrict__ q, const float* __restrict__ k,
                const float* __restrict__ v,
                const float* __restrict__ gq, const float* __restrict__ bq,
                const float* __restrict__ gk, const float* __restrict__ bk,
                const float* __restrict__ gv, const float* __restrict__ bv,
                float* __restrict__ yq, float* __restrict__ yk,
                float* __restrict__ yv)
{
    int slice = blockIdx.y;
    const float* x  = (slice == 0) ? q  : (slice == 1) ? k  : v;
    const float* g  = (slice == 0) ? gq : (slice == 1) ? gk : gv;
    const float* bb = (slice == 0) ? bq : (slice == 1) ? bk : bv;
    float*       y  = (slice == 0) ? yq : (slice == 1) ? yk : yv;

    long row = blockIdx.x;
    const float2* xr = (const float2*)(x + row * D_);
    float2*       yr = (float2*)(y + row * D_);
    int tid = threadIdx.x;
    float2 vv = xr[tid];
    float s  = vv.x + vv.y;
    float sq = vv.x * vv.x + vv.y * vv.y;

    __shared__ float rs[8], rq[8];
    #pragma unroll
    for (int o = 16; o > 0; o >>= 1) {
        s  += __shfl_xor_sync(0xffffffffu, s,  o);
        sq += __shfl_xor_sync(0xffffffffu, sq, o);
    }
    int wid = tid >> 5;
    if ((tid & 31) == 0) { rs[wid] = s; rq[wid] = sq; }
    __syncthreads();
    if (tid == 0) {
        float a = 0.f, b2 = 0.f;
        #pragma unroll
        for (int w = 0; w < 8; w++) { a += rs[w]; b2 += rq[w]; }
        rs[0] = a; rq[0] = b2;
    }
    __syncthreads();
    float mean = rs[0] * (1.0f / D_);
    float var  = rq[0] * (1.0f / D_) - mean * mean;
    float rstd = rsqrtf(var + 1e-5f);
    const float2* gv2 = (const float2*)g;
    const float2* bv2 = (const float2*)bb;
    float2 gg = gv2[tid], bbv = bv2[tid];
    float2 o;
    o.x = tfr((vv.x - mean) * rstd * gg.x + bbv.x);
    o.y = tfr((vv.y - mean) * rstd * gg.y + bbv.y);
    yr[tid] = o;
}

// ------------------------------ TF32 MMA GEMM core ----------------------------
template<int BM, int BN, int WM, int WN, bool TRANS_B, bool CVT_OUT>
__device__ __forceinline__
void gemm_core(const float* __restrict__ A, const float* __restrict__ Bm,
               float* __restrict__ C, float* __restrict__ C2,
               const float* __restrict__ bias1, const float* __restrict__ bias2,
               const float* __restrict__ Res,
               int M, int N, int K, int lda, int ldb, int ldc,
               float alpha, bool perm, int m0, int n0)
{
    constexpr int BK = 16;
    constexpr int MT = WM / 16;
    constexpr int NT = WN / 8;
    constexpr int WCOLS = BN / WN;
    static_assert((BM / WM) * (BN / WN) == 8, "8 warps required");

    __shared__ float As[3][BM][BK + 4];
    __shared__ float Bs[3][TRANS_B ? BN : BK][TRANS_B ? (BK + 4) : (BN + 8)];

    int tid  = threadIdx.x;
    int warp = tid >> 5, lane = tid & 31;
    int wm0 = (warp / WCOLS) * WM;
    int wn0 = (warp % WCOLS) * WN;

    auto ldg_async = [&](int k0, int buf) {
        #pragma unroll
        for (int it = 0; it < (BM * BK) / (4 * 256); it++) {
            int s = tid + it * 256;
            int row = s >> 2, kq = s & 3;
            int gm = m0 + row;
            cp16(&As[buf][row][kq * 4], A + (long)gm * lda + k0 + kq * 4, gm < M);
        }
        if (TRANS_B) {
            #pragma unroll
            for (int it = 0; it < (BN * BK) / (4 * 256); it++) {
                int s = tid + it * 256;
                int n = s >> 2, kq = s & 3;
                int gn = n0 + n;
                cp16(&Bs[buf][n][kq * 4], Bm + (long)gn * ldb + k0 + kq * 4, gn < N);
            }
        } else {
            #pragma unroll
            for (int it = 0; it < (BK * BN) / (4 * 256); it++) {
                int s = tid + it * 256;
                int kk = s / (BN / 4), nq = s % (BN / 4);
                cp16(&Bs[buf][kk][nq * 4],
                     Bm + (long)(k0 + kk) * ldb + n0 + nq * 4, true);
            }
        }
        CP_COMMIT();
    };

    float acc[MT][NT][4];
    #pragma unroll
    for (int i = 0; i < MT; i++)
        #pragma unroll
        for (int j = 0; j < NT; j++)
            #pragma unroll
            for (int e = 0; e < 4; e++) acc[i][j][e] = 0.f;

    const int nIter = K / BK;
    ldg_async(0, 0);
    if (nIter > 1) ldg_async(BK, 1);
    if (nIter > 1) { CP_WAIT1(); } else { CP_WAIT0(); }
    __syncthreads();

    for (int itk = 0; itk < nIter; itk++) {
        int buf = itk % 3;
        if (itk + 2 < nIter) ldg_async((itk + 2) * BK, (itk + 2) % 3);

        #pragma unroll
        for (int ks = 0; ks < 2; ks++) {
            const int kc = ks * 8 + (lane & 3);
            uint32_t af[MT][4];
            uint32_t bf[NT][2];
            #pragma unroll
            for (int mt = 0; mt < MT; mt++) {
                int mrow = wm0 + mt * 16 + (lane >> 2);
                af[mt][0] = ldu(&As[buf][mrow    ][kc    ]);
                af[mt][1] = ldu(&As[buf][mrow + 8][kc    ]);
                af[mt][2] = ldu(&As[buf][mrow    ][kc + 4]);
                af[mt][3] = ldu(&As[buf][mrow + 8][kc + 4]);
            }
            #pragma unroll
            for (int nt = 0; nt < NT; nt++) {
                int ncol = wn0 + nt * 8 + (lane >> 2);
                if (TRANS_B) {
                    bf[nt][0] = ldu(&Bs[buf][ncol][kc    ]);
                    bf[nt][1] = ldu(&Bs[buf][ncol][kc + 4]);
                } else {
                    bf[nt][0] = ldu(&Bs[buf][kc    ][ncol]);
                    bf[nt][1] = ldu(&Bs[buf][kc + 4][ncol]);
                }
            }
            #pragma unroll
            for (int mt = 0; mt < MT; mt++)
                #pragma unroll
                for (int nt = 0; nt < NT; nt++)
                    mma_tf32(acc[mt][nt], af[mt], bf[nt]);
        }

        if (itk + 1 < nIter) {
            if (itk + 2 < nIter) { CP_WAIT1(); } else { CP_WAIT0(); }
        }
        __syncthreads();
    }

    auto emit = [&](int gm, int gn, float v) {
        if (gm < M && gn < N) {
            float val = v * alpha;
            if (Res) val += Res[(long)gm * ldc + gn];
            int gns = perm ? ((gn & ~7) | pos8(gn & 7)) : gn;
            if (C2) {
                float v1 = val + bias1[gn];
                float v2 = val + bias2[gn];
                if (CVT_OUT) { v1 = tfr(v1); v2 = tfr(v2); }
                C [(long)gm * ldc + gns] = v1;
                C2[(long)gm * ldc + gns] = v2;
            } else {
                float v1 = val + (bias1 ? bias1[gn] : 0.f);
                if (CVT_OUT) v1 = tfr(v1);
                C[(long)gm * ldc + gns] = v1;
            }
        }
    };
    #pragma unroll
    for (int mt = 0; mt < MT; mt++) {
        #pragma unroll
        for (int nt = 0; nt < NT; nt++) {
            int gm = m0 + wm0 + mt * 16 + (lane >> 2);
            int gn = n0 + wn0 + nt * 8 + 2 * (lane & 3);
            emit(gm,     gn,     acc[mt][nt][0]);
            emit(gm,     gn + 1, acc[mt][nt][1]);
            emit(gm + 8, gn,     acc[mt][nt][2]);
            emit(gm + 8, gn + 1, acc[mt][nt][3]);
        }
    }
}

// generic wrapper (FC)
template<int BM, int BN, int WM, int WN, bool TRANS_B, bool CVT_OUT>
__global__ __launch_bounds__(256)
void mma_gemm(const float* __restrict__ A, const float* __restrict__ Bm,
              float* __restrict__ C,
              const float* __restrict__ Res,
              int M, int N, int K, float alpha, int perm)
{
    gemm_core<BM,BN,WM,WN,TRANS_B,CVT_OUT>(
        A, Bm, C, nullptr, nullptr, nullptr, Res,
        M, N, K, K, K, N, alpha, perm != 0,
        blockIdx.y * BM, blockIdx.x * BN);
}

// merged Q/K/V/pos projection: grid.z in {0,1,2,3}
__global__ __launch_bounds__(256)
void qkvp_gemm(const float* __restrict__ qn, const float* __restrict__ kn,
               const float* __restrict__ vn, const float* __restrict__ prb,
               const float* __restrict__ wbuf,
               float* __restrict__ qu, float* __restrict__ kh,
               float* __restrict__ vh, float* __restrict__ qvb,
               float* __restrict__ pb,
               const float* __restrict__ pbu, const float* __restrict__ pbv)
{
    int zz = blockIdx.z;
    if (zz == 3) {
        if (blockIdx.y >= 16) return;
        gemm_core<128,128,64,32,true,true>(
            prb, wbuf + 3L * D_ * D_, pb, nullptr, nullptr, nullptr, nullptr,
            P_, D_, D_, D_, D_, D_, 1.f, true,
            blockIdx.y * 128, blockIdx.x * 128);
        return;
    }
    const float* A  = (zz == 0) ? qn : (zz == 1) ? kn : vn;
    const float* Bm = wbuf + (long)zz * D_ * D_;
    float* C  = (zz == 0) ? qu : (zz == 1) ? kh : vh;
    float* C2 = (zz == 0) ? qvb : nullptr;
    const float* b1 = (zz == 0) ? pbu : nullptr;
    const float* b2 = (zz == 0) ? pbv : nullptr;
    bool perm = (zz < 2);
    gemm_core<128,128,64,32,true,true>(
        A, Bm, C, C2, b1, b2, nullptr,
        NROW_, D_, D_, D_, D_, D_, 1.f, perm,
        blockIdx.y * 128, blockIdx.x * 128);
}

// ===================== FUSED ATTENTION ======================================
// Phases 1-2 run as 8 independent warp-pairs (64-thread named barriers):
// pair ne owns key/pos rows [ne*16, ne*16+16) of every streamed tile.
#define S_STRIDE 1028
#define K_STRIDE 72
#define V_STRIDE 72
#define P_STRIDE 72                 // partial-sum row stride (phase 4 reduce)
#define PSLICE   (32 * P_STRIDE)    // 2304 floats per k-slice partial
#define SMEM_FLOATS (32*S_STRIDE + 2*128*V_STRIDE + 2*32*K_STRIDE)

__global__ __launch_bounds__(512)
void fused_attn(const float* __restrict__ qu, const float* __restrict__ qv,
                const float* __restrict__ kh, const float* __restrict__ vh,
                const float* __restrict__ pbuf, const int* __restrict__ mask,
                float* __restrict__ attn, float* __restrict__ ctx)
{
    extern __shared__ float sm[];
    float* S   = sm;                          // [32][1028], natural
    float* KV0 = sm + 32 * S_STRIDE;          // [128][72]
    float* KV1 = KV0 + 128 * V_STRIDE;
    float* Qu  = KV1 + 128 * V_STRIDE;        // [32][72]
    float* Qv  = Qu + 32 * K_STRIDE;
    float* part = KV0;                        // phase-4 partials alias KV0/KV1

    const int i0 = blockIdx.x * 32;
    const int z  = blockIdx.y;                // b*H + h
    const int b  = z >> 3, h = z & 7;
    const int tid = threadIdx.x;
    const int w = tid >> 5, lane = tid & 31;
    const float scale = 0.125f;
    const float NEG = __int_as_float(0xff7fffff);

    const int mh = w & 1, ne = w >> 1;        // pair id = ne, member = mh
    const int r0 = mh * 16 + (lane >> 2);
    const int l  = lane & 3;
    const int pt_id = tid & 63;               // thread id within pair

    // pair-scoped barrier (ids 1..8; 0 is __syncthreads)
    #define PAIRBAR() asm volatile("bar.sync %0, 64;\n" :: "r"(ne + 1) : "memory")

    // ---- load Qu, Qv tiles (32 x 64), CTA-wide ----
    {
        int r = tid >> 4, kq = tid & 15;
        long base = ((long)(b * T_ + i0 + r) * D_ + h * DK_ + kq * 4);
        cp16(&Qu[r * K_STRIDE + kq * 4], qu + base, true);
        cp16(&Qv[r * K_STRIDE + kq * 4], qv + base, true);
    }
    CP_COMMIT();

    // pair-scoped strip loads: 16 rows x 64 floats = 256 float4 / 64 threads
    auto pload_k = [&](int jt, float* buf) {
        #pragma unroll
        for (int it = 0; it < 4; it++) {
            int s = pt_id + it * 64;
            int n = ne * 16 + (s >> 4), kq = s & 15;
            cp16(&buf[n * K_STRIDE + kq * 4],
                 kh + ((long)(b * T_ + jt * 128 + n) * D_ + h * DK_ + kq * 4), true);
        }
        CP_COMMIT();
    };
    auto pload_p = [&](int pt0, float* buf) {
        #pragma unroll
        for (int it = 0; it < 4; it++) {
            int s = pt_id + it * 64;
            int n = ne * 16 + (s >> 4), kq = s & 15;
            int p = pt0 + n;
            cp16(&buf[n * K_STRIDE + kq * 4],
                 pbuf + ((long)p * D_ + h * DK_ + kq * 4), p <= P_ - 1);
        }
        CP_COMMIT();
    };
    // CTA-wide V tile load (phase 4)
    auto load_v = [&](int jt, float* buf) {
        #pragma unroll
        for (int it = 0; it < 4; it++) {
            int s = tid + it * 512;
            int n = s >> 4, kq = s & 15;
            cp16(&buf[n * V_STRIDE + kq * 4],
                 vh + ((long)(b * T_ + jt * 128 + n) * D_ + h * DK_ + kq * 4), true);
        }
        CP_COMMIT();
    };

    // ---------------- Phase 1: ac = scale * Qu @ K^T (pair pipelines) --------
    pload_k(0, KV0);
    CP_WAIT0();
    __syncthreads();           // Qu/Qv visible CTA-wide + pair K0 strips done

    {
        uint32_t au[8][4];
        #pragma unroll
        for (int kk = 0; kk < 8; kk++) {
            int kp = kk * 8 + 2 * l;
            float2 p0 = *(const float2*)&Qu[r0 * K_STRIDE + kp];
            float2 p1 = *(const float2*)&Qu[(r0 + 8) * K_STRIDE + kp];
            au[kk][0] = __float_as_uint(p0.x);
            au[kk][1] = __float_as_uint(p1.x);
            au[kk][2] = __float_as_uint(p0.y);
            au[kk][3] = __float_as_uint(p1.y);
        }

        for (int jt = 0; jt < 8; jt++) {
            float* cur = (jt & 1) ? KV1 : KV0;
            float* nxt = (jt & 1) ? KV0 : KV1;
            if (jt + 1 < 8) pload_k(jt + 1, nxt);

            float acc[2][4] = {{0.f,0.f,0.f,0.f},{0.f,0.f,0.f,0.f}};
            #pragma unroll
            for (int kk = 0; kk < 8; kk++) {
                int kp = kk * 8 + 2 * l;
                #pragma unroll
                for (int nt = 0; nt < 2; nt++) {
                    int ncol = ne * 16 + nt * 8 + (lane >> 2);
                    float2 bp = *(const float2*)&cur[ncol * K_STRIDE + kp];
                    uint32_t bf[2] = { __float_as_uint(bp.x), __float_as_uint(bp.y) };
                    mma_tf32(acc[nt], au[kk], bf);
                }
            }
            #pragma unroll
            for (int nt = 0; nt < 2; nt++) {
                int c0 = jt * 128 + ne * 16 + nt * 8 + 2 * l;
                *(float2*)&S[r0 * S_STRIDE + c0] =
                    make_float2(acc[nt][0] * scale, acc[nt][1] * scale);
                *(float2*)&S[(r0 + 8) * S_STRIDE + c0] =
                    make_float2(acc[nt][2] * scale, acc[nt][3] * scale);
            }
            if (jt + 1 < 8) CP_WAIT0();
            PAIRBAR();
        }
    }

    // ------------- Phase 2: bd scatter-add over p-window (pair pipelines) ----
    const int pbase = (T_ - 1) - (i0 + 31);
    __syncthreads();           // all phase-1 S stores complete before scatter
    pload_p(pbase, KV0);
    {
        uint32_t av[8][4];
        #pragma unroll
        for (int kk = 0; kk < 8; kk++) {
            int kp = kk * 8 + 2 * l;
            float2 p0 = *(const float2*)&Qv[r0 * K_STRIDE + kp];
            float2 p1 = *(const float2*)&Qv[(r0 + 8) * K_STRIDE + kp];
            av[kk][0] = __float_as_uint(p0.x);
            av[kk][1] = __float_as_uint(p1.x);
            av[kk][2] = __float_as_uint(p0.y);
            av[kk][3] = __float_as_uint(p1.y);
        }
        CP_WAIT0();
        PAIRBAR();

        for (int pt = 0; pt < 9; pt++) {
            float* cur = (pt & 1) ? KV1 : KV0;
            float* nxt = (pt & 1) ? KV0 : KV1;
            if (pt + 1 < 9) pload_p(pbase + (pt + 1) * 128, nxt);

            float acc[2][4] = {{0.f,0.f,0.f,0.f},{0.f,0.f,0.f,0.f}};
            #pragma unroll
            for (int kk = 0; kk < 8; kk++) {
                int kp = kk * 8 + 2 * l;
                #pragma unroll
                for (int nt = 0; nt < 2; nt++) {
                    int ncol = ne * 16 + nt * 8 + (lane >> 2);
                    float2 bp = *(const float2*)&cur[ncol * K_STRIDE + kp];
                    uint32_t bf[2] = { __float_as_uint(bp.x), __float_as_uint(bp.y) };
                    mma_tf32(acc[nt], av[kk], bf);
                }
            }
            const int pt0 = pbase + pt * 128;
            #pragma unroll
            for (int nt = 0; nt < 2; nt++) {
                int c0 = ne * 16 + nt * 8 + 2 * l;
                #pragma unroll
                for (int e = 0; e < 4; e++) {
                    int r = r0 + (e >> 1) * 8;
                    int p = pt0 + c0 + (e & 1);
                    int j = p - (T_ - 1) + i0 + r;
                    if ((unsigned)j < (unsigned)T_)
                        S[r * S_STRIDE + j] += acc[nt][e] * scale;
                }
            }
            if (pt + 1 < 9) CP_WAIT0();
            PAIRBAR();
        }
    }
    __syncthreads();           // all scatters done before softmax / V overwrite

    // -------- prefetch V tile 0 (overlaps softmax) --------
    load_v(0, KV0);

    // ------ Phase 3: softmax; attn gets fp32, S gets tf32-rounded ------
    #pragma unroll
    for (int t = 0; t < 2; t++) {
        int r = w + 16 * t;
        int i = i0 + r;
        const int4*   mrow = (const int4*)(mask + ((long)b * T_ + i) * T_);
        float4*       srow = (float4*)(S + r * S_STRIDE);
        float4*       arow = (float4*)(attn + ((long)z * T_ + i) * T_);

        float4 vals[8];
        float lmax = NEG;
        #pragma unroll
        for (int e = 0; e < 8; e++) {
            int idx = e * 32 + lane;
            float4 v = srow[idx];
            int4   m = mrow[idx];
            v.x = (m.x == 0) ? NEG : v.x;
            v.y = (m.y == 0) ? NEG : v.y;
            v.z = (m.z == 0) ? NEG : v.z;
            v.w = (m.w == 0) ? NEG : v.w;
            vals[e] = v;
            lmax = fmaxf(lmax, fmaxf(fmaxf(v.x, v.y), fmaxf(v.z, v.w)));
        }
        #pragma unroll
        for (int o = 16; o > 0; o >>= 1)
            lmax = fmaxf(lmax, __shfl_xor_sync(0xffffffffu, lmax, o));

        if (lmax == NEG) {
            float4 zero = make_float4(0.f, 0.f, 0.f, 0.f);
            #pragma unroll
            for (int e = 0; e < 8; e++) {
                int idx = e * 32 + lane;
                srow[idx] = zero;
                arow[idx] = zero;
            }
            continue;
        }
        float sum = 0.f;
        #pragma unroll
        for (int e = 0; e < 8; e++) {
            float4 v = vals[e];
            v.x = __expf(v.x - lmax); v.y = __expf(v.y - lmax);
            v.z = __expf(v.z - lmax); v.w = __expf(v.w - lmax);
            vals[e] = v;
            sum += (v.x + v.y) + (v.z + v.w);
        }
        #pragma unroll
        for (int o = 16; o > 0; o >>= 1)
            sum += __shfl_xor_sync(0xffffffffu, sum, o);
        float inv = 1.0f / sum;
        #pragma unroll
        for (int e = 0; e < 8; e++) {
            int idx = e * 32 + lane;
            float4 v = vals[e];
            v.x *= inv; v.y *= inv; v.z *= inv; v.w *= inv;
            arow[idx] = v;
            float4 vt;
            vt.x = tfr(v.x); vt.y = tfr(v.y);
            vt.z = tfr(v.z); vt.w = tfr(v.w);
            srow[idx] = vt;
        }
    }
    CP_WAIT0();
    __syncthreads();

    // ------- Phase 4 (split-K): warp (mt, ks); ks covers kk {2ks, 2ks+1} -----
    {
        const int mt4 = w & 1, ks = w >> 1;
        const int r4 = mt4 * 16 + (lane >> 2);
        float oacc[8][4];
        #pragma unroll
        for (int nt = 0; nt < 8; nt++)
            #pragma unroll
            for (int e = 0; e < 4; e++) oacc[nt][e] = 0.f;

        for (int jt = 0; jt < 8; jt++) {
            float* cur = (jt & 1) ? KV1 : KV0;
            float* nxt = (jt & 1) ? KV0 : KV1;
            if (jt + 1 < 8) load_v(jt + 1, nxt);

            #pragma unroll
            for (int kx = 0; kx < 2; kx++) {
                int kc = (ks * 2 + kx) * 8 + l;
                uint32_t af[4] = {
                    ldu(&S[r4 * S_STRIDE + jt * 128 + kc]),
                    ldu(&S[(r4 + 8) * S_STRIDE + jt * 128 + kc]),
                    ldu(&S[r4 * S_STRIDE + jt * 128 + kc + 4]),
                    ldu(&S[(r4 + 8) * S_STRIDE + jt * 128 + kc + 4]) };
                #pragma unroll
                for (int nt = 0; nt < 8; nt++) {
                    int vn = nt * 8 + (lane >> 2);
                    uint32_t bf[2] = { ldu(&cur[kc * V_STRIDE + vn]),
                                       ldu(&cur[(kc + 4) * V_STRIDE + vn]) };
                    mma_tf32(oacc[nt], af, bf);
                }
            }
            if (jt + 1 < 8) CP_WAIT0();
            __syncthreads();
        }

        // store per-slice partials (stride 72 -> conflict-free float2)
        #pragma unroll
        for (int nt = 0; nt < 8; nt++) {
            int c = nt * 8 + 2 * l;
            *(float2*)&part[ks * PSLICE + r4 * P_STRIDE + c] =
                make_float2(oacc[nt][0], oacc[nt][1]);
            *(float2*)&part[ks * PSLICE + (r4 + 8) * P_STRIDE + c] =
                make_float2(oacc[nt][2], oacc[nt][3]);
        }
    }
    __syncthreads();

    // reduce 8 partials -> ctx (tf32-rounded)
    {
        int rr = tid >> 4;              // 0..31
        int c0 = (tid & 15) * 4;        // 0..60
        float4 acc = make_float4(0.f, 0.f, 0.f, 0.f);
        #pragma unroll
        for (int s = 0; s < 8; s++) {
            float4 pv = *(const float4*)&part[s * PSLICE + rr * P_STRIDE + c0];
            acc.x += pv.x; acc.y += pv.y; acc.z += pv.z; acc.w += pv.w;
        }
        long o = (long)(b * T_ + i0 + rr) * D_ + h * DK_ + c0;
        *(float4*)&ctx[o] = make_float4(tfr(acc.x), tfr(acc.y),
                                        tfr(acc.z), tfr(acc.w));
    }
    #undef PAIRBAR
}

// ------------------------------ launch ---------------------------------------
extern "C" void kernel_launch(void* const* d_in, const int* in_sizes, int n_in,
                              void* d_out, int out_size)
{
    const float* q    = (const float*)d_in[0];
    const float* k    = (const float*)d_in[1];
    const float* v    = (const float*)d_in[2];
    const float* pos  = (const float*)d_in[3];
    const int*   mask = (const int*)  d_in[4];
    const float* lnqg = (const float*)d_in[5],  *lnqb = (const float*)d_in[6];
    const float* lnkg = (const float*)d_in[7],  *lnkb = (const float*)d_in[8];
    const float* lnvg = (const float*)d_in[9],  *lnvb = (const float*)d_in[10];
    const float* wq   = (const float*)d_in[11], *wk   = (const float*)d_in[12];
    const float* wv   = (const float*)d_in[13], *wpos = (const float*)d_in[14];
    const float* wfc  = (const float*)d_in[15];
    const float* pbu  = (const float*)d_in[16], *pbv  = (const float*)d_in[17];

    float* out  = (float*)d_out;                 // [B,T,D]
    float* attn = out + (size_t)ND_;             // [B,H,T,T]

    float *qn,*kn,*vn,*qu,*qvb,*kh,*vh,*pb,*ctx,*wbuf,*prb;
    cudaGetSymbolAddress((void**)&qn,  g_qn);
    cudaGetSymbolAddress((void**)&kn,  g_kn);
    cudaGetSymbolAddress((void**)&vn,  g_vn);
    cudaGetSymbolAddress((void**)&qu,  g_qu);
    cudaGetSymbolAddress((void**)&qvb, g_qv);
    cudaGetSymbolAddress((void**)&kh,  g_kh);
    cudaGetSymbolAddress((void**)&vh,  g_vh);
    cudaGetSymbolAddress((void**)&pb,  g_p);
    cudaGetSymbolAddress((void**)&ctx, g_ctx);
    cudaGetSymbolAddress((void**)&wbuf, g_w);
    cudaGetSymbolAddress((void**)&prb, g_pr);

    static const size_t fused_smem = SMEM_FLOATS * sizeof(float);
    cudaFuncSetAttribute(fused_attn,
                         cudaFuncAttributeMaxDynamicSharedMemorySize,
                         (int)fused_smem);

    // single-launch tf32 pre-round of 5 weights + pos input
    {
        int pn4 = (P_ * D_) / 4;
        round_all<<<dim3((pn4 + 255) / 256, 6), 256>>>(
            wq, wk, wv, wpos, wfc, pos, wbuf, prb);
    }

    // merged LayerNorms (tf32-rounded outputs)
    ln3_kernel<<<dim3(NROW_, 3), 256>>>(q, k, v,
        lnqg, lnqb, lnkg, lnkb, lnvg, lnvb, qn, kn, vn);

    // merged Q/K/V/pos projections (grid.z = 4)
    qkvp_gemm<<<dim3(4,64,4),256>>>(qn, kn, vn, prb, wbuf,
        qu, kh, vh, qvb, pb, pbu, pbv);

    // fused attention
    fused_attn<<<dim3(32, 64), 512, fused_smem>>>(
        qu, qvb, kh, vh, pb, mask, attn, ctx);

    // out = ctx @ Wfc^T + residual(q)  (fp32 output)
    mma_gemm<128,128,64,32,true,false><<<dim3(4,64,1),256>>>(
        ctx, wbuf + 4L * D_ * D_, out, q,
        NROW_, D_, D_, 1.f, 0);
}

// round 16
// speedup vs baseline: 1.5237x; 1.0245x over previous
#include <cuda_runtime.h>
#include <cuda_bf16.h>
#include <math.h>
#include <stdint.h>

// Problem constants
#define B_  8
#define T_  1024
#define D_  512
#define H_  8
#define DK_ 64
#define P_  2047          // 2*T-1
#define NROW_ (B_*T_)     // 8192
#define ND_  (NROW_*D_)   // 4194304

// -------------------- device scratch (no allocs allowed) --------------------
__device__ float g_qn [ND_];
__device__ float g_kn [ND_];
__device__ float g_vn [ND_];
__device__ float g_qu [ND_];   // qh + pos_bias_u (tf32, dk pair-permuted)
__device__ float g_qv [ND_];   // qh + pos_bias_v (tf32, dk pair-permuted)
__device__ float g_kh [ND_];   // tf32, dk pair-permuted
__device__ float g_vh [ND_];   // tf32, natural
__device__ float g_p  [(P_+1)*D_]; // tf32, dk pair-permuted (row 2047 = pad)
__device__ float g_ctx[ND_];   // attn @ V (tf32-rounded at producer)
__device__ float g_w  [5][D_*D_];  // tf32-rounded weights: wq,wk,wv,wpos,wfc
__device__ float g_pr [P_*D_];     // tf32-rounded pos input

__device__ __forceinline__ int pos8(int x) { return ((x & 3) << 1) | ((x >> 2) & 1); }

// ------------------------- TF32 helpers --------------------------------------
__device__ __forceinline__ uint32_t f2tf(float f) {
    uint32_t u;
    asm("cvt.rna.tf32.f32 %0, %1;" : "=r"(u) : "f"(f));
    return u;
}
__device__ __forceinline__ float tfr(float f) { return __uint_as_float(f2tf(f)); }

__device__ __forceinline__ void mma_tf32(float c[4], const uint32_t a[4],
                                         const uint32_t b[2]) {
    asm volatile(
        "mma.sync.aligned.m16n8k8.row.col.f32.tf32.tf32.f32 "
        "{%0,%1,%2,%3},{%4,%5,%6,%7},{%8,%9},{%0,%1,%2,%3};\n"
        : "+f"(c[0]), "+f"(c[1]), "+f"(c[2]), "+f"(c[3])
        : "r"(a[0]), "r"(a[1]), "r"(a[2]), "r"(a[3]), "r"(b[0]), "r"(b[1]));
}

__device__ __forceinline__ void cp16(float* dst_smem, const float* src, bool valid) {
    uint32_t d = (uint32_t)__cvta_generic_to_shared(dst_smem);
    int sz = valid ? 16 : 0;
    asm volatile("cp.async.cg.shared.global [%0], [%1], 16, %2;\n"
                 :: "r"(d), "l"(src), "r"(sz));
}
#define CP_COMMIT() asm volatile("cp.async.commit_group;\n" ::: "memory")
#define CP_WAIT0()  asm volatile("cp.async.wait_group 0;\n" ::: "memory")
#define CP_WAIT1()  asm volatile("cp.async.wait_group 1;\n" ::: "memory")

__device__ __forceinline__ uint32_t ldu(const float* p) {
    return __float_as_uint(*p);
}

// ----------------------- tf32 pre-round pass (single launch) ------------------
__global__ __launch_bounds__(256)
void round_all(const float* __restrict__ wq, const float* __restrict__ wk,
               const float* __restrict__ wv, const float* __restrict__ wpos,
               const float* __restrict__ wfc, const float* __restrict__ pos,
               float* __restrict__ wbuf, float* __restrict__ prb)
{
    int slice = blockIdx.y;
    const float* src;
    float* dst;
    int n4;
    if (slice < 5) {
        src = (slice == 0) ? wq : (slice == 1) ? wk : (slice == 2) ? wv
            : (slice == 3) ? wpos : wfc;
        dst = wbuf + (long)slice * D_ * D_;
        n4 = (D_ * D_) / 4;
    } else {
        src = pos;
        dst = prb;
        n4 = (P_ * D_) / 4;
    }
    int i = blockIdx.x * 256 + threadIdx.x;
    if (i < n4) {
        float4 v = ((const float4*)src)[i];
        v.x = tfr(v.x); v.y = tfr(v.y); v.z = tfr(v.z); v.w = tfr(v.w);
        ((float4*)dst)[i] = v;
    }
}

// ------------------------- merged LayerNorm (3 slices) ------------------------
__global__ __launch_bounds__(256)
void ln3_kernel(const float* __restrict__ q, const float* __restrict__ k,
                const float* __restrict__ v,
                const float* __restrict__ gq, const float* __restrict__ bq,
                const float* __restrict__ gk, const float* __restrict__ bk,
                const float* __restrict__ gv, const float* __restrict__ bv,
                float* __restrict__ yq, float* __restrict__ yk,
                float* __restrict__ yv)
{
    int slice = blockIdx.y;
    const float* x  = (slice == 0) ? q  : (slice == 1) ? k  : v;
    const float* g  = (slice == 0) ? gq : (slice == 1) ? gk : gv;
    const float* bb = (slice == 0) ? bq : (slice == 1) ? bk : bv;
    float*       y  = (slice == 0) ? yq : (slice == 1) ? yk : yv;

    long row = blockIdx.x;
    const float2* xr = (const float2*)(x + row * D_);
    float2*       yr = (float2*)(y + row * D_);
    int tid = threadIdx.x;
    float2 vv = xr[tid];
    float s  = vv.x + vv.y;
    float sq = vv.x * vv.x + vv.y * vv.y;

    __shared__ float rs[8], rq[8];
    #pragma unroll
    for (int o = 16; o > 0; o >>= 1) {
        s  += __shfl_xor_sync(0xffffffffu, s,  o);
        sq += __shfl_xor_sync(0xffffffffu, sq, o);
    }
    int wid = tid >> 5;
    if ((tid & 31) == 0) { rs[wid] = s; rq[wid] = sq; }
    __syncthreads();
    if (tid == 0) {
        float a = 0.f, b2 = 0.f;
        #pragma unroll
        for (int w = 0; w < 8; w++) { a += rs[w]; b2 += rq[w]; }
        rs[0] = a; rq[0] = b2;
    }
    __syncthreads();
    float mean = rs[0] * (1.0f / D_);
    float var  = rq[0] * (1.0f / D_) - mean * mean;
    float rstd = rsqrtf(var + 1e-5f);
    const float2* gv2 = (const float2*)g;
    const float2* bv2 = (const float2*)bb;
    float2 gg = gv2[tid], bbv = bv2[tid];
    float2 o;
    o.x = tfr((vv.x - mean) * rstd * gg.x + bbv.x);
    o.y = tfr((vv.y - mean) * rstd * gg.y + bbv.y);
    yr[tid] = o;
}

// ------------------------------ TF32 MMA GEMM core ----------------------------
template<int BM, int BN, int WM, int WN, bool TRANS_B, bool CVT_OUT>
__device__ __forceinline__
void gemm_core(const float* __restrict__ A, const float* __restrict__ Bm,
               float* __restrict__ C, float* __restrict__ C2,
               const float* __restrict__ bias1, const float* __restrict__ bias2,
               const float* __restrict__ Res,
               int M, int N, int K, int lda, int ldb, int ldc,
               float alpha, bool perm, int m0, int n0)
{
    constexpr int BK = 16;
    constexpr int MT = WM / 16;
    constexpr int NT = WN / 8;
    constexpr int WCOLS = BN / WN;
    static_assert((BM / WM) * (BN / WN) == 8, "8 warps required");

    __shared__ float As[3][BM][BK + 4];
    __shared__ float Bs[3][TRANS_B ? BN : BK][TRANS_B ? (BK + 4) : (BN + 8)];

    int tid  = threadIdx.x;
    int warp = tid >> 5, lane = tid & 31;
    int wm0 = (warp / WCOLS) * WM;
    int wn0 = (warp % WCOLS) * WN;

    auto ldg_async = [&](int k0, int buf) {
        #pragma unroll
        for (int it = 0; it < (BM * BK) / (4 * 256); it++) {
            int s = tid + it * 256;
            int row = s >> 2, kq = s & 3;
            int gm = m0 + row;
            cp16(&As[buf][row][kq * 4], A + (long)gm * lda + k0 + kq * 4, gm < M);
        }
        if (TRANS_B) {
            #pragma unroll
            for (int it = 0; it < (BN * BK) / (4 * 256); it++) {
                int s = tid + it * 256;
                int n = s >> 2, kq = s & 3;
                int gn = n0 + n;
                cp16(&Bs[buf][n][kq * 4], Bm + (long)gn * ldb + k0 + kq * 4, gn < N);
            }
        } else {
            #pragma unroll
            for (int it = 0; it < (BK * BN) / (4 * 256); it++) {
                int s = tid + it * 256;
                int kk = s / (BN / 4), nq = s % (BN / 4);
                cp16(&Bs[buf][kk][nq * 4],
                     Bm + (long)(k0 + kk) * ldb + n0 + nq * 4, true);
            }
        }
        CP_COMMIT();
    };

    float acc[MT][NT][4];
    #pragma unroll
    for (int i = 0; i < MT; i++)
        #pragma unroll
        for (int j = 0; j < NT; j++)
            #pragma unroll
            for (int e = 0; e < 4; e++) acc[i][j][e] = 0.f;

    const int nIter = K / BK;
    ldg_async(0, 0);
    if (nIter > 1) ldg_async(BK, 1);
    if (nIter > 1) { CP_WAIT1(); } else { CP_WAIT0(); }
    __syncthreads();

    for (int itk = 0; itk < nIter; itk++) {
        int buf = itk % 3;
        if (itk + 2 < nIter) ldg_async((itk + 2) * BK, (itk + 2) % 3);

        #pragma unroll
        for (int ks = 0; ks < 2; ks++) {
            const int kc = ks * 8 + (lane & 3);
            uint32_t af[MT][4];
            uint32_t bf[NT][2];
            #pragma unroll
            for (int mt = 0; mt < MT; mt++) {
                int mrow = wm0 + mt * 16 + (lane >> 2);
                af[mt][0] = ldu(&As[buf][mrow    ][kc    ]);
                af[mt][1] = ldu(&As[buf][mrow + 8][kc    ]);
                af[mt][2] = ldu(&As[buf][mrow    ][kc + 4]);
                af[mt][3] = ldu(&As[buf][mrow + 8][kc + 4]);
            }
            #pragma unroll
            for (int nt = 0; nt < NT; nt++) {
                int ncol = wn0 + nt * 8 + (lane >> 2);
                if (TRANS_B) {
                    bf[nt][0] = ldu(&Bs[buf][ncol][kc    ]);
                    bf[nt][1] = ldu(&Bs[buf][ncol][kc + 4]);
                } else {
                    bf[nt][0] = ldu(&Bs[buf][kc    ][ncol]);
                    bf[nt][1] = ldu(&Bs[buf][kc + 4][ncol]);
                }
            }
            #pragma unroll
            for (int mt = 0; mt < MT; mt++)
                #pragma unroll
                for (int nt = 0; nt < NT; nt++)
                    mma_tf32(acc[mt][nt], af[mt], bf[nt]);
        }

        if (itk + 1 < nIter) {
            if (itk + 2 < nIter) { CP_WAIT1(); } else { CP_WAIT0(); }
        }
        __syncthreads();
    }

    auto emit = [&](int gm, int gn, float v) {
        if (gm < M && gn < N) {
            float val = v * alpha;
            if (Res) val += Res[(long)gm * ldc + gn];
            int gns = perm ? ((gn & ~7) | pos8(gn & 7)) : gn;
            if (C2) {
                float v1 = val + bias1[gn];
                float v2 = val + bias2[gn];
                if (CVT_OUT) { v1 = tfr(v1); v2 = tfr(v2); }
                C [(long)gm * ldc + gns] = v1;
                C2[(long)gm * ldc + gns] = v2;
            } else {
                float v1 = val + (bias1 ? bias1[gn] : 0.f);
                if (CVT_OUT) v1 = tfr(v1);
                C[(long)gm * ldc + gns] = v1;
            }
        }
    };
    #pragma unroll
    for (int mt = 0; mt < MT; mt++) {
        #pragma unroll
        for (int nt = 0; nt < NT; nt++) {
            int gm = m0 + wm0 + mt * 16 + (lane >> 2);
            int gn = n0 + wn0 + nt * 8 + 2 * (lane & 3);
            emit(gm,     gn,     acc[mt][nt][0]);
            emit(gm,     gn + 1, acc[mt][nt][1]);
            emit(gm + 8, gn,     acc[mt][nt][2]);
            emit(gm + 8, gn + 1, acc[mt][nt][3]);
        }
    }
}

// generic wrapper (FC)
template<int BM, int BN, int WM, int WN, bool TRANS_B, bool CVT_OUT>
__global__ __launch_bounds__(256)
void mma_gemm(const float* __restrict__ A, const float* __restrict__ Bm,
              float* __restrict__ C,
              const float* __restrict__ Res,
              int M, int N, int K, float alpha, int perm)
{
    gemm_core<BM,BN,WM,WN,TRANS_B,CVT_OUT>(
        A, Bm, C, nullptr, nullptr, nullptr, Res,
        M, N, K, K, K, N, alpha, perm != 0,
        blockIdx.y * BM, blockIdx.x * BN);
}

// merged Q/K/V/pos projection: grid.z in {0,1,2,3}
__global__ __launch_bounds__(256)
void qkvp_gemm(const float* __restrict__ qn, const float* __restrict__ kn,
               const float* __restrict__ vn, const float* __restrict__ prb,
               const float* __restrict__ wbuf,
               float* __restrict__ qu, float* __restrict__ kh,
               float* __restrict__ vh, float* __restrict__ qvb,
               float* __restrict__ pb,
               const float* __restrict__ pbu, const float* __restrict__ pbv)
{
    int zz = blockIdx.z;
    if (zz == 3) {
        if (blockIdx.y >= 16) return;
        gemm_core<128,128,64,32,true,true>(
            prb, wbuf + 3L * D_ * D_, pb, nullptr, nullptr, nullptr, nullptr,
            P_, D_, D_, D_, D_, D_, 1.f, true,
            blockIdx.y * 128, blockIdx.x * 128);
        return;
    }
    const float* A  = (zz == 0) ? qn : (zz == 1) ? kn : vn;
    const float* Bm = wbuf + (long)zz * D_ * D_;
    float* C  = (zz == 0) ? qu : (zz == 1) ? kh : vh;
    float* C2 = (zz == 0) ? qvb : nullptr;
    const float* b1 = (zz == 0) ? pbu : nullptr;
    const float* b2 = (zz == 0) ? pbv : nullptr;
    bool perm = (zz < 2);
    gemm_core<128,128,64,32,true,true>(
        A, Bm, C, C2, b1, b2, nullptr,
        NROW_, D_, D_, D_, D_, D_, 1.f, perm,
        blockIdx.y * 128, blockIdx.x * 128);
}

// ===================== FUSED ATTENTION ======================================
// Phases 1-2 AND 4 run as 8 independent warp-pairs (64-thread named barriers).
// Phases 1-2: pair ne owns key/pos rows [ne*16, ne*16+16) of each tile.
// Phase 4 (split-K): pair ks owns V rows [ks*16, ks*16+16) of each tile.
#define S_STRIDE 1028
#define K_STRIDE 72
#define V_STRIDE 72
#define P_STRIDE 72                 // partial-sum row stride (phase 4 reduce)
#define PSLICE   (32 * P_STRIDE)    // 2304 floats per k-slice partial
#define SMEM_FLOATS (32*S_STRIDE + 2*128*V_STRIDE + 2*32*K_STRIDE)

__global__ __launch_bounds__(512)
void fused_attn(const float* __restrict__ qu, const float* __restrict__ qv,
                const float* __restrict__ kh, const float* __restrict__ vh,
                const float* __restrict__ pbuf, const int* __restrict__ mask,
                float* __restrict__ attn, float* __restrict__ ctx)
{
    extern __shared__ float sm[];
    float* S   = sm;                          // [32][1028], natural
    float* KV0 = sm + 32 * S_STRIDE;          // [128][72]
    float* KV1 = KV0 + 128 * V_STRIDE;
    float* Qu  = KV1 + 128 * V_STRIDE;        // [32][72]
    float* Qv  = Qu + 32 * K_STRIDE;
    float* part = KV0;                        // phase-4 partials alias KV0/KV1

    const int i0 = blockIdx.x * 32;
    const int z  = blockIdx.y;                // b*H + h
    const int b  = z >> 3, h = z & 7;
    const int tid = threadIdx.x;
    const int w = tid >> 5, lane = tid & 31;
    const float scale = 0.125f;
    const float NEG = __int_as_float(0xff7fffff);

    const int mh = w & 1, ne = w >> 1;        // pair id = ne, member = mh
    const int r0 = mh * 16 + (lane >> 2);
    const int l  = lane & 3;
    const int pt_id = tid & 63;               // thread id within pair

    // pair-scoped barrier (ids 1..8; 0 is __syncthreads)
    #define PAIRBAR() asm volatile("bar.sync %0, 64;\n" :: "r"(ne + 1) : "memory")

    // ---- load Qu, Qv tiles (32 x 64), CTA-wide ----
    {
        int r = tid >> 4, kq = tid & 15;
        long base = ((long)(b * T_ + i0 + r) * D_ + h * DK_ + kq * 4);
        cp16(&Qu[r * K_STRIDE + kq * 4], qu + base, true);
        cp16(&Qv[r * K_STRIDE + kq * 4], qv + base, true);
    }
    CP_COMMIT();

    // pair-scoped strip loads: 16 rows x 64 floats = 256 float4 / 64 threads
    auto pload_k = [&](int jt, float* buf) {
        #pragma unroll
        for (int it = 0; it < 4; it++) {
            int s = pt_id + it * 64;
            int n = ne * 16 + (s >> 4), kq = s & 15;
            cp16(&buf[n * K_STRIDE + kq * 4],
                 kh + ((long)(b * T_ + jt * 128 + n) * D_ + h * DK_ + kq * 4), true);
        }
        CP_COMMIT();
    };
    auto pload_p = [&](int pt0, float* buf) {
        #pragma unroll
        for (int it = 0; it < 4; it++) {
            int s = pt_id + it * 64;
            int n = ne * 16 + (s >> 4), kq = s & 15;
            int p = pt0 + n;
            cp16(&buf[n * K_STRIDE + kq * 4],
                 pbuf + ((long)p * D_ + h * DK_ + kq * 4), p <= P_ - 1);
        }
        CP_COMMIT();
    };
    // pair-scoped V strip load (phase 4; pair ne == ks owns rows [ne*16,+16))
    auto pload_v = [&](int jt, float* buf) {
        #pragma unroll
        for (int it = 0; it < 4; it++) {
            int s = pt_id + it * 64;
            int n = ne * 16 + (s >> 4), kq = s & 15;
            cp16(&buf[n * V_STRIDE + kq * 4],
                 vh + ((long)(b * T_ + jt * 128 + n) * D_ + h * DK_ + kq * 4), true);
        }
        CP_COMMIT();
    };

    // ---------------- Phase 1: ac = scale * Qu @ K^T (pair pipelines) --------
    pload_k(0, KV0);
    CP_WAIT0();
    __syncthreads();           // Qu/Qv visible CTA-wide + pair K0 strips done

    {
        uint32_t au[8][4];
        #pragma unroll
        for (int kk = 0; kk < 8; kk++) {
            int kp = kk * 8 + 2 * l;
            float2 p0 = *(const float2*)&Qu[r0 * K_STRIDE + kp];
            float2 p1 = *(const float2*)&Qu[(r0 + 8) * K_STRIDE + kp];
            au[kk][0] = __float_as_uint(p0.x);
            au[kk][1] = __float_as_uint(p1.x);
            au[kk][2] = __float_as_uint(p0.y);
            au[kk][3] = __float_as_uint(p1.y);
        }

        for (int jt = 0; jt < 8; jt++) {
            float* cur = (jt & 1) ? KV1 : KV0;
            float* nxt = (jt & 1) ? KV0 : KV1;
            if (jt + 1 < 8) pload_k(jt + 1, nxt);

            float acc[2][4] = {{0.f,0.f,0.f,0.f},{0.f,0.f,0.f,0.f}};
            #pragma unroll
            for (int kk = 0; kk < 8; kk++) {
                int kp = kk * 8 + 2 * l;
                #pragma unroll
                for (int nt = 0; nt < 2; nt++) {
                    int ncol = ne * 16 + nt * 8 + (lane >> 2);
                    float2 bp = *(const float2*)&cur[ncol * K_STRIDE + kp];
                    uint32_t bf[2] = { __float_as_uint(bp.x), __float_as_uint(bp.y) };
                    mma_tf32(acc[nt], au[kk], bf);
                }
            }
            #pragma unroll
            for (int nt = 0; nt < 2; nt++) {
                int c0 = jt * 128 + ne * 16 + nt * 8 + 2 * l;
                *(float2*)&S[r0 * S_STRIDE + c0] =
                    make_float2(acc[nt][0] * scale, acc[nt][1] * scale);
                *(float2*)&S[(r0 + 8) * S_STRIDE + c0] =
                    make_float2(acc[nt][2] * scale, acc[nt][3] * scale);
            }
            if (jt + 1 < 8) CP_WAIT0();
            PAIRBAR();
        }
    }

    // ------------- Phase 2: bd scatter-add over p-window (pair pipelines) ----
    const int pbase = (T_ - 1) - (i0 + 31);
    __syncthreads();           // all phase-1 S stores complete before scatter
    pload_p(pbase, KV0);
    {
        uint32_t av[8][4];
        #pragma unroll
        for (int kk = 0; kk < 8; kk++) {
            int kp = kk * 8 + 2 * l;
            float2 p0 = *(const float2*)&Qv[r0 * K_STRIDE + kp];
            float2 p1 = *(const float2*)&Qv[(r0 + 8) * K_STRIDE + kp];
            av[kk][0] = __float_as_uint(p0.x);
            av[kk][1] = __float_as_uint(p1.x);
            av[kk][2] = __float_as_uint(p0.y);
            av[kk][3] = __float_as_uint(p1.y);
        }
        CP_WAIT0();
        PAIRBAR();

        for (int pt = 0; pt < 9; pt++) {
            float* cur = (pt & 1) ? KV1 : KV0;
            float* nxt = (pt & 1) ? KV0 : KV1;
            if (pt + 1 < 9) pload_p(pbase + (pt + 1) * 128, nxt);

            float acc[2][4] = {{0.f,0.f,0.f,0.f},{0.f,0.f,0.f,0.f}};
            #pragma unroll
            for (int kk = 0; kk < 8; kk++) {
                int kp = kk * 8 + 2 * l;
                #pragma unroll
                for (int nt = 0; nt < 2; nt++) {
                    int ncol = ne * 16 + nt * 8 + (lane >> 2);
                    float2 bp = *(const float2*)&cur[ncol * K_STRIDE + kp];
                    uint32_t bf[2] = { __float_as_uint(bp.x), __float_as_uint(bp.y) };
                    mma_tf32(acc[nt], av[kk], bf);
                }
            }
            const int pt0 = pbase + pt * 128;
            #pragma unroll
            for (int nt = 0; nt < 2; nt++) {
                int c0 = ne * 16 + nt * 8 + 2 * l;
                #pragma unroll
                for (int e = 0; e < 4; e++) {
                    int r = r0 + (e >> 1) * 8;
                    int p = pt0 + c0 + (e & 1);
                    int j = p - (T_ - 1) + i0 + r;
                    if ((unsigned)j < (unsigned)T_)
                        S[r * S_STRIDE + j] += acc[nt][e] * scale;
                }
            }
            if (pt + 1 < 9) CP_WAIT0();
            PAIRBAR();
        }
    }
    __syncthreads();           // all scatters done before softmax / V overwrite

    // -------- prefetch V tile 0 strip (overlaps softmax) --------
    pload_v(0, KV0);

    // ------ Phase 3: softmax; attn gets fp32, S gets tf32-rounded ------
    #pragma unroll
    for (int t = 0; t < 2; t++) {
        int r = w + 16 * t;
        int i = i0 + r;
        const int4*   mrow = (const int4*)(mask + ((long)b * T_ + i) * T_);
        float4*       srow = (float4*)(S + r * S_STRIDE);
        float4*       arow = (float4*)(attn + ((long)z * T_ + i) * T_);

        float4 vals[8];
        float lmax = NEG;
        #pragma unroll
        for (int e = 0; e < 8; e++) {
            int idx = e * 32 + lane;
            float4 v = srow[idx];
            int4   m = mrow[idx];
            v.x = (m.x == 0) ? NEG : v.x;
            v.y = (m.y == 0) ? NEG : v.y;
            v.z = (m.z == 0) ? NEG : v.z;
            v.w = (m.w == 0) ? NEG : v.w;
            vals[e] = v;
            lmax = fmaxf(lmax, fmaxf(fmaxf(v.x, v.y), fmaxf(v.z, v.w)));
        }
        #pragma unroll
        for (int o = 16; o > 0; o >>= 1)
            lmax = fmaxf(lmax, __shfl_xor_sync(0xffffffffu, lmax, o));

        if (lmax == NEG) {
            float4 zero = make_float4(0.f, 0.f, 0.f, 0.f);
            #pragma unroll
            for (int e = 0; e < 8; e++) {
                int idx = e * 32 + lane;
                srow[idx] = zero;
                arow[idx] = zero;
            }
            continue;
        }
        float sum = 0.f;
        #pragma unroll
        for (int e = 0; e < 8; e++) {
            float4 v = vals[e];
            v.x = __expf(v.x - lmax); v.y = __expf(v.y - lmax);
            v.z = __expf(v.z - lmax); v.w = __expf(v.w - lmax);
            vals[e] = v;
            sum += (v.x + v.y) + (v.z + v.w);
        }
        #pragma unroll
        for (int o = 16; o > 0; o >>= 1)
            sum += __shfl_xor_sync(0xffffffffu, sum, o);
        float inv = 1.0f / sum;
        #pragma unroll
        for (int e = 0; e < 8; e++) {
            int idx = e * 32 + lane;
            float4 v = vals[e];
            v.x *= inv; v.y *= inv; v.z *= inv; v.w *= inv;
            arow[idx] = v;
            float4 vt;
            vt.x = tfr(v.x); vt.y = tfr(v.y);
            vt.z = tfr(v.z); vt.w = tfr(v.w);
            srow[idx] = vt;
        }
    }
    CP_WAIT0();
    __syncthreads();

    // ------- Phase 4 (split-K, pair pipelines): pair ks = ne -----------------
    {
        const int mt4 = w & 1, ks = w >> 1;   // ks == ne
        const int r4 = mt4 * 16 + (lane >> 2);
        float oacc[8][4];
        #pragma unroll
        for (int nt = 0; nt < 8; nt++)
            #pragma unroll
            for (int e = 0; e < 4; e++) oacc[nt][e] = 0.f;

        for (int jt = 0; jt < 8; jt++) {
            float* cur = (jt & 1) ? KV1 : KV0;
            float* nxt = (jt & 1) ? KV0 : KV1;
            if (jt + 1 < 8) pload_v(jt + 1, nxt);

            #pragma unroll
            for (int kx = 0; kx < 2; kx++) {
                int kc = (ks * 2 + kx) * 8 + l;
                uint32_t af[4] = {
                    ldu(&S[r4 * S_STRIDE + jt * 128 + kc]),
                    ldu(&S[(r4 + 8) * S_STRIDE + jt * 128 + kc]),
                    ldu(&S[r4 * S_STRIDE + jt * 128 + kc + 4]),
                    ldu(&S[(r4 + 8) * S_STRIDE + jt * 128 + kc + 4]) };
                #pragma unroll
                for (int nt = 0; nt < 8; nt++) {
                    int vn = nt * 8 + (lane >> 2);
                    uint32_t bf[2] = { ldu(&cur[kc * V_STRIDE + vn]),
                                       ldu(&cur[(kc + 4) * V_STRIDE + vn]) };
                    mma_tf32(oacc[nt], af, bf);
                }
            }
            if (jt + 1 < 8) CP_WAIT0();
            PAIRBAR();
        }
        __syncthreads();       // all pairs done reading V before part overwrite

        // store per-slice partials (stride 72 -> conflict-free float2)
        #pragma unroll
        for (int nt = 0; nt < 8; nt++) {
            int c = nt * 8 + 2 * l;
            *(float2*)&part[ks * PSLICE + r4 * P_STRIDE + c] =
                make_float2(oacc[nt][0], oacc[nt][1]);
            *(float2*)&part[ks * PSLICE + (r4 + 8) * P_STRIDE + c] =
                make_float2(oacc[nt][2], oacc[nt][3]);
        }
    }
    __syncthreads();

    // reduce 8 partials -> ctx (tf32-rounded)
    {
        int rr = tid >> 4;              // 0..31
        int c0 = (tid & 15) * 4;        // 0..60
        float4 acc = make_float4(0.f, 0.f, 0.f, 0.f);
        #pragma unroll
        for (int s = 0; s < 8; s++) {
            float4 pv = *(const float4*)&part[s * PSLICE + rr * P_STRIDE + c0];
            acc.x += pv.x; acc.y += pv.y; acc.z += pv.z; acc.w += pv.w;
        }
        long o = (long)(b * T_ + i0 + rr) * D_ + h * DK_ + c0;
        *(float4*)&ctx[o] = make_float4(tfr(acc.x), tfr(acc.y),
                                        tfr(acc.z), tfr(acc.w));
    }
    #undef PAIRBAR
}

// ------------------------------ launch ---------------------------------------
extern "C" void kernel_launch(void* const* d_in, const int* in_sizes, int n_in,
                              void* d_out, int out_size)
{
    const float* q    = (const float*)d_in[0];
    const float* k    = (const float*)d_in[1];
    const float* v    = (const float*)d_in[2];
    const float* pos  = (const float*)d_in[3];
    const int*   mask = (const int*)  d_in[4];
    const float* lnqg = (const float*)d_in[5],  *lnqb = (const float*)d_in[6];
    const float* lnkg = (const float*)d_in[7],  *lnkb = (const float*)d_in[8];
    const float* lnvg = (const float*)d_in[9],  *lnvb = (const float*)d_in[10];
    const float* wq   = (const float*)d_in[11], *wk   = (const float*)d_in[12];
    const float* wv   = (const float*)d_in[13], *wpos = (const float*)d_in[14];
    const float* wfc  = (const float*)d_in[15];
    const float* pbu  = (const float*)d_in[16], *pbv  = (const float*)d_in[17];

    float* out  = (float*)d_out;                 // [B,T,D]
    float* attn = out + (size_t)ND_;             // [B,H,T,T]

    float *qn,*kn,*vn,*qu,*qvb,*kh,*vh,*pb,*ctx,*wbuf,*prb;
    cudaGetSymbolAddress((void**)&qn,  g_qn);
    cudaGetSymbolAddress((void**)&kn,  g_kn);
    cudaGetSymbolAddress((void**)&vn,  g_vn);
    cudaGetSymbolAddress((void**)&qu,  g_qu);
    cudaGetSymbolAddress((void**)&qvb, g_qv);
    cudaGetSymbolAddress((void**)&kh,  g_kh);
    cudaGetSymbolAddress((void**)&vh,  g_vh);
    cudaGetSymbolAddress((void**)&pb,  g_p);
    cudaGetSymbolAddress((void**)&ctx, g_ctx);
    cudaGetSymbolAddress((void**)&wbuf, g_w);
    cudaGetSymbolAddress((void**)&prb, g_pr);

    static const size_t fused_smem = SMEM_FLOATS * sizeof(float);
    cudaFuncSetAttribute(fused_attn,
                         cudaFuncAttributeMaxDynamicSharedMemorySize,
                         (int)fused_smem);

    // single-launch tf32 pre-round of 5 weights + pos input
    {
        int pn4 = (P_ * D_) / 4;
        round_all<<<dim3((pn4 + 255) / 256, 6), 256>>>(
            wq, wk, wv, wpos, wfc, pos, wbuf, prb);
    }

    // merged LayerNorms (tf32-rounded outputs)
    ln3_kernel<<<dim3(NROW_, 3), 256>>>(q, k, v,
        lnqg, lnqb, lnkg, lnkb, lnvg, lnvb, qn, kn, vn);

    // merged Q/K/V/pos projections (grid.z = 4)
    qkvp_gemm<<<dim3(4,64,4),256>>>(qn, kn, vn, prb, wbuf,
        qu, kh, vh, qvb, pb, pbu, pbv);

    // fused attention
    fused_attn<<<dim3(32, 64), 512, fused_smem>>>(
        qu, qvb, kh, vh, pb, mask, attn, ctx);

    // out = ctx @ Wfc^T + residual(q)  (fp32 output, 64-row tiles: 512 CTAs)
    mma_gemm<64,128,32,32,true,false><<<dim3(4,128,1),256>>>(
        ctx, wbuf + 4L * D_ * D_, out, q,
        NROW_, D_, D_, 1.f, 0);
}

// round 17
// speedup vs baseline: 1.5255x; 1.0012x over previous
#include <cuda_runtime.h>
#include <cuda_bf16.h>
#include <math.h>
#include <stdint.h>

// Problem constants
#define B_  8
#define T_  1024
#define D_  512
#define H_  8
#define DK_ 64
#define P_  2047          // 2*T-1
#define NROW_ (B_*T_)     // 8192
#define ND_  (NROW_*D_)   // 4194304

// -------------------- device scratch (no allocs allowed) --------------------
__device__ float g_qn [ND_];
__device__ float g_kn [ND_];
__device__ float g_vn [ND_];
__device__ float g_qu [ND_];   // qh + pos_bias_u (tf32, dk pair-permuted)
__device__ float g_qv [ND_];   // qh + pos_bias_v (tf32, dk pair-permuted)
__device__ float g_kh [ND_];   // tf32, dk pair-permuted
__device__ float g_vh [ND_];   // tf32, natural
__device__ float g_p  [(P_+1)*D_]; // tf32, dk pair-permuted (row 2047 = pad)
__device__ float g_ctx[ND_];   // attn @ V (tf32-rounded at producer)
__device__ float g_w  [5][D_*D_];  // tf32-rounded weights: wq,wk,wv,wpos,wfc
__device__ float g_pr [P_*D_];     // tf32-rounded pos input

__device__ __forceinline__ int pos8(int x) { return ((x & 3) << 1) | ((x >> 2) & 1); }

// ------------------------- TF32 helpers --------------------------------------
__device__ __forceinline__ uint32_t f2tf(float f) {
    uint32_t u;
    asm("cvt.rna.tf32.f32 %0, %1;" : "=r"(u) : "f"(f));
    return u;
}
__device__ __forceinline__ float tfr(float f) { return __uint_as_float(f2tf(f)); }

__device__ __forceinline__ void mma_tf32(float c[4], const uint32_t a[4],
                                         const uint32_t b[2]) {
    asm volatile(
        "mma.sync.aligned.m16n8k8.row.col.f32.tf32.tf32.f32 "
        "{%0,%1,%2,%3},{%4,%5,%6,%7},{%8,%9},{%0,%1,%2,%3};\n"
        : "+f"(c[0]), "+f"(c[1]), "+f"(c[2]), "+f"(c[3])
        : "r"(a[0]), "r"(a[1]), "r"(a[2]), "r"(a[3]), "r"(b[0]), "r"(b[1]));
}

__device__ __forceinline__ void cp16(float* dst_smem, const float* src, bool valid) {
    uint32_t d = (uint32_t)__cvta_generic_to_shared(dst_smem);
    int sz = valid ? 16 : 0;
    asm volatile("cp.async.cg.shared.global [%0], [%1], 16, %2;\n"
                 :: "r"(d), "l"(src), "r"(sz));
}
#define CP_COMMIT() asm volatile("cp.async.commit_group;\n" ::: "memory")
#define CP_WAIT0()  asm volatile("cp.async.wait_group 0;\n" ::: "memory")
#define CP_WAIT1()  asm volatile("cp.async.wait_group 1;\n" ::: "memory")

__device__ __forceinline__ uint32_t ldu(const float* p) {
    return __float_as_uint(*p);
}

// ---------------- merged prep: LN (slices 0-2) + tf32 rounding (slice 3) -----
__global__ __launch_bounds__(256)
void prep_kernel(const float* __restrict__ q, const float* __restrict__ k,
                 const float* __restrict__ v,
                 const float* __restrict__ gq, const float* __restrict__ bq,
                 const float* __restrict__ gk, const float* __restrict__ bk,
                 const float* __restrict__ gv, const float* __restrict__ bv,
                 float* __restrict__ yq, float* __restrict__ yk,
                 float* __restrict__ yv,
                 const float* __restrict__ wq, const float* __restrict__ wk,
                 const float* __restrict__ wv, const float* __restrict__ wpos,
                 const float* __restrict__ wfc, const float* __restrict__ pos,
                 float* __restrict__ wbuf, float* __restrict__ prb)
{
    int slice = blockIdx.y;
    int tid = threadIdx.x;

    if (slice == 3) {       // rounding pass: 5 weights + pos input
        const int WQ4 = (D_ * D_) / 4;       // 65536 per weight
        const int PQ4 = (P_ * D_) / 4;       // 262016
        int i = blockIdx.x * 256 + tid;
        int total = 5 * WQ4 + PQ4;
        if (i >= total) return;
        const float* src;
        float* dst;
        if (i < 5 * WQ4) {
            int s = i / WQ4, off = i % WQ4;
            src = ((s == 0) ? wq : (s == 1) ? wk : (s == 2) ? wv
                 : (s == 3) ? wpos : wfc) + (long)off * 4 - (long)off * 4;
            // read via float4 index
            float4 vv = ((const float4*)((s == 0) ? wq : (s == 1) ? wk
                        : (s == 2) ? wv : (s == 3) ? wpos : wfc))[off];
            vv.x = tfr(vv.x); vv.y = tfr(vv.y); vv.z = tfr(vv.z); vv.w = tfr(vv.w);
            ((float4*)(wbuf + (long)s * D_ * D_))[off] = vv;
        } else {
            int off = i - 5 * WQ4;
            float4 vv = ((const float4*)pos)[off];
            vv.x = tfr(vv.x); vv.y = tfr(vv.y); vv.z = tfr(vv.z); vv.w = tfr(vv.w);
            ((float4*)prb)[off] = vv;
        }
        return;
    }

    const float* x  = (slice == 0) ? q  : (slice == 1) ? k  : v;
    const float* g  = (slice == 0) ? gq : (slice == 1) ? gk : gv;
    const float* bb = (slice == 0) ? bq : (slice == 1) ? bk : bv;
    float*       y  = (slice == 0) ? yq : (slice == 1) ? yk : yv;

    long row = blockIdx.x;
    const float2* xr = (const float2*)(x + row * D_);
    float2*       yr = (float2*)(y + row * D_);
    float2 vv = xr[tid];
    float s  = vv.x + vv.y;
    float sq = vv.x * vv.x + vv.y * vv.y;

    __shared__ float rs[8], rq[8];
    #pragma unroll
    for (int o = 16; o > 0; o >>= 1) {
        s  += __shfl_xor_sync(0xffffffffu, s,  o);
        sq += __shfl_xor_sync(0xffffffffu, sq, o);
    }
    int wid = tid >> 5;
    if ((tid & 31) == 0) { rs[wid] = s; rq[wid] = sq; }
    __syncthreads();
    if (tid == 0) {
        float a = 0.f, b2 = 0.f;
        #pragma unroll
        for (int w = 0; w < 8; w++) { a += rs[w]; b2 += rq[w]; }
        rs[0] = a; rq[0] = b2;
    }
    __syncthreads();
    float mean = rs[0] * (1.0f / D_);
    float var  = rq[0] * (1.0f / D_) - mean * mean;
    float rstd = rsqrtf(var + 1e-5f);
    const float2* gv2 = (const float2*)g;
    const float2* bv2 = (const float2*)bb;
    float2 gg = gv2[tid], bbv = bv2[tid];
    float2 o;
    o.x = tfr((vv.x - mean) * rstd * gg.x + bbv.x);
    o.y = tfr((vv.y - mean) * rstd * gg.y + bbv.y);
    yr[tid] = o;
}

// ------------------------------ TF32 MMA GEMM core ----------------------------
template<int BM, int BN, int WM, int WN, bool TRANS_B, bool CVT_OUT>
__device__ __forceinline__
void gemm_core(const float* __restrict__ A, const float* __restrict__ Bm,
               float* __restrict__ C, float* __restrict__ C2,
               const float* __restrict__ bias1, const float* __restrict__ bias2,
               const float* __restrict__ Res,
               int M, int N, int K, int lda, int ldb, int ldc,
               float alpha, bool perm, int m0, int n0)
{
    constexpr int BK = 16;
    constexpr int MT = WM / 16;
    constexpr int NT = WN / 8;
    constexpr int WCOLS = BN / WN;
    static_assert((BM / WM) * (BN / WN) == 8, "8 warps required");

    __shared__ float As[3][BM][BK + 4];
    __shared__ float Bs[3][TRANS_B ? BN : BK][TRANS_B ? (BK + 4) : (BN + 8)];

    int tid  = threadIdx.x;
    int warp = tid >> 5, lane = tid & 31;
    int wm0 = (warp / WCOLS) * WM;
    int wn0 = (warp % WCOLS) * WN;

    auto ldg_async = [&](int k0, int buf) {
        #pragma unroll
        for (int it = 0; it < (BM * BK) / (4 * 256); it++) {
            int s = tid + it * 256;
            int row = s >> 2, kq = s & 3;
            int gm = m0 + row;
            cp16(&As[buf][row][kq * 4], A + (long)gm * lda + k0 + kq * 4, gm < M);
        }
        if (TRANS_B) {
            #pragma unroll
            for (int it = 0; it < (BN * BK) / (4 * 256); it++) {
                int s = tid + it * 256;
                int n = s >> 2, kq = s & 3;
                int gn = n0 + n;
                cp16(&Bs[buf][n][kq * 4], Bm + (long)gn * ldb + k0 + kq * 4, gn < N);
            }
        } else {
            #pragma unroll
            for (int it = 0; it < (BK * BN) / (4 * 256); it++) {
                int s = tid + it * 256;
                int kk = s / (BN / 4), nq = s % (BN / 4);
                cp16(&Bs[buf][kk][nq * 4],
                     Bm + (long)(k0 + kk) * ldb + n0 + nq * 4, true);
            }
        }
        CP_COMMIT();
    };

    float acc[MT][NT][4];
    #pragma unroll
    for (int i = 0; i < MT; i++)
        #pragma unroll
        for (int j = 0; j < NT; j++)
            #pragma unroll
            for (int e = 0; e < 4; e++) acc[i][j][e] = 0.f;

    const int nIter = K / BK;
    ldg_async(0, 0);
    if (nIter > 1) ldg_async(BK, 1);
    if (nIter > 1) { CP_WAIT1(); } else { CP_WAIT0(); }
    __syncthreads();

    for (int itk = 0; itk < nIter; itk++) {
        int buf = itk % 3;
        if (itk + 2 < nIter) ldg_async((itk + 2) * BK, (itk + 2) % 3);

        #pragma unroll
        for (int ks = 0; ks < 2; ks++) {
            const int kc = ks * 8 + (lane & 3);
            uint32_t af[MT][4];
            uint32_t bf[NT][2];
            #pragma unroll
            for (int mt = 0; mt < MT; mt++) {
                int mrow = wm0 + mt * 16 + (lane >> 2);
                af[mt][0] = ldu(&As[buf][mrow    ][kc    ]);
                af[mt][1] = ldu(&As[buf][mrow + 8][kc    ]);
                af[mt][2] = ldu(&As[buf][mrow    ][kc + 4]);
                af[mt][3] = ldu(&As[buf][mrow + 8][kc + 4]);
            }
            #pragma unroll
            for (int nt = 0; nt < NT; nt++) {
                int ncol = wn0 + nt * 8 + (lane >> 2);
                if (TRANS_B) {
                    bf[nt][0] = ldu(&Bs[buf][ncol][kc    ]);
                    bf[nt][1] = ldu(&Bs[buf][ncol][kc + 4]);
                } else {
                    bf[nt][0] = ldu(&Bs[buf][kc    ][ncol]);
                    bf[nt][1] = ldu(&Bs[buf][kc + 4][ncol]);
                }
            }
            #pragma unroll
            for (int mt = 0; mt < MT; mt++)
                #pragma unroll
                for (int nt = 0; nt < NT; nt++)
                    mma_tf32(acc[mt][nt], af[mt], bf[nt]);
        }

        if (itk + 1 < nIter) {
            if (itk + 2 < nIter) { CP_WAIT1(); } else { CP_WAIT0(); }
        }
        __syncthreads();
    }

    auto emit = [&](int gm, int gn, float v) {
        if (gm < M && gn < N) {
            float val = v * alpha;
            if (Res) val += Res[(long)gm * ldc + gn];
            int gns = perm ? ((gn & ~7) | pos8(gn & 7)) : gn;
            if (C2) {
                float v1 = val + bias1[gn];
                float v2 = val + bias2[gn];
                if (CVT_OUT) { v1 = tfr(v1); v2 = tfr(v2); }
                C [(long)gm * ldc + gns] = v1;
                C2[(long)gm * ldc + gns] = v2;
            } else {
                float v1 = val + (bias1 ? bias1[gn] : 0.f);
                if (CVT_OUT) v1 = tfr(v1);
                C[(long)gm * ldc + gns] = v1;
            }
        }
    };
    #pragma unroll
    for (int mt = 0; mt < MT; mt++) {
        #pragma unroll
        for (int nt = 0; nt < NT; nt++) {
            int gm = m0 + wm0 + mt * 16 + (lane >> 2);
            int gn = n0 + wn0 + nt * 8 + 2 * (lane & 3);
            emit(gm,     gn,     acc[mt][nt][0]);
            emit(gm,     gn + 1, acc[mt][nt][1]);
            emit(gm + 8, gn,     acc[mt][nt][2]);
            emit(gm + 8, gn + 1, acc[mt][nt][3]);
        }
    }
}

// generic wrapper (FC)
template<int BM, int BN, int WM, int WN, bool TRANS_B, bool CVT_OUT>
__global__ __launch_bounds__(256)
void mma_gemm(const float* __restrict__ A, const float* __restrict__ Bm,
              float* __restrict__ C,
              const float* __restrict__ Res,
              int M, int N, int K, float alpha, int perm)
{
    gemm_core<BM,BN,WM,WN,TRANS_B,CVT_OUT>(
        A, Bm, C, nullptr, nullptr, nullptr, Res,
        M, N, K, K, K, N, alpha, perm != 0,
        blockIdx.y * BM, blockIdx.x * BN);
}

// merged Q/K/V/pos projection: grid.z in {0,1,2,3}
__global__ __launch_bounds__(256)
void qkvp_gemm(const float* __restrict__ qn, const float* __restrict__ kn,
               const float* __restrict__ vn, const float* __restrict__ prb,
               const float* __restrict__ wbuf,
               float* __restrict__ qu, float* __restrict__ kh,
               float* __restrict__ vh, float* __restrict__ qvb,
               float* __restrict__ pb,
               const float* __restrict__ pbu, const float* __restrict__ pbv)
{
    int zz = blockIdx.z;
    if (zz == 3) {
        if (blockIdx.y >= 16) return;
        gemm_core<128,128,64,32,true,true>(
            prb, wbuf + 3L * D_ * D_, pb, nullptr, nullptr, nullptr, nullptr,
            P_, D_, D_, D_, D_, D_, 1.f, true,
            blockIdx.y * 128, blockIdx.x * 128);
        return;
    }
    const float* A  = (zz == 0) ? qn : (zz == 1) ? kn : vn;
    const float* Bm = wbuf + (long)zz * D_ * D_;
    float* C  = (zz == 0) ? qu : (zz == 1) ? kh : vh;
    float* C2 = (zz == 0) ? qvb : nullptr;
    const float* b1 = (zz == 0) ? pbu : nullptr;
    const float* b2 = (zz == 0) ? pbv : nullptr;
    bool perm = (zz < 2);
    gemm_core<128,128,64,32,true,true>(
        A, Bm, C, C2, b1, b2, nullptr,
        NROW_, D_, D_, D_, D_, D_, 1.f, perm,
        blockIdx.y * 128, blockIdx.x * 128);
}

// ===================== FUSED ATTENTION ======================================
// Phases 1-2 AND 4 run as 8 independent warp-pairs (64-thread named barriers).
// Score phases use in-register split-K (2 accumulator sets) for 4 MMA chains.
#define S_STRIDE 1028
#define K_STRIDE 72
#define V_STRIDE 72
#define P_STRIDE 72                 // partial-sum row stride (phase 4 reduce)
#define PSLICE   (32 * P_STRIDE)    // 2304 floats per k-slice partial
#define SMEM_FLOATS (32*S_STRIDE + 2*128*V_STRIDE + 2*32*K_STRIDE)

__global__ __launch_bounds__(512)
void fused_attn(const float* __restrict__ qu, const float* __restrict__ qv,
                const float* __restrict__ kh, const float* __restrict__ vh,
                const float* __restrict__ pbuf, const int* __restrict__ mask,
                float* __restrict__ attn, float* __restrict__ ctx)
{
    extern __shared__ float sm[];
    float* S   = sm;                          // [32][1028], natural
    float* KV0 = sm + 32 * S_STRIDE;          // [128][72]
    float* KV1 = KV0 + 128 * V_STRIDE;
    float* Qu  = KV1 + 128 * V_STRIDE;        // [32][72]
    float* Qv  = Qu + 32 * K_STRIDE;
    float* part = KV0;                        // phase-4 partials alias KV0/KV1

    const int i0 = blockIdx.x * 32;
    const int z  = blockIdx.y;                // b*H + h
    const int b  = z >> 3, h = z & 7;
    const int tid = threadIdx.x;
    const int w = tid >> 5, lane = tid & 31;
    const float scale = 0.125f;
    const float NEG = __int_as_float(0xff7fffff);

    const int mh = w & 1, ne = w >> 1;        // pair id = ne, member = mh
    const int r0 = mh * 16 + (lane >> 2);
    const int l  = lane & 3;
    const int pt_id = tid & 63;               // thread id within pair

    // pair-scoped barrier (ids 1..8; 0 is __syncthreads)
    #define PAIRBAR() asm volatile("bar.sync %0, 64;\n" :: "r"(ne + 1) : "memory")

    // ---- load Qu, Qv tiles (32 x 64), CTA-wide ----
    {
        int r = tid >> 4, kq = tid & 15;
        long base = ((long)(b * T_ + i0 + r) * D_ + h * DK_ + kq * 4);
        cp16(&Qu[r * K_STRIDE + kq * 4], qu + base, true);
        cp16(&Qv[r * K_STRIDE + kq * 4], qv + base, true);
    }
    CP_COMMIT();

    // pair-scoped strip loads: 16 rows x 64 floats = 256 float4 / 64 threads
    auto pload_k = [&](int jt, float* buf) {
        #pragma unroll
        for (int it = 0; it < 4; it++) {
            int s = pt_id + it * 64;
            int n = ne * 16 + (s >> 4), kq = s & 15;
            cp16(&buf[n * K_STRIDE + kq * 4],
                 kh + ((long)(b * T_ + jt * 128 + n) * D_ + h * DK_ + kq * 4), true);
        }
        CP_COMMIT();
    };
    auto pload_p = [&](int pt0, float* buf) {
        #pragma unroll
        for (int it = 0; it < 4; it++) {
            int s = pt_id + it * 64;
            int n = ne * 16 + (s >> 4), kq = s & 15;
            int p = pt0 + n;
            cp16(&buf[n * K_STRIDE + kq * 4],
                 pbuf + ((long)p * D_ + h * DK_ + kq * 4), p <= P_ - 1);
        }
        CP_COMMIT();
    };
    // pair-scoped V strip load (phase 4; pair ne == ks owns rows [ne*16,+16))
    auto pload_v = [&](int jt, float* buf) {
        #pragma unroll
        for (int it = 0; it < 4; it++) {
            int s = pt_id + it * 64;
            int n = ne * 16 + (s >> 4), kq = s & 15;
            cp16(&buf[n * V_STRIDE + kq * 4],
                 vh + ((long)(b * T_ + jt * 128 + n) * D_ + h * DK_ + kq * 4), true);
        }
        CP_COMMIT();
    };

    // ---------------- Phase 1: ac = scale * Qu @ K^T (pair pipelines) --------
    pload_k(0, KV0);
    CP_WAIT0();
    __syncthreads();           // Qu/Qv visible CTA-wide + pair K0 strips done

    {
        uint32_t au[8][4];
        #pragma unroll
        for (int kk = 0; kk < 8; kk++) {
            int kp = kk * 8 + 2 * l;
            float2 p0 = *(const float2*)&Qu[r0 * K_STRIDE + kp];
            float2 p1 = *(const float2*)&Qu[(r0 + 8) * K_STRIDE + kp];
            au[kk][0] = __float_as_uint(p0.x);
            au[kk][1] = __float_as_uint(p1.x);
            au[kk][2] = __float_as_uint(p0.y);
            au[kk][3] = __float_as_uint(p1.y);
        }

        for (int jt = 0; jt < 8; jt++) {
            float* cur = (jt & 1) ? KV1 : KV0;
            float* nxt = (jt & 1) ? KV0 : KV1;
            if (jt + 1 < 8) pload_k(jt + 1, nxt);

            float acc [2][4] = {{0.f,0.f,0.f,0.f},{0.f,0.f,0.f,0.f}};
            float acc2[2][4] = {{0.f,0.f,0.f,0.f},{0.f,0.f,0.f,0.f}};
            #pragma unroll
            for (int kk = 0; kk < 4; kk++) {
                int kp  = kk * 8 + 2 * l;
                int kp2 = (kk + 4) * 8 + 2 * l;
                #pragma unroll
                for (int nt = 0; nt < 2; nt++) {
                    int ncol = ne * 16 + nt * 8 + (lane >> 2);
                    float2 bp  = *(const float2*)&cur[ncol * K_STRIDE + kp];
                    float2 bp2 = *(const float2*)&cur[ncol * K_STRIDE + kp2];
                    uint32_t bf [2] = { __float_as_uint(bp.x),  __float_as_uint(bp.y) };
                    uint32_t bf2[2] = { __float_as_uint(bp2.x), __float_as_uint(bp2.y) };
                    mma_tf32(acc [nt], au[kk],     bf);
                    mma_tf32(acc2[nt], au[kk + 4], bf2);
                }
            }
            #pragma unroll
            for (int nt = 0; nt < 2; nt++) {
                int c0 = jt * 128 + ne * 16 + nt * 8 + 2 * l;
                *(float2*)&S[r0 * S_STRIDE + c0] =
                    make_float2((acc[nt][0] + acc2[nt][0]) * scale,
                                (acc[nt][1] + acc2[nt][1]) * scale);
                *(float2*)&S[(r0 + 8) * S_STRIDE + c0] =
                    make_float2((acc[nt][2] + acc2[nt][2]) * scale,
                                (acc[nt][3] + acc2[nt][3]) * scale);
            }
            if (jt + 1 < 8) CP_WAIT0();
            PAIRBAR();
        }
    }

    // ------------- Phase 2: bd scatter-add over p-window (pair pipelines) ----
    const int pbase = (T_ - 1) - (i0 + 31);
    __syncthreads();           // all phase-1 S stores complete before scatter
    pload_p(pbase, KV0);
    {
        uint32_t av[8][4];
        #pragma unroll
        for (int kk = 0; kk < 8; kk++) {
            int kp = kk * 8 + 2 * l;
            float2 p0 = *(const float2*)&Qv[r0 * K_STRIDE + kp];
            float2 p1 = *(const float2*)&Qv[(r0 + 8) * K_STRIDE + kp];
            av[kk][0] = __float_as_uint(p0.x);
            av[kk][1] = __float_as_uint(p1.x);
            av[kk][2] = __float_as_uint(p0.y);
            av[kk][3] = __float_as_uint(p1.y);
        }
        CP_WAIT0();
        PAIRBAR();

        for (int pt = 0; pt < 9; pt++) {
            float* cur = (pt & 1) ? KV1 : KV0;
            float* nxt = (pt & 1) ? KV0 : KV1;
            if (pt + 1 < 9) pload_p(pbase + (pt + 1) * 128, nxt);

            float acc [2][4] = {{0.f,0.f,0.f,0.f},{0.f,0.f,0.f,0.f}};
            float acc2[2][4] = {{0.f,0.f,0.f,0.f},{0.f,0.f,0.f,0.f}};
            #pragma unroll
            for (int kk = 0; kk < 4; kk++) {
                int kp  = kk * 8 + 2 * l;
                int kp2 = (kk + 4) * 8 + 2 * l;
                #pragma unroll
                for (int nt = 0; nt < 2; nt++) {
                    int ncol = ne * 16 + nt * 8 + (lane >> 2);
                    float2 bp  = *(const float2*)&cur[ncol * K_STRIDE + kp];
                    float2 bp2 = *(const float2*)&cur[ncol * K_STRIDE + kp2];
                    uint32_t bf [2] = { __float_as_uint(bp.x),  __float_as_uint(bp.y) };
                    uint32_t bf2[2] = { __float_as_uint(bp2.x), __float_as_uint(bp2.y) };
                    mma_tf32(acc [nt], av[kk],     bf);
                    mma_tf32(acc2[nt], av[kk + 4], bf2);
                }
            }
            const int pt0 = pbase + pt * 128;
            #pragma unroll
            for (int nt = 0; nt < 2; nt++) {
                int c0 = ne * 16 + nt * 8 + 2 * l;
                #pragma unroll
                for (int e = 0; e < 4; e++) {
                    int r = r0 + (e >> 1) * 8;
                    int p = pt0 + c0 + (e & 1);
                    int j = p - (T_ - 1) + i0 + r;
                    if ((unsigned)j < (unsigned)T_)
                        S[r * S_STRIDE + j] += (acc[nt][e] + acc2[nt][e]) * scale;
                }
            }
            if (pt + 1 < 9) CP_WAIT0();
            PAIRBAR();
        }
    }
    __syncthreads();           // all scatters done before softmax / V overwrite

    // -------- prefetch V tile 0 strip (overlaps softmax) --------
    pload_v(0, KV0);

    // ------ Phase 3: softmax; attn gets fp32, S gets tf32-rounded ------
    #pragma unroll
    for (int t = 0; t < 2; t++) {
        int r = w + 16 * t;
        int i = i0 + r;
        const int4*   mrow = (const int4*)(mask + ((long)b * T_ + i) * T_);
        float4*       srow = (float4*)(S + r * S_STRIDE);
        float4*       arow = (float4*)(attn + ((long)z * T_ + i) * T_);

        float4 vals[8];
        float lmax = NEG;
        #pragma unroll
        for (int e = 0; e < 8; e++) {
            int idx = e * 32 + lane;
            float4 v = srow[idx];
            int4   m = mrow[idx];
            v.x = (m.x == 0) ? NEG : v.x;
            v.y = (m.y == 0) ? NEG : v.y;
            v.z = (m.z == 0) ? NEG : v.z;
            v.w = (m.w == 0) ? NEG : v.w;
            vals[e] = v;
            lmax = fmaxf(lmax, fmaxf(fmaxf(v.x, v.y), fmaxf(v.z, v.w)));
        }
        #pragma unroll
        for (int o = 16; o > 0; o >>= 1)
            lmax = fmaxf(lmax, __shfl_xor_sync(0xffffffffu, lmax, o));

        if (lmax == NEG) {
            float4 zero = make_float4(0.f, 0.f, 0.f, 0.f);
            #pragma unroll
            for (int e = 0; e < 8; e++) {
                int idx = e * 32 + lane;
                srow[idx] = zero;
                arow[idx] = zero;
            }
            continue;
        }
        float sum = 0.f;
        #pragma unroll
        for (int e = 0; e < 8; e++) {
            float4 v = vals[e];
            v.x = __expf(v.x - lmax); v.y = __expf(v.y - lmax);
            v.z = __expf(v.z - lmax); v.w = __expf(v.w - lmax);
            vals[e] = v;
            sum += (v.x + v.y) + (v.z + v.w);
        }
        #pragma unroll
        for (int o = 16; o > 0; o >>= 1)
            sum += __shfl_xor_sync(0xffffffffu, sum, o);
        float inv = 1.0f / sum;
        #pragma unroll
        for (int e = 0; e < 8; e++) {
            int idx = e * 32 + lane;
            float4 v = vals[e];
            v.x *= inv; v.y *= inv; v.z *= inv; v.w *= inv;
            arow[idx] = v;
            float4 vt;
            vt.x = tfr(v.x); vt.y = tfr(v.y);
            vt.z = tfr(v.z); vt.w = tfr(v.w);
            srow[idx] = vt;
        }
    }
    CP_WAIT0();
    __syncthreads();

    // ------- Phase 4 (split-K, pair pipelines): pair ks = ne -----------------
    {
        const int mt4 = w & 1, ks = w >> 1;   // ks == ne
        const int r4 = mt4 * 16 + (lane >> 2);
        float oacc[8][4];
        #pragma unroll
        for (int nt = 0; nt < 8; nt++)
            #pragma unroll
            for (int e = 0; e < 4; e++) oacc[nt][e] = 0.f;

        for (int jt = 0; jt < 8; jt++) {
            float* cur = (jt & 1) ? KV1 : KV0;
            float* nxt = (jt & 1) ? KV0 : KV1;
            if (jt + 1 < 8) pload_v(jt + 1, nxt);

            #pragma unroll
            for (int kx = 0; kx < 2; kx++) {
                int kc = (ks * 2 + kx) * 8 + l;
                uint32_t af[4] = {
                    ldu(&S[r4 * S_STRIDE + jt * 128 + kc]),
                    ldu(&S[(r4 + 8) * S_STRIDE + jt * 128 + kc]),
                    ldu(&S[r4 * S_STRIDE + jt * 128 + kc + 4]),
                    ldu(&S[(r4 + 8) * S_STRIDE + jt * 128 + kc + 4]) };
                #pragma unroll
                for (int nt = 0; nt < 8; nt++) {
                    int vn = nt * 8 + (lane >> 2);
                    uint32_t bf[2] = { ldu(&cur[kc * V_STRIDE + vn]),
                                       ldu(&cur[(kc + 4) * V_STRIDE + vn]) };
                    mma_tf32(oacc[nt], af, bf);
                }
            }
            if (jt + 1 < 8) CP_WAIT0();
            PAIRBAR();
        }
        __syncthreads();       // all pairs done reading V before part overwrite

        // store per-slice partials (stride 72 -> conflict-free float2)
        #pragma unroll
        for (int nt = 0; nt < 8; nt++) {
            int c = nt * 8 + 2 * l;
            *(float2*)&part[ks * PSLICE + r4 * P_STRIDE + c] =
                make_float2(oacc[nt][0], oacc[nt][1]);
            *(float2*)&part[ks * PSLICE + (r4 + 8) * P_STRIDE + c] =
                make_float2(oacc[nt][2], oacc[nt][3]);
        }
    }
    __syncthreads();

    // reduce 8 partials -> ctx (tf32-rounded)
    {
        int rr = tid >> 4;              // 0..31
        int c0 = (tid & 15) * 4;        // 0..60
        float4 acc = make_float4(0.f, 0.f, 0.f, 0.f);
        #pragma unroll
        for (int s = 0; s < 8; s++) {
            float4 pv = *(const float4*)&part[s * PSLICE + rr * P_STRIDE + c0];
            acc.x += pv.x; acc.y += pv.y; acc.z += pv.z; acc.w += pv.w;
        }
        long o = (long)(b * T_ + i0 + rr) * D_ + h * DK_ + c0;
        *(float4*)&ctx[o] = make_float4(tfr(acc.x), tfr(acc.y),
                                        tfr(acc.z), tfr(acc.w));
    }
    #undef PAIRBAR
}

// ------------------------------ launch ---------------------------------------
extern "C" void kernel_launch(void* const* d_in, const int* in_sizes, int n_in,
                              void* d_out, int out_size)
{
    const float* q    = (const float*)d_in[0];
    const float* k    = (const float*)d_in[1];
    const float* v    = (const float*)d_in[2];
    const float* pos  = (const float*)d_in[3];
    const int*   mask = (const int*)  d_in[4];
    const float* lnqg = (const float*)d_in[5],  *lnqb = (const float*)d_in[6];
    const float* lnkg = (const float*)d_in[7],  *lnkb = (const float*)d_in[8];
    const float* lnvg = (const float*)d_in[9],  *lnvb = (const float*)d_in[10];
    const float* wq   = (const float*)d_in[11], *wk   = (const float*)d_in[12];
    const float* wv   = (const float*)d_in[13], *wpos = (const float*)d_in[14];
    const float* wfc  = (const float*)d_in[15];
    const float* pbu  = (const float*)d_in[16], *pbv  = (const float*)d_in[17];

    float* out  = (float*)d_out;                 // [B,T,D]
    float* attn = out + (size_t)ND_;             // [B,H,T,T]

    float *qn,*kn,*vn,*qu,*qvb,*kh,*vh,*pb,*ctx,*wbuf,*prb;
    cudaGetSymbolAddress((void**)&qn,  g_qn);
    cudaGetSymbolAddress((void**)&kn,  g_kn);
    cudaGetSymbolAddress((void**)&vn,  g_vn);
    cudaGetSymbolAddress((void**)&qu,  g_qu);
    cudaGetSymbolAddress((void**)&qvb, g_qv);
    cudaGetSymbolAddress((void**)&kh,  g_kh);
    cudaGetSymbolAddress((void**)&vh,  g_vh);
    cudaGetSymbolAddress((void**)&pb,  g_p);
    cudaGetSymbolAddress((void**)&ctx, g_ctx);
    cudaGetSymbolAddress((void**)&wbuf, g_w);
    cudaGetSymbolAddress((void**)&prb, g_pr);

    static const size_t fused_smem = SMEM_FLOATS * sizeof(float);
    cudaFuncSetAttribute(fused_attn,
                         cudaFuncAttributeMaxDynamicSharedMemorySize,
                         (int)fused_smem);

    // merged prep: 3 LayerNorm slices + tf32 rounding (weights + pos)
    prep_kernel<<<dim3(NROW_, 4), 256>>>(q, k, v,
        lnqg, lnqb, lnkg, lnkb, lnvg, lnvb, qn, kn, vn,
        wq, wk, wv, wpos, wfc, pos, wbuf, prb);

    // merged Q/K/V/pos projections (grid.z = 4)
    qkvp_gemm<<<dim3(4,64,4),256>>>(qn, kn, vn, prb, wbuf,
        qu, kh, vh, qvb, pb, pbu, pbv);

    // fused attention
    fused_attn<<<dim3(32, 64), 512, fused_smem>>>(
        qu, qvb, kh, vh, pb, mask, attn, ctx);

    // out = ctx @ Wfc^T + residual(q)  (fp32 output, 64-row tiles: 512 CTAs)
    mma_gemm<64,128,32,32,true,false><<<dim3(4,128,1),256>>>(
        ctx, wbuf + 4L * D_ * D_, out, q,
        NROW_, D_, D_, 1.f, 0);
}